// round 1
// baseline (speedup 1.0000x reference)
#include <cuda_runtime.h>
#include <cuda_bf16.h>
#include <math.h>

// ---------------- Problem constants (fixed by setup_inputs) ----------------
#define S_TOK   2304      // T*H*W = 1*48*48
#define HID     1280
#define HEADS   16
#define HD      80
#define DEPTH   8
#define INTER   3420
#define OUTDIM  3584
#define QKV3    3840      // 3*HID
#define GROUPS  576       // S/4
#define PIXF    1176      // 6*14*14
#define MERGED  5120      // 4*HID
#define NTILE64 36        // S/64

// ---------------- Scratch (device globals; no allocation allowed) ----------
__device__ float g_x[S_TOK * HID];
__device__ float g_h[S_TOK * HID];       // also viewed as (576, 5120) for merger
__device__ float g_qkv[S_TOK * QKV3];    // reused for m2 output (576*3584 fits)
__device__ float g_attn[S_TOK * HID];
__device__ float g_gate[S_TOK * INTER];  // reused for m1 output (576*5120 fits)
__device__ float g_up[S_TOK * INTER];
__device__ float g_pix[S_TOK * PIXF];
__device__ float g_cos[S_TOK * HD];
__device__ float g_sin[S_TOK * HD];
__device__ int   g_orig[S_TOK];          // permuted token -> original pixel row
__device__ int   g_wingrp[GROUPS];       // win[g]: output scatter target row

// ---------------- Index + rotary precompute --------------------------------
__global__ void init_kernel() {
    int s = blockIdx.x * blockDim.x + threadIdx.x;
    if (s >= S_TOK) return;
    int g = s >> 2, r = s & 3;
    // window permutation: j=(hb,wb,hr,wr) -> win[j]=(hb*4+hr)*24 + (wb*4+wr)
    int hb = g / 96, wb = (g / 16) % 6, hr = (g % 16) / 4, wr = g & 3;
    int og = (hb * 4 + hr) * 24 + (wb * 4 + wr);
    g_orig[s] = og * 4 + r;
    if (r == 0) g_wingrp[g] = og;
    // spatial position of original token (SMS=2 perm inside group)
    int hg = og / 24, wg = og % 24;
    int hh = hg * 2 + (r >> 1), ww = wg * 2 + (r & 1);
    for (int j = 0; j < 40; j++) {
        float invf = powf(10000.f, -(float)(j % 20) / 20.f);
        float ang = (float)((j < 20) ? hh : ww) * invf;
        float c = cosf(ang), sn = sinf(ang);
        g_cos[s * HD + j] = c;  g_cos[s * HD + 40 + j] = c;
        g_sin[s * HD + j] = sn; g_sin[s * HD + 40 + j] = sn;
    }
}

__global__ void gather_pixels(const float* __restrict__ pix) {
    for (long i = blockIdx.x * (long)blockDim.x + threadIdx.x;
         i < (long)S_TOK * PIXF; i += (long)gridDim.x * blockDim.x) {
        int s = (int)(i / PIXF), c = (int)(i % PIXF);
        g_pix[i] = pix[(long)g_orig[s] * PIXF + c];
    }
}

// ---------------- Generic SGEMM: C[M,N] (+)= A[M,K] @ B[N,K]^T + bias ------
#define BM 64
#define BN 64
#define BK 16
__global__ void gemm_kernel(const float* __restrict__ A, const float* __restrict__ B,
                            const float* __restrict__ bias, float* __restrict__ C,
                            int M, int N, int K, int addFlag) {
    __shared__ float As[BK][BM];
    __shared__ float Bs[BK][BN];
    int bm = blockIdx.y * BM, bn = blockIdx.x * BN;
    int tid = threadIdx.x;
    int ty = tid / 16, tx = tid % 16;
    float acc[4][4];
#pragma unroll
    for (int i = 0; i < 4; i++)
#pragma unroll
        for (int j = 0; j < 4; j++) acc[i][j] = 0.f;

    int lr = tid >> 2, lc = (tid & 3) * 4;
    for (int k0 = 0; k0 < K; k0 += BK) {
#pragma unroll
        for (int j = 0; j < 4; j++) {
            int kk = k0 + lc + j;
            As[lc + j][lr] = (bm + lr < M && kk < K) ? A[(size_t)(bm + lr) * K + kk] : 0.f;
            Bs[lc + j][lr] = (bn + lr < N && kk < K) ? B[(size_t)(bn + lr) * K + kk] : 0.f;
        }
        __syncthreads();
#pragma unroll
        for (int kk = 0; kk < BK; kk++) {
            float a[4], b[4];
#pragma unroll
            for (int i = 0; i < 4; i++) a[i] = As[kk][ty * 4 + i];
#pragma unroll
            for (int i = 0; i < 4; i++) b[i] = Bs[kk][tx * 4 + i];
#pragma unroll
            for (int i = 0; i < 4; i++)
#pragma unroll
                for (int j = 0; j < 4; j++) acc[i][j] += a[i] * b[j];
        }
        __syncthreads();
    }
#pragma unroll
    for (int i = 0; i < 4; i++) {
        int m = bm + ty * 4 + i;
        if (m >= M) continue;
#pragma unroll
        for (int j = 0; j < 4; j++) {
            int n = bn + tx * 4 + j;
            if (n >= N) continue;
            float v = acc[i][j] + (bias ? bias[n] : 0.f);
            if (addFlag) C[(size_t)m * N + n] += v;
            else         C[(size_t)m * N + n] = v;
        }
    }
}

// ---------------- RMSNorm (block per token, 1280 cols) ---------------------
__global__ void rmsnorm_kernel(const float* __restrict__ x, const float* __restrict__ w,
                               float* __restrict__ h) {
    int s = blockIdx.x;
    const float* xr = x + (size_t)s * HID;
    float ss = 0.f;
    for (int i = threadIdx.x; i < HID; i += 256) { float v = xr[i]; ss += v * v; }
#pragma unroll
    for (int o = 16; o; o >>= 1) ss += __shfl_xor_sync(0xffffffffu, ss, o);
    __shared__ float red[8];
    if ((threadIdx.x & 31) == 0) red[threadIdx.x >> 5] = ss;
    __syncthreads();
    if (threadIdx.x < 8) {
        float v = red[threadIdx.x];
#pragma unroll
        for (int o = 4; o; o >>= 1) v += __shfl_xor_sync(0xffu, v, o);
        if (threadIdx.x == 0) red[0] = v;
    }
    __syncthreads();
    float scale = rsqrtf(red[0] * (1.f / HID) + 1e-6f);
    for (int i = threadIdx.x; i < HID; i += 256)
        h[(size_t)s * HID + i] = xr[i] * scale * w[i];
}

// ---------------- RoPE on q,k inside g_qkv (in-place) ----------------------
__global__ void rope_kernel() {
    int s = blockIdx.x;
    size_t base = (size_t)s * QKV3;
    for (int p = threadIdx.x; p < 2 * HEADS * 40; p += 256) {
        int part = p / (HEADS * 40);
        int rem = p % (HEADS * 40);
        int head = rem / 40, d = rem % 40;
        size_t off = base + part * HID + head * HD + d;
        float c = g_cos[s * HD + d], sn = g_sin[s * HD + d];
        float v0 = g_qkv[off], v1 = g_qkv[off + 40];
        g_qkv[off]      = v0 * c - v1 * sn;
        g_qkv[off + 40] = v1 * c + v0 * sn;
    }
}

// ---------------- Attention (flash-style; windowed or full) ----------------
#define QP 84   // padded row stride for Q/K/V tiles
__global__ void attn_kernel(const float* __restrict__ qkv, float* __restrict__ out,
                            int windowed) {
    extern __shared__ float sm[];
    float* Qs = sm;                 // 64*QP
    float* Ks = Qs + 64 * QP;
    float* Vs = Ks + 64 * QP;
    float* Ss = Vs + 64 * QP;       // 64*65
    int qt = blockIdx.x, head = blockIdx.y;
    int tid = threadIdx.x;
    int row = tid >> 2, l4 = tid & 3;

    for (int i = tid; i < 64 * HD; i += 256) {
        int r = i / HD, d = i % HD;
        Qs[r * QP + d] = qkv[(size_t)(qt * 64 + r) * QKV3 + head * HD + d];
    }
    float M = -1e30f, L = 0.f, O[20];
#pragma unroll
    for (int i = 0; i < 20; i++) O[i] = 0.f;

    int t0 = windowed ? qt : 0;
    int t1 = windowed ? qt + 1 : NTILE64;
    for (int t = t0; t < t1; t++) {
        __syncthreads();
        for (int i = tid; i < 64 * HD; i += 256) {
            int r = i / HD, d = i % HD;
            size_t base = (size_t)(t * 64 + r) * QKV3 + head * HD + d;
            Ks[r * QP + d] = qkv[base + HID];
            Vs[r * QP + d] = qkv[base + 2 * HID];
        }
        __syncthreads();

        float dots[16];
#pragma unroll
        for (int j = 0; j < 16; j++) dots[j] = 0.f;
        for (int d = 0; d < HD; d++) {
            float qd = Qs[row * QP + d];
#pragma unroll
            for (int j = 0; j < 16; j++) dots[j] += qd * Ks[(l4 * 16 + j) * QP + d];
        }
        float tmax = -1e30f;
#pragma unroll
        for (int j = 0; j < 16; j++) {
            dots[j] *= 0.11180339887498949f;   // 80^-0.5
            tmax = fmaxf(tmax, dots[j]);
        }
        tmax = fmaxf(tmax, __shfl_xor_sync(0xffffffffu, tmax, 1));
        tmax = fmaxf(tmax, __shfl_xor_sync(0xffffffffu, tmax, 2));
        float Mnew = fmaxf(M, tmax);
        float alpha = __expf(M - Mnew);
        float lsum = 0.f;
#pragma unroll
        for (int j = 0; j < 16; j++) {
            float p = __expf(dots[j] - Mnew);
            Ss[row * 65 + l4 * 16 + j] = p;
            lsum += p;
        }
        lsum += __shfl_xor_sync(0xffffffffu, lsum, 1);
        lsum += __shfl_xor_sync(0xffffffffu, lsum, 2);
        L = L * alpha + lsum;
        M = Mnew;
#pragma unroll
        for (int i = 0; i < 20; i++) O[i] *= alpha;
        __syncwarp();
        for (int key = 0; key < 64; key++) {
            float p = Ss[row * 65 + key];
#pragma unroll
            for (int i = 0; i < 20; i++) O[i] += p * Vs[key * QP + l4 * 20 + i];
        }
    }
    float inv = 1.f / L;
    int token = qt * 64 + row;
#pragma unroll
    for (int i = 0; i < 20; i++)
        out[(size_t)token * HID + head * HD + l4 * 20 + i] = O[i] * inv;
}

// ---------------- Elementwise ----------------------------------------------
__global__ void silu_mul_kernel(float* __restrict__ gate, const float* __restrict__ up, long n) {
    for (long i = blockIdx.x * (long)blockDim.x + threadIdx.x; i < n;
         i += (long)gridDim.x * blockDim.x) {
        float g = gate[i];
        gate[i] = g / (1.f + __expf(-g)) * up[i];
    }
}
__global__ void gelu_kernel(float* __restrict__ x, long n) {
    for (long i = blockIdx.x * (long)blockDim.x + threadIdx.x; i < n;
         i += (long)gridDim.x * blockDim.x) {
        float v = x[i];
        x[i] = 0.5f * v * (1.f + erff(v * 0.70710678118654752f));
    }
}
__global__ void scatter_out_kernel(const float* __restrict__ src, float* __restrict__ dst) {
    for (long i = blockIdx.x * (long)blockDim.x + threadIdx.x;
         i < (long)GROUPS * OUTDIM; i += (long)gridDim.x * blockDim.x) {
        int g = (int)(i / OUTDIM), n = (int)(i % OUTDIM);
        dst[(size_t)g_wingrp[g] * OUTDIM + n] = src[i];
    }
}

// ---------------- Host orchestration ---------------------------------------
static void run_gemm(const float* A, const float* B, const float* bias, float* C,
                     int M, int N, int K, int add) {
    dim3 grid((N + BN - 1) / BN, (M + BM - 1) / BM);
    gemm_kernel<<<grid, 256>>>(A, B, bias, C, M, N, K, add);
}

extern "C" void kernel_launch(void* const* d_in, const int* in_sizes, int n_in,
                              void* d_out, int out_size) {
    const float* pixel_values = (const float*)d_in[0];
    const float* patch_w = (const float*)d_in[1];
    const float* qkv_w   = (const float*)d_in[2];
    const float* qkv_b   = (const float*)d_in[3];
    const float* proj_w  = (const float*)d_in[4];
    const float* proj_b  = (const float*)d_in[5];
    const float* norm1_w = (const float*)d_in[6];
    const float* norm2_w = (const float*)d_in[7];
    const float* gate_w  = (const float*)d_in[8];
    const float* gate_b  = (const float*)d_in[9];
    const float* up_w    = (const float*)d_in[10];
    const float* up_b    = (const float*)d_in[11];
    const float* down_w  = (const float*)d_in[12];
    const float* down_b  = (const float*)d_in[13];
    const float* ln_q_w  = (const float*)d_in[14];
    const float* m1_w    = (const float*)d_in[15];
    const float* m1_b    = (const float*)d_in[16];
    const float* m2_w    = (const float*)d_in[17];
    const float* m2_b    = (const float*)d_in[18];
    float* out = (float*)d_out;

    float *x, *h, *qkv, *attn, *gate, *up, *pix;
    cudaGetSymbolAddress((void**)&x,    g_x);
    cudaGetSymbolAddress((void**)&h,    g_h);
    cudaGetSymbolAddress((void**)&qkv,  g_qkv);
    cudaGetSymbolAddress((void**)&attn, g_attn);
    cudaGetSymbolAddress((void**)&gate, g_gate);
    cudaGetSymbolAddress((void**)&up,   g_up);
    cudaGetSymbolAddress((void**)&pix,  g_pix);

    static int smem_set = 0;
    int attn_smem = (3 * 64 * QP + 64 * 65) * (int)sizeof(float);
    if (!smem_set) {
        cudaFuncSetAttribute(attn_kernel, cudaFuncAttributeMaxDynamicSharedMemorySize, attn_smem);
        smem_set = 1;
    }

    // indices + rotary tables + permuted pixel gather
    init_kernel<<<(S_TOK + 255) / 256, 256>>>();
    gather_pixels<<<512, 256>>>(pixel_values);

    // patch embed (already in window-permuted token order)
    run_gemm(pix, patch_w, nullptr, x, S_TOK, HID, PIXF, 0);

    for (int i = 0; i < DEPTH; i++) {
        const float* qw = qkv_w + (size_t)i * QKV3 * HID;
        const float* qb = qkv_b + (size_t)i * QKV3;
        const float* pw = proj_w + (size_t)i * HID * HID;
        const float* pb = proj_b + (size_t)i * HID;
        const float* n1 = norm1_w + (size_t)i * HID;
        const float* n2 = norm2_w + (size_t)i * HID;
        const float* gw = gate_w + (size_t)i * INTER * HID;
        const float* gb = gate_b + (size_t)i * INTER;
        const float* uw = up_w + (size_t)i * INTER * HID;
        const float* ub = up_b + (size_t)i * INTER;
        const float* dw = down_w + (size_t)i * HID * INTER;
        const float* db = down_b + (size_t)i * HID;

        rmsnorm_kernel<<<S_TOK, 256>>>(x, n1, h);
        run_gemm(h, qw, qb, qkv, S_TOK, QKV3, HID, 0);
        rope_kernel<<<S_TOK, 256>>>();
        int windowed = (i == 3 || i == 7) ? 0 : 1;
        attn_kernel<<<dim3(NTILE64, HEADS), 256, attn_smem>>>(qkv, attn, windowed);
        run_gemm(attn, pw, pb, x, S_TOK, HID, HID, 1);

        rmsnorm_kernel<<<S_TOK, 256>>>(x, n2, h);
        run_gemm(h, gw, gb, gate, S_TOK, INTER, HID, 0);
        run_gemm(h, uw, ub, up, S_TOK, INTER, HID, 0);
        silu_mul_kernel<<<512, 256>>>(gate, up, (long)S_TOK * INTER);
        run_gemm(gate, dw, db, x, S_TOK, HID, INTER, 1);
    }

    // merger: rmsnorm -> (576, 5120) -> gelu(m1) -> m2 -> scatter rows by win
    rmsnorm_kernel<<<S_TOK, 256>>>(x, ln_q_w, h);
    run_gemm(h, m1_w, m1_b, gate, GROUPS, MERGED, MERGED, 0);   // gate reused: 576*5120
    gelu_kernel<<<512, 256>>>(gate, (long)GROUPS * MERGED);
    run_gemm(gate, m2_w, m2_b, qkv, GROUPS, OUTDIM, MERGED, 0); // qkv reused: 576*3584
    scatter_out_kernel<<<512, 256>>>(qkv, out);
}

// round 2
// speedup vs baseline: 1.9551x; 1.9551x over previous
#include <cuda_runtime.h>
#include <cuda_bf16.h>
#include <math.h>

// ---------------- Problem constants (fixed by setup_inputs) ----------------
#define S_TOK   2304      // T*H*W = 1*48*48
#define HID     1280
#define HEADS   16
#define HD      80
#define DEPTH   8
#define INTER   3420
#define OUTDIM  3584
#define QKV3    3840      // 3*HID
#define GROUPS  576       // S/4
#define PIXF    1176      // 6*14*14
#define MERGED  5120      // 4*HID
#define NTILE64 36        // S/64

// ---------------- Scratch (device globals; no allocation allowed) ----------
__device__ float g_x[S_TOK * HID];
__device__ float g_h[S_TOK * HID];       // also viewed as (576, 5120) for merger
__device__ float g_qkv[S_TOK * QKV3];    // reused for m2 output (576*3584 fits)
__device__ float g_attn[S_TOK * HID];
__device__ float g_gate[S_TOK * INTER];  // reused for m1 output (576*5120 fits)
__device__ float g_up[S_TOK * INTER];
__device__ float g_pix[S_TOK * PIXF];
__device__ float g_cos[S_TOK * HD];
__device__ float g_sin[S_TOK * HD];
__device__ int   g_orig[S_TOK];          // permuted token -> original pixel row
__device__ int   g_wingrp[GROUPS];       // win[g]: output scatter target row

// ---------------- Index + rotary precompute --------------------------------
__global__ void init_kernel() {
    int s = blockIdx.x * blockDim.x + threadIdx.x;
    if (s >= S_TOK) return;
    int g = s >> 2, r = s & 3;
    int hb = g / 96, wb = (g / 16) % 6, hr = (g % 16) / 4, wr = g & 3;
    int og = (hb * 4 + hr) * 24 + (wb * 4 + wr);
    g_orig[s] = og * 4 + r;
    if (r == 0) g_wingrp[g] = og;
    int hg = og / 24, wg = og % 24;
    int hh = hg * 2 + (r >> 1), ww = wg * 2 + (r & 1);
    for (int j = 0; j < 40; j++) {
        float invf = powf(10000.f, -(float)(j % 20) / 20.f);
        float ang = (float)((j < 20) ? hh : ww) * invf;
        float c = cosf(ang), sn = sinf(ang);
        g_cos[s * HD + j] = c;  g_cos[s * HD + 40 + j] = c;
        g_sin[s * HD + j] = sn; g_sin[s * HD + 40 + j] = sn;
    }
}

__global__ void gather_pixels(const float* __restrict__ pix) {
    for (long i = blockIdx.x * (long)blockDim.x + threadIdx.x;
         i < (long)S_TOK * PIXF; i += (long)gridDim.x * blockDim.x) {
        int s = (int)(i / PIXF), c = (int)(i % PIXF);
        g_pix[i] = pix[(long)g_orig[s] * PIXF + c];
    }
}

// ============ Split-bf16 tensor-core GEMM: C[M,N](+)=A[M,K]@B[N,K]^T+bias ===
// Accuracy trick: a = a_hi + a_lo (bf16 each). D = ahi*bhi + alo*bhi + ahi*blo
// leaves only the ~2^-18 alo*blo term -> fp32-grade result from bf16 MMAs.
#define GBM 128
#define GBN 64
#define GBK 32
#define SKA 36   // padded bf16 row stride (conflict-free fragment loads)

__device__ __forceinline__ void mma16816(float* c, const unsigned* a, const unsigned* b) {
    asm volatile(
        "mma.sync.aligned.m16n8k16.row.col.f32.bf16.bf16.f32 "
        "{%0,%1,%2,%3}, {%4,%5,%6,%7}, {%8,%9}, {%0,%1,%2,%3};\n"
        : "+f"(c[0]), "+f"(c[1]), "+f"(c[2]), "+f"(c[3])
        : "r"(a[0]), "r"(a[1]), "r"(a[2]), "r"(a[3]), "r"(b[0]), "r"(b[1]));
}

__global__ __launch_bounds__(256, 2)
void gemm_tc_kernel(const float* __restrict__ A, const float* __restrict__ B,
                    const float* __restrict__ bias, float* __restrict__ C,
                    int M, int N, int K, int addFlag) {
    __shared__ __nv_bfloat16 sAhi[GBM * SKA];
    __shared__ __nv_bfloat16 sAlo[GBM * SKA];
    __shared__ __nv_bfloat16 sBhi[GBN * SKA];
    __shared__ __nv_bfloat16 sBlo[GBN * SKA];

    int bm = blockIdx.y * GBM, bn = blockIdx.x * GBN;
    int tid = threadIdx.x;
    int wid = tid >> 5, lane = tid & 31;
    int wm = (wid & 3) * 32;     // warp row offset in block tile
    int wn = (wid >> 2) * 32;    // warp col offset in block tile
    int gid = lane >> 2, qid = lane & 3;

    float acc[2][4][4];
#pragma unroll
    for (int mi = 0; mi < 2; mi++)
#pragma unroll
        for (int ni = 0; ni < 4; ni++)
#pragma unroll
            for (int r = 0; r < 4; r++) acc[mi][ni][r] = 0.f;

    for (int k0 = 0; k0 < K; k0 += GBK) {
        // ---- load A tile (128 x 32) split hi/lo ----
#pragma unroll
        for (int it = 0; it < 4; it++) {
            int i = tid + it * 256;             // 1024 float4 slots
            int row = i >> 3, q = i & 7;
            int gm = bm + row, k = k0 + q * 4;
            float4 v = make_float4(0.f, 0.f, 0.f, 0.f);
            if (gm < M && k < K) v = *(const float4*)(A + (size_t)gm * K + k);
            __nv_bfloat16 h0 = __float2bfloat16(v.x), h1 = __float2bfloat16(v.y);
            __nv_bfloat16 h2 = __float2bfloat16(v.z), h3 = __float2bfloat16(v.w);
            __nv_bfloat16 l0 = __float2bfloat16(v.x - __bfloat162float(h0));
            __nv_bfloat16 l1 = __float2bfloat16(v.y - __bfloat162float(h1));
            __nv_bfloat16 l2 = __float2bfloat16(v.z - __bfloat162float(h2));
            __nv_bfloat16 l3 = __float2bfloat16(v.w - __bfloat162float(h3));
            int off = row * SKA + q * 4;
            *(__nv_bfloat162*)(sAhi + off)     = __nv_bfloat162(h0, h1);
            *(__nv_bfloat162*)(sAhi + off + 2) = __nv_bfloat162(h2, h3);
            *(__nv_bfloat162*)(sAlo + off)     = __nv_bfloat162(l0, l1);
            *(__nv_bfloat162*)(sAlo + off + 2) = __nv_bfloat162(l2, l3);
        }
        // ---- load B tile (64 x 32) split hi/lo ----
#pragma unroll
        for (int it = 0; it < 2; it++) {
            int i = tid + it * 256;             // 512 float4 slots
            int row = i >> 3, q = i & 7;
            int gn = bn + row, k = k0 + q * 4;
            float4 v = make_float4(0.f, 0.f, 0.f, 0.f);
            if (gn < N && k < K) v = *(const float4*)(B + (size_t)gn * K + k);
            __nv_bfloat16 h0 = __float2bfloat16(v.x), h1 = __float2bfloat16(v.y);
            __nv_bfloat16 h2 = __float2bfloat16(v.z), h3 = __float2bfloat16(v.w);
            __nv_bfloat16 l0 = __float2bfloat16(v.x - __bfloat162float(h0));
            __nv_bfloat16 l1 = __float2bfloat16(v.y - __bfloat162float(h1));
            __nv_bfloat16 l2 = __float2bfloat16(v.z - __bfloat162float(h2));
            __nv_bfloat16 l3 = __float2bfloat16(v.w - __bfloat162float(h3));
            int off = row * SKA + q * 4;
            *(__nv_bfloat162*)(sBhi + off)     = __nv_bfloat162(h0, h1);
            *(__nv_bfloat162*)(sBhi + off + 2) = __nv_bfloat162(h2, h3);
            *(__nv_bfloat162*)(sBlo + off)     = __nv_bfloat162(l0, l1);
            *(__nv_bfloat162*)(sBlo + off + 2) = __nv_bfloat162(l2, l3);
        }
        __syncthreads();

#pragma unroll
        for (int ks = 0; ks < GBK; ks += 16) {
            unsigned ah[2][4], al[2][4], bh[4][2], bl[4][2];
#pragma unroll
            for (int mi = 0; mi < 2; mi++) {
                int r0 = wm + mi * 16 + gid;
                int c0 = ks + qid * 2;
                ah[mi][0] = *(const unsigned*)(sAhi + r0 * SKA + c0);
                ah[mi][1] = *(const unsigned*)(sAhi + (r0 + 8) * SKA + c0);
                ah[mi][2] = *(const unsigned*)(sAhi + r0 * SKA + c0 + 8);
                ah[mi][3] = *(const unsigned*)(sAhi + (r0 + 8) * SKA + c0 + 8);
                al[mi][0] = *(const unsigned*)(sAlo + r0 * SKA + c0);
                al[mi][1] = *(const unsigned*)(sAlo + (r0 + 8) * SKA + c0);
                al[mi][2] = *(const unsigned*)(sAlo + r0 * SKA + c0 + 8);
                al[mi][3] = *(const unsigned*)(sAlo + (r0 + 8) * SKA + c0 + 8);
            }
#pragma unroll
            for (int ni = 0; ni < 4; ni++) {
                int n0 = wn + ni * 8 + gid;
                int c0 = ks + qid * 2;
                bh[ni][0] = *(const unsigned*)(sBhi + n0 * SKA + c0);
                bh[ni][1] = *(const unsigned*)(sBhi + n0 * SKA + c0 + 8);
                bl[ni][0] = *(const unsigned*)(sBlo + n0 * SKA + c0);
                bl[ni][1] = *(const unsigned*)(sBlo + n0 * SKA + c0 + 8);
            }
#pragma unroll
            for (int mi = 0; mi < 2; mi++)
#pragma unroll
                for (int ni = 0; ni < 4; ni++) {
                    mma16816(acc[mi][ni], ah[mi], bh[ni]);
                    mma16816(acc[mi][ni], al[mi], bh[ni]);
                    mma16816(acc[mi][ni], ah[mi], bl[ni]);
                }
        }
        __syncthreads();
    }

    // ---- epilogue ----
#pragma unroll
    for (int mi = 0; mi < 2; mi++) {
#pragma unroll
        for (int ni = 0; ni < 4; ni++) {
#pragma unroll
            for (int r = 0; r < 4; r++) {
                int m = bm + wm + mi * 16 + gid + (r >> 1) * 8;
                int n = bn + wn + ni * 8 + qid * 2 + (r & 1);
                if (m < M && n < N) {
                    float v = acc[mi][ni][r] + (bias ? bias[n] : 0.f);
                    if (addFlag) C[(size_t)m * N + n] += v;
                    else         C[(size_t)m * N + n] = v;
                }
            }
        }
    }
}

// ---------------- RMSNorm (block per token, 1280 cols) ---------------------
__global__ void rmsnorm_kernel(const float* __restrict__ x, const float* __restrict__ w,
                               float* __restrict__ h) {
    int s = blockIdx.x;
    const float* xr = x + (size_t)s * HID;
    float ss = 0.f;
    for (int i = threadIdx.x; i < HID; i += 256) { float v = xr[i]; ss += v * v; }
#pragma unroll
    for (int o = 16; o; o >>= 1) ss += __shfl_xor_sync(0xffffffffu, ss, o);
    __shared__ float red[8];
    if ((threadIdx.x & 31) == 0) red[threadIdx.x >> 5] = ss;
    __syncthreads();
    if (threadIdx.x < 8) {
        float v = red[threadIdx.x];
#pragma unroll
        for (int o = 4; o; o >>= 1) v += __shfl_xor_sync(0xffu, v, o);
        if (threadIdx.x == 0) red[0] = v;
    }
    __syncthreads();
    float scale = rsqrtf(red[0] * (1.f / HID) + 1e-6f);
    for (int i = threadIdx.x; i < HID; i += 256)
        h[(size_t)s * HID + i] = xr[i] * scale * w[i];
}

// ---------------- RoPE on q,k inside g_qkv (in-place) ----------------------
__global__ void rope_kernel() {
    int s = blockIdx.x;
    size_t base = (size_t)s * QKV3;
    for (int p = threadIdx.x; p < 2 * HEADS * 40; p += 256) {
        int part = p / (HEADS * 40);
        int rem = p % (HEADS * 40);
        int head = rem / 40, d = rem % 40;
        size_t off = base + part * HID + head * HD + d;
        float c = g_cos[s * HD + d], sn = g_sin[s * HD + d];
        float v0 = g_qkv[off], v1 = g_qkv[off + 40];
        g_qkv[off]      = v0 * c - v1 * sn;
        g_qkv[off + 40] = v1 * c + v0 * sn;
    }
}

// ---------------- Attention (flash-style; windowed or full) ----------------
#define QP 84   // padded row stride for Q/K/V tiles
__global__ void attn_kernel(const float* __restrict__ qkv, float* __restrict__ out,
                            int windowed) {
    extern __shared__ float sm[];
    float* Qs = sm;                 // 64*QP
    float* Ks = Qs + 64 * QP;
    float* Vs = Ks + 64 * QP;
    float* Ss = Vs + 64 * QP;       // 64*65
    int qt = blockIdx.x, head = blockIdx.y;
    int tid = threadIdx.x;
    int row = tid >> 2, l4 = tid & 3;

    for (int i = tid; i < 64 * HD; i += 256) {
        int r = i / HD, d = i % HD;
        Qs[r * QP + d] = qkv[(size_t)(qt * 64 + r) * QKV3 + head * HD + d];
    }
    float M = -1e30f, L = 0.f, O[20];
#pragma unroll
    for (int i = 0; i < 20; i++) O[i] = 0.f;

    int t0 = windowed ? qt : 0;
    int t1 = windowed ? qt + 1 : NTILE64;
    for (int t = t0; t < t1; t++) {
        __syncthreads();
        for (int i = tid; i < 64 * HD; i += 256) {
            int r = i / HD, d = i % HD;
            size_t base = (size_t)(t * 64 + r) * QKV3 + head * HD + d;
            Ks[r * QP + d] = qkv[base + HID];
            Vs[r * QP + d] = qkv[base + 2 * HID];
        }
        __syncthreads();

        float dots[16];
#pragma unroll
        for (int j = 0; j < 16; j++) dots[j] = 0.f;
        for (int d = 0; d < HD; d++) {
            float qd = Qs[row * QP + d];
#pragma unroll
            for (int j = 0; j < 16; j++) dots[j] += qd * Ks[(l4 * 16 + j) * QP + d];
        }
        float tmax = -1e30f;
#pragma unroll
        for (int j = 0; j < 16; j++) {
            dots[j] *= 0.11180339887498949f;   // 80^-0.5
            tmax = fmaxf(tmax, dots[j]);
        }
        tmax = fmaxf(tmax, __shfl_xor_sync(0xffffffffu, tmax, 1));
        tmax = fmaxf(tmax, __shfl_xor_sync(0xffffffffu, tmax, 2));
        float Mnew = fmaxf(M, tmax);
        float alpha = __expf(M - Mnew);
        float lsum = 0.f;
#pragma unroll
        for (int j = 0; j < 16; j++) {
            float p = __expf(dots[j] - Mnew);
            Ss[row * 65 + l4 * 16 + j] = p;
            lsum += p;
        }
        lsum += __shfl_xor_sync(0xffffffffu, lsum, 1);
        lsum += __shfl_xor_sync(0xffffffffu, lsum, 2);
        L = L * alpha + lsum;
        M = Mnew;
#pragma unroll
        for (int i = 0; i < 20; i++) O[i] *= alpha;
        __syncwarp();
        for (int key = 0; key < 64; key++) {
            float p = Ss[row * 65 + key];
#pragma unroll
            for (int i = 0; i < 20; i++) O[i] += p * Vs[key * QP + l4 * 20 + i];
        }
    }
    float inv = 1.f / L;
    int token = qt * 64 + row;
#pragma unroll
    for (int i = 0; i < 20; i++)
        out[(size_t)token * HID + head * HD + l4 * 20 + i] = O[i] * inv;
}

// ---------------- Elementwise ----------------------------------------------
__global__ void silu_mul_kernel(float* __restrict__ gate, const float* __restrict__ up, long n) {
    for (long i = blockIdx.x * (long)blockDim.x + threadIdx.x; i < n;
         i += (long)gridDim.x * blockDim.x) {
        float g = gate[i];
        gate[i] = g / (1.f + __expf(-g)) * up[i];
    }
}
__global__ void gelu_kernel(float* __restrict__ x, long n) {
    for (long i = blockIdx.x * (long)blockDim.x + threadIdx.x; i < n;
         i += (long)gridDim.x * blockDim.x) {
        float v = x[i];
        x[i] = 0.5f * v * (1.f + erff(v * 0.70710678118654752f));
    }
}
__global__ void scatter_out_kernel(const float* __restrict__ src, float* __restrict__ dst) {
    for (long i = blockIdx.x * (long)blockDim.x + threadIdx.x;
         i < (long)GROUPS * OUTDIM; i += (long)gridDim.x * blockDim.x) {
        int g = (int)(i / OUTDIM), n = (int)(i % OUTDIM);
        dst[(size_t)g_wingrp[g] * OUTDIM + n] = src[i];
    }
}

// ---------------- Host orchestration ---------------------------------------
static void run_gemm(const float* A, const float* B, const float* bias, float* C,
                     int M, int N, int K, int add) {
    dim3 grid((N + GBN - 1) / GBN, (M + GBM - 1) / GBM);
    gemm_tc_kernel<<<grid, 256>>>(A, B, bias, C, M, N, K, add);
}

extern "C" void kernel_launch(void* const* d_in, const int* in_sizes, int n_in,
                              void* d_out, int out_size) {
    const float* pixel_values = (const float*)d_in[0];
    const float* patch_w = (const float*)d_in[1];
    const float* qkv_w   = (const float*)d_in[2];
    const float* qkv_b   = (const float*)d_in[3];
    const float* proj_w  = (const float*)d_in[4];
    const float* proj_b  = (const float*)d_in[5];
    const float* norm1_w = (const float*)d_in[6];
    const float* norm2_w = (const float*)d_in[7];
    const float* gate_w  = (const float*)d_in[8];
    const float* gate_b  = (const float*)d_in[9];
    const float* up_w    = (const float*)d_in[10];
    const float* up_b    = (const float*)d_in[11];
    const float* down_w  = (const float*)d_in[12];
    const float* down_b  = (const float*)d_in[13];
    const float* ln_q_w  = (const float*)d_in[14];
    const float* m1_w    = (const float*)d_in[15];
    const float* m1_b    = (const float*)d_in[16];
    const float* m2_w    = (const float*)d_in[17];
    const float* m2_b    = (const float*)d_in[18];
    float* out = (float*)d_out;

    float *x, *h, *qkv, *attn, *gate, *up, *pix;
    cudaGetSymbolAddress((void**)&x,    g_x);
    cudaGetSymbolAddress((void**)&h,    g_h);
    cudaGetSymbolAddress((void**)&qkv,  g_qkv);
    cudaGetSymbolAddress((void**)&attn, g_attn);
    cudaGetSymbolAddress((void**)&gate, g_gate);
    cudaGetSymbolAddress((void**)&up,   g_up);
    cudaGetSymbolAddress((void**)&pix,  g_pix);

    static int smem_set = 0;
    int attn_smem = (3 * 64 * QP + 64 * 65) * (int)sizeof(float);
    if (!smem_set) {
        cudaFuncSetAttribute(attn_kernel, cudaFuncAttributeMaxDynamicSharedMemorySize, attn_smem);
        smem_set = 1;
    }

    init_kernel<<<(S_TOK + 255) / 256, 256>>>();
    gather_pixels<<<512, 256>>>(pixel_values);

    run_gemm(pix, patch_w, nullptr, x, S_TOK, HID, PIXF, 0);

    for (int i = 0; i < DEPTH; i++) {
        const float* qw = qkv_w + (size_t)i * QKV3 * HID;
        const float* qb = qkv_b + (size_t)i * QKV3;
        const float* pw = proj_w + (size_t)i * HID * HID;
        const float* pb = proj_b + (size_t)i * HID;
        const float* n1 = norm1_w + (size_t)i * HID;
        const float* n2 = norm2_w + (size_t)i * HID;
        const float* gw = gate_w + (size_t)i * INTER * HID;
        const float* gb = gate_b + (size_t)i * INTER;
        const float* uw = up_w + (size_t)i * INTER * HID;
        const float* ub = up_b + (size_t)i * INTER;
        const float* dw = down_w + (size_t)i * HID * INTER;
        const float* db = down_b + (size_t)i * HID;

        rmsnorm_kernel<<<S_TOK, 256>>>(x, n1, h);
        run_gemm(h, qw, qb, qkv, S_TOK, QKV3, HID, 0);
        rope_kernel<<<S_TOK, 256>>>();
        int windowed = (i == 3 || i == 7) ? 0 : 1;
        attn_kernel<<<dim3(NTILE64, HEADS), 256, attn_smem>>>(qkv, attn, windowed);
        run_gemm(attn, pw, pb, x, S_TOK, HID, HID, 1);

        rmsnorm_kernel<<<S_TOK, 256>>>(x, n2, h);
        run_gemm(h, gw, gb, gate, S_TOK, INTER, HID, 0);
        run_gemm(h, uw, ub, up, S_TOK, INTER, HID, 0);
        silu_mul_kernel<<<512, 256>>>(gate, up, (long)S_TOK * INTER);
        run_gemm(gate, dw, db, x, S_TOK, HID, INTER, 1);
    }

    rmsnorm_kernel<<<S_TOK, 256>>>(x, ln_q_w, h);
    run_gemm(h, m1_w, m1_b, gate, GROUPS, MERGED, MERGED, 0);
    gelu_kernel<<<512, 256>>>(gate, (long)GROUPS * MERGED);
    run_gemm(gate, m2_w, m2_b, qkv, GROUPS, OUTDIM, MERGED, 0);
    scatter_out_kernel<<<512, 256>>>(qkv, out);
}

// round 4
// speedup vs baseline: 2.0858x; 1.0669x over previous
#include <cuda_runtime.h>
#include <cuda_bf16.h>
#include <math.h>

// ---------------- Problem constants (fixed by setup_inputs) ----------------
#define S_TOK   2304
#define HID     1280
#define HEADS   16
#define HD      80
#define DEPTH   8
#define INTER   3420
#define INTER_P 3424     // padded to 16B-aligned rows (3424*2 = 6848 = 428*16)
#define OUTDIM  3584
#define QKV3    3840
#define GROUPS  576
#define PIXF    1176
#define MERGED  5120
#define NTILE64 36

// ---------------- Weight arena offsets (elements) ---------------------------
#define OFF_PATCH 0L
#define SZ_PATCH  (1280L*1176)
#define OFF_QKV   (OFF_PATCH + SZ_PATCH)
#define SZ_QKV    (8L*3840*1280)
#define OFF_PROJ  (OFF_QKV + SZ_QKV)
#define SZ_PROJ   (8L*1280*1280)
#define OFF_GATE  (OFF_PROJ + SZ_PROJ)
#define SZ_GATE   (8L*3420*1280)
#define OFF_UP    (OFF_GATE + SZ_GATE)
#define SZ_UP     (8L*3420*1280)
#define OFF_DOWN  (OFF_UP + SZ_UP)
#define SZ_DOWN   (8L*1280*INTER_P)     // padded K stride
#define OFF_M1    (OFF_DOWN + SZ_DOWN)
#define SZ_M1     (5120L*5120)
#define OFF_M2    (OFF_M1 + SZ_M1)
#define SZ_M2     (3584L*5120)
#define W_TOTAL   (OFF_M2 + SZ_M2)

// ---------------- Scratch (device globals) ----------------------------------
__device__ __nv_bfloat16 g_whi[W_TOTAL];
__device__ __nv_bfloat16 g_wlo[W_TOTAL];
__device__ float g_x[S_TOK * HID];
__device__ float g_qkv[S_TOK * QKV3];      // reused for m2 output
__device__ float g_gate[S_TOK * INTER];    // reused for m1 output
__device__ float g_up[S_TOK * INTER];
__device__ __nv_bfloat16 g_hhi[S_TOK * HID],  g_hlo[S_TOK * HID];
__device__ __nv_bfloat16 g_athi[S_TOK * HID], g_atlo[S_TOK * HID];
__device__ __nv_bfloat16 g_achi[S_TOK * INTER_P], g_aclo[S_TOK * INTER_P];
__device__ __nv_bfloat16 g_pxhi[S_TOK * PIXF], g_pxlo[S_TOK * PIXF];
__device__ float g_cos[S_TOK * HD];
__device__ float g_sin[S_TOK * HD];
__device__ int   g_orig[S_TOK];
__device__ int   g_wingrp[GROUPS];

// ---------------- helpers ----------------------------------------------------
__device__ __forceinline__ void split1(float v, __nv_bfloat16& h, __nv_bfloat16& l) {
    h = __float2bfloat16(v);
    l = __float2bfloat16(v - __bfloat162float(h));
}

// ---------------- Index + rotary precompute ---------------------------------
__global__ void init_kernel() {
    int s = blockIdx.x * blockDim.x + threadIdx.x;
    if (s >= S_TOK) return;
    int g = s >> 2, r = s & 3;
    int hb = g / 96, wb = (g / 16) % 6, hr = (g % 16) / 4, wr = g & 3;
    int og = (hb * 4 + hr) * 24 + (wb * 4 + wr);
    g_orig[s] = og * 4 + r;
    if (r == 0) g_wingrp[g] = og;
    int hg = og / 24, wg = og % 24;
    int hh = hg * 2 + (r >> 1), ww = wg * 2 + (r & 1);
    for (int j = 0; j < 40; j++) {
        float invf = powf(10000.f, -(float)(j % 20) / 20.f);
        float ang = (float)((j < 20) ? hh : ww) * invf;
        float c = cosf(ang), sn = sinf(ang);
        g_cos[s * HD + j] = c;  g_cos[s * HD + 40 + j] = c;
        g_sin[s * HD + j] = sn; g_sin[s * HD + 40 + j] = sn;
    }
}

__global__ void gather_pixels(const float* __restrict__ pix) {
    for (long i = blockIdx.x * (long)blockDim.x + threadIdx.x;
         i < (long)S_TOK * PIXF; i += (long)gridDim.x * blockDim.x) {
        int s = (int)(i / PIXF), c = (int)(i % PIXF);
        split1(pix[(long)g_orig[s] * PIXF + c], g_pxhi[i], g_pxlo[i]);
    }
}

// ---------------- Weight split (fp32 -> bf16 hi/lo) --------------------------
__global__ void split_w_kernel(const float* __restrict__ src,
                               __nv_bfloat16* __restrict__ hi,
                               __nv_bfloat16* __restrict__ lo, long n4) {
    for (long i = blockIdx.x * (long)blockDim.x + threadIdx.x; i < n4;
         i += (long)gridDim.x * blockDim.x) {
        float4 v = ((const float4*)src)[i];
        __nv_bfloat16 h0, h1, h2, h3, l0, l1, l2, l3;
        split1(v.x, h0, l0); split1(v.y, h1, l1);
        split1(v.z, h2, l2); split1(v.w, h3, l3);
        ((__nv_bfloat162*)hi)[2*i]   = __nv_bfloat162(h0, h1);
        ((__nv_bfloat162*)hi)[2*i+1] = __nv_bfloat162(h2, h3);
        ((__nv_bfloat162*)lo)[2*i]   = __nv_bfloat162(l0, l1);
        ((__nv_bfloat162*)lo)[2*i+1] = __nv_bfloat162(l2, l3);
    }
}

// down_w: split with row padding 3420 -> 3424 (pad = zeros)
__global__ void split_down_kernel(const float* __restrict__ src,
                                  __nv_bfloat16* __restrict__ hi,
                                  __nv_bfloat16* __restrict__ lo) {
    long total = 8L * 1280 * INTER_P;
    for (long i = blockIdx.x * (long)blockDim.x + threadIdx.x; i < total;
         i += (long)gridDim.x * blockDim.x) {
        long row = i / INTER_P;
        int col = (int)(i % INTER_P);
        float v = (col < INTER) ? src[row * INTER + col] : 0.f;
        split1(v, hi[i], lo[i]);
    }
}

// ============ Split-bf16 tensor-core GEMM ====================================
// C[M,N] (+)= A[M,K] @ B[N,K]^T + bias, A/B pre-split bf16 hi/lo.
#define GBM 128
#define GBN 128
#define GBK 32
#define SKA 40
#define STG (4 * 128 * SKA)

__device__ __forceinline__ void mma16816(float* c, const unsigned* a, const unsigned* b) {
    asm volatile(
        "mma.sync.aligned.m16n8k16.row.col.f32.bf16.bf16.f32 "
        "{%0,%1,%2,%3}, {%4,%5,%6,%7}, {%8,%9}, {%0,%1,%2,%3};\n"
        : "+f"(c[0]), "+f"(c[1]), "+f"(c[2]), "+f"(c[3])
        : "r"(a[0]), "r"(a[1]), "r"(a[2]), "r"(a[3]), "r"(b[0]), "r"(b[1]));
}

__device__ __forceinline__ void cpa16(__nv_bfloat16* dst, const __nv_bfloat16* src, int sz) {
    unsigned d = (unsigned)__cvta_generic_to_shared(dst);
    asm volatile("cp.async.cg.shared.global [%0], [%1], 16, %2;\n"
                 :: "r"(d), "l"(src), "r"(sz));
}

__global__ __launch_bounds__(256, 1)
void gemm_tc_kernel(const __nv_bfloat16* __restrict__ Ahi, const __nv_bfloat16* __restrict__ Alo,
                    const __nv_bfloat16* __restrict__ Bhi, const __nv_bfloat16* __restrict__ Blo,
                    const float* __restrict__ bias, float* __restrict__ C,
                    int M, int N, int K, int addFlag) {
    extern __shared__ __nv_bfloat16 smem[];
    int bm = blockIdx.y * GBM, bn = blockIdx.x * GBN;
    int tid = threadIdx.x;
    int wid = tid >> 5, lane = tid & 31;
    int wm = (wid & 1) * 64;
    int wn = (wid >> 1) * 32;
    int gid = lane >> 2, qid = lane & 3;

    float acc[4][4][4];
#pragma unroll
    for (int mi = 0; mi < 4; mi++)
#pragma unroll
        for (int ni = 0; ni < 4; ni++)
#pragma unroll
            for (int r = 0; r < 4; r++) acc[mi][ni][r] = 0.f;

    int nT = (K + GBK - 1) / GBK;

    auto load_tile = [&](int k0, int st) {
        __nv_bfloat16* base = smem + st * STG;
#pragma unroll
        for (int it = 0; it < 2; it++) {
            int c = tid + it * 256;
            int row = c >> 2, seg = c & 3;
            int kk = k0 + seg * 8;
            int rem = K - kk;
            int ksz = rem >= 8 ? 16 : (rem >= 4 ? 8 : 0);
            int gm = bm + row;
            int szA = (gm < M) ? ksz : 0;
            size_t offA = szA ? ((size_t)gm * K + kk) : 0;
            int gn = bn + row;
            int szB = (gn < N) ? ksz : 0;
            size_t offB = szB ? ((size_t)gn * K + kk) : 0;
            int so = row * SKA + seg * 8;
            cpa16(base + so,                 Ahi + offA, szA);
            cpa16(base + 128 * SKA + so,     Alo + offA, szA);
            cpa16(base + 2 * 128 * SKA + so, Bhi + offB, szB);
            cpa16(base + 3 * 128 * SKA + so, Blo + offB, szB);
        }
        asm volatile("cp.async.commit_group;\n" ::);
    };

    load_tile(0, 0);

    for (int t = 0; t < nT; t++) {
        asm volatile("cp.async.wait_group 0;\n" ::);
        __syncthreads();
        if (t + 1 < nT) load_tile((t + 1) * GBK, (t + 1) & 1);

        const __nv_bfloat16* sAh = smem + (t & 1) * STG;
        const __nv_bfloat16* sAl = sAh + 128 * SKA;
        const __nv_bfloat16* sBh = sAh + 2 * 128 * SKA;
        const __nv_bfloat16* sBl = sAh + 3 * 128 * SKA;

#pragma unroll
        for (int ks = 0; ks < GBK; ks += 16) {
            unsigned ah[4][4], al[4][4], bh[4][2], bl[4][2];
            int c0 = ks + qid * 2;
#pragma unroll
            for (int mi = 0; mi < 4; mi++) {
                int r0 = wm + mi * 16 + gid;
                ah[mi][0] = *(const unsigned*)(sAh + r0 * SKA + c0);
                ah[mi][1] = *(const unsigned*)(sAh + (r0 + 8) * SKA + c0);
                ah[mi][2] = *(const unsigned*)(sAh + r0 * SKA + c0 + 8);
                ah[mi][3] = *(const unsigned*)(sAh + (r0 + 8) * SKA + c0 + 8);
                al[mi][0] = *(const unsigned*)(sAl + r0 * SKA + c0);
                al[mi][1] = *(const unsigned*)(sAl + (r0 + 8) * SKA + c0);
                al[mi][2] = *(const unsigned*)(sAl + r0 * SKA + c0 + 8);
                al[mi][3] = *(const unsigned*)(sAl + (r0 + 8) * SKA + c0 + 8);
            }
#pragma unroll
            for (int ni = 0; ni < 4; ni++) {
                int n0 = wn + ni * 8 + gid;
                bh[ni][0] = *(const unsigned*)(sBh + n0 * SKA + c0);
                bh[ni][1] = *(const unsigned*)(sBh + n0 * SKA + c0 + 8);
                bl[ni][0] = *(const unsigned*)(sBl + n0 * SKA + c0);
                bl[ni][1] = *(const unsigned*)(sBl + n0 * SKA + c0 + 8);
            }
#pragma unroll
            for (int mi = 0; mi < 4; mi++)
#pragma unroll
                for (int ni = 0; ni < 4; ni++) {
                    mma16816(acc[mi][ni], ah[mi], bh[ni]);
                    mma16816(acc[mi][ni], al[mi], bh[ni]);
                    mma16816(acc[mi][ni], ah[mi], bl[ni]);
                }
        }
        __syncthreads();
    }

#pragma unroll
    for (int mi = 0; mi < 4; mi++) {
#pragma unroll
        for (int rr = 0; rr < 2; rr++) {
            int m = bm + wm + mi * 16 + gid + rr * 8;
            if (m >= M) continue;
#pragma unroll
            for (int ni = 0; ni < 4; ni++) {
                int n = bn + wn + ni * 8 + qid * 2;
                if (n >= N) continue;
                float v0 = acc[mi][ni][rr * 2]     + (bias ? bias[n] : 0.f);
                float v1 = acc[mi][ni][rr * 2 + 1] + (bias ? bias[n + 1] : 0.f);
                float* p = C + (size_t)m * N + n;
                if (addFlag) { p[0] += v0; p[1] += v1; }
                else { *(float2*)p = make_float2(v0, v1); }
            }
        }
    }
}

// ---------------- RMSNorm -> bf16 hi/lo --------------------------------------
__global__ void rmsnorm_kernel(const float* __restrict__ x, const float* __restrict__ w,
                               __nv_bfloat16* __restrict__ hi, __nv_bfloat16* __restrict__ lo) {
    int s = blockIdx.x;
    const float* xr = x + (size_t)s * HID;
    float ss = 0.f;
    for (int i = threadIdx.x; i < HID; i += 256) { float v = xr[i]; ss += v * v; }
#pragma unroll
    for (int o = 16; o; o >>= 1) ss += __shfl_xor_sync(0xffffffffu, ss, o);
    __shared__ float red[8];
    if ((threadIdx.x & 31) == 0) red[threadIdx.x >> 5] = ss;
    __syncthreads();
    if (threadIdx.x < 8) {
        float v = red[threadIdx.x];
#pragma unroll
        for (int o = 4; o; o >>= 1) v += __shfl_xor_sync(0xffu, v, o);
        if (threadIdx.x == 0) red[0] = v;
    }
    __syncthreads();
    float scale = rsqrtf(red[0] * (1.f / HID) + 1e-6f);
    for (int i = threadIdx.x; i < HID; i += 256)
        split1(xr[i] * scale * w[i], hi[(size_t)s * HID + i], lo[(size_t)s * HID + i]);
}

// ---------------- RoPE on q,k inside g_qkv ----------------------------------
__global__ void rope_kernel() {
    int s = blockIdx.x;
    size_t base = (size_t)s * QKV3;
    for (int p = threadIdx.x; p < 2 * HEADS * 40; p += 256) {
        int part = p / (HEADS * 40);
        int rem = p % (HEADS * 40);
        int head = rem / 40, d = rem % 40;
        size_t off = base + part * HID + head * HD + d;
        float c = g_cos[s * HD + d], sn = g_sin[s * HD + d];
        float v0 = g_qkv[off], v1 = g_qkv[off + 40];
        g_qkv[off]      = v0 * c - v1 * sn;
        g_qkv[off + 40] = v1 * c + v0 * sn;
    }
}

// ---------------- Attention (flash-style; windowed or full) -----------------
#define QP 84
__global__ void attn_kernel(const float* __restrict__ qkv,
                            __nv_bfloat16* __restrict__ ohi, __nv_bfloat16* __restrict__ olo,
                            int windowed) {
    extern __shared__ float sm[];
    float* Qs = sm;
    float* Ks = Qs + 64 * QP;
    float* Vs = Ks + 64 * QP;
    float* Ss = Vs + 64 * QP;
    int qt = blockIdx.x, head = blockIdx.y;
    int tid = threadIdx.x;
    int row = tid >> 2, l4 = tid & 3;

    for (int i = tid; i < 64 * HD; i += 256) {
        int r = i / HD, d = i % HD;
        Qs[r * QP + d] = qkv[(size_t)(qt * 64 + r) * QKV3 + head * HD + d];
    }
    float M = -1e30f, L = 0.f, O[20];
#pragma unroll
    for (int i = 0; i < 20; i++) O[i] = 0.f;

    int t0 = windowed ? qt : 0;
    int t1 = windowed ? qt + 1 : NTILE64;
    for (int t = t0; t < t1; t++) {
        __syncthreads();
        for (int i = tid; i < 64 * HD; i += 256) {
            int r = i / HD, d = i % HD;
            size_t base = (size_t)(t * 64 + r) * QKV3 + head * HD + d;
            Ks[r * QP + d] = qkv[base + HID];
            Vs[r * QP + d] = qkv[base + 2 * HID];
        }
        __syncthreads();

        float dots[16];
#pragma unroll
        for (int j = 0; j < 16; j++) dots[j] = 0.f;
        for (int d = 0; d < HD; d++) {
            float qd = Qs[row * QP + d];
#pragma unroll
            for (int j = 0; j < 16; j++) dots[j] += qd * Ks[(l4 * 16 + j) * QP + d];
        }
        float tmax = -1e30f;
#pragma unroll
        for (int j = 0; j < 16; j++) {
            dots[j] *= 0.11180339887498949f;
            tmax = fmaxf(tmax, dots[j]);
        }
        tmax = fmaxf(tmax, __shfl_xor_sync(0xffffffffu, tmax, 1));
        tmax = fmaxf(tmax, __shfl_xor_sync(0xffffffffu, tmax, 2));
        float Mnew = fmaxf(M, tmax);
        float alpha = __expf(M - Mnew);
        float lsum = 0.f;
#pragma unroll
        for (int j = 0; j < 16; j++) {
            float p = __expf(dots[j] - Mnew);
            Ss[row * 65 + l4 * 16 + j] = p;
            lsum += p;
        }
        lsum += __shfl_xor_sync(0xffffffffu, lsum, 1);
        lsum += __shfl_xor_sync(0xffffffffu, lsum, 2);
        L = L * alpha + lsum;
        M = Mnew;
#pragma unroll
        for (int i = 0; i < 20; i++) O[i] *= alpha;
        __syncwarp();
        for (int key = 0; key < 64; key++) {
            float p = Ss[row * 65 + key];
#pragma unroll
            for (int i = 0; i < 20; i++) O[i] += p * Vs[key * QP + l4 * 20 + i];
        }
    }
    float inv = 1.f / L;
    int token = qt * 64 + row;
#pragma unroll
    for (int i = 0; i < 20; i++) {
        size_t off = (size_t)token * HID + head * HD + l4 * 20 + i;
        split1(O[i] * inv, ohi[off], olo[off]);
    }
}

// ---------------- Elementwise producers --------------------------------------
// silu(gate)*up, written hi/lo with row padding INTER -> INTER_P (pad zeros)
__global__ void silu_mul_kernel(const float* __restrict__ gate, const float* __restrict__ up,
                                __nv_bfloat16* __restrict__ hi, __nv_bfloat16* __restrict__ lo) {
    long total = (long)S_TOK * INTER_P;
    for (long i = blockIdx.x * (long)blockDim.x + threadIdx.x; i < total;
         i += (long)gridDim.x * blockDim.x) {
        long row = i / INTER_P;
        int col = (int)(i % INTER_P);
        float v = 0.f;
        if (col < INTER) {
            float g = gate[row * INTER + col];
            v = g / (1.f + __expf(-g)) * up[row * INTER + col];
        }
        split1(v, hi[i], lo[i]);
    }
}
__global__ void gelu_kernel(const float* __restrict__ x,
                            __nv_bfloat16* __restrict__ hi, __nv_bfloat16* __restrict__ lo,
                            long n) {
    for (long i = blockIdx.x * (long)blockDim.x + threadIdx.x; i < n;
         i += (long)gridDim.x * blockDim.x) {
        float v = x[i];
        split1(0.5f * v * (1.f + erff(v * 0.70710678118654752f)), hi[i], lo[i]);
    }
}
__global__ void scatter_out_kernel(const float* __restrict__ src, float* __restrict__ dst) {
    for (long i = blockIdx.x * (long)blockDim.x + threadIdx.x;
         i < (long)GROUPS * OUTDIM; i += (long)gridDim.x * blockDim.x) {
        int g = (int)(i / OUTDIM), n = (int)(i % OUTDIM);
        dst[(size_t)g_wingrp[g] * OUTDIM + n] = src[i];
    }
}

// ---------------- Host orchestration -----------------------------------------
#define GEMM_SMEM (2 * STG * (int)sizeof(__nv_bfloat16))

static void run_gemm(const __nv_bfloat16* Ahi, const __nv_bfloat16* Alo,
                     const __nv_bfloat16* Bhi, const __nv_bfloat16* Blo,
                     const float* bias, float* C, int M, int N, int K, int add) {
    dim3 grid((N + GBN - 1) / GBN, (M + GBM - 1) / GBM);
    gemm_tc_kernel<<<grid, 256, GEMM_SMEM>>>(Ahi, Alo, Bhi, Blo, bias, C, M, N, K, add);
}

extern "C" void kernel_launch(void* const* d_in, const int* in_sizes, int n_in,
                              void* d_out, int out_size) {
    const float* pixel_values = (const float*)d_in[0];
    const float* patch_w = (const float*)d_in[1];
    const float* qkv_w   = (const float*)d_in[2];
    const float* qkv_b   = (const float*)d_in[3];
    const float* proj_w  = (const float*)d_in[4];
    const float* proj_b  = (const float*)d_in[5];
    const float* norm1_w = (const float*)d_in[6];
    const float* norm2_w = (const float*)d_in[7];
    const float* gate_w  = (const float*)d_in[8];
    const float* gate_b  = (const float*)d_in[9];
    const float* up_w    = (const float*)d_in[10];
    const float* up_b    = (const float*)d_in[11];
    const float* down_w  = (const float*)d_in[12];
    const float* down_b  = (const float*)d_in[13];
    const float* ln_q_w  = (const float*)d_in[14];
    const float* m1_w    = (const float*)d_in[15];
    const float* m1_b    = (const float*)d_in[16];
    const float* m2_w    = (const float*)d_in[17];
    const float* m2_b    = (const float*)d_in[18];
    float* out = (float*)d_out;

    __nv_bfloat16 *whi, *wlo, *hhi, *hlo, *athi, *atlo, *achi, *aclo, *pxhi, *pxlo;
    float *x, *qkv, *gate, *up;
    cudaGetSymbolAddress((void**)&whi, g_whi);
    cudaGetSymbolAddress((void**)&wlo, g_wlo);
    cudaGetSymbolAddress((void**)&hhi, g_hhi);
    cudaGetSymbolAddress((void**)&hlo, g_hlo);
    cudaGetSymbolAddress((void**)&athi, g_athi);
    cudaGetSymbolAddress((void**)&atlo, g_atlo);
    cudaGetSymbolAddress((void**)&achi, g_achi);
    cudaGetSymbolAddress((void**)&aclo, g_aclo);
    cudaGetSymbolAddress((void**)&pxhi, g_pxhi);
    cudaGetSymbolAddress((void**)&pxlo, g_pxlo);
    cudaGetSymbolAddress((void**)&x,    g_x);
    cudaGetSymbolAddress((void**)&qkv,  g_qkv);
    cudaGetSymbolAddress((void**)&gate, g_gate);
    cudaGetSymbolAddress((void**)&up,   g_up);

    static int attr_set = 0;
    int attn_smem = (3 * 64 * QP + 64 * 65) * (int)sizeof(float);
    if (!attr_set) {
        cudaFuncSetAttribute(attn_kernel, cudaFuncAttributeMaxDynamicSharedMemorySize, attn_smem);
        cudaFuncSetAttribute(gemm_tc_kernel, cudaFuncAttributeMaxDynamicSharedMemorySize, GEMM_SMEM);
        attr_set = 1;
    }

    split_w_kernel<<<512, 256>>>(patch_w, whi + OFF_PATCH, wlo + OFF_PATCH, SZ_PATCH / 4);
    split_w_kernel<<<1024, 256>>>(qkv_w,  whi + OFF_QKV,   wlo + OFF_QKV,   SZ_QKV / 4);
    split_w_kernel<<<512, 256>>>(proj_w,  whi + OFF_PROJ,  wlo + OFF_PROJ,  SZ_PROJ / 4);
    split_w_kernel<<<1024, 256>>>(gate_w, whi + OFF_GATE,  wlo + OFF_GATE,  SZ_GATE / 4);
    split_w_kernel<<<1024, 256>>>(up_w,   whi + OFF_UP,    wlo + OFF_UP,    SZ_UP / 4);
    split_down_kernel<<<1024, 256>>>(down_w, whi + OFF_DOWN, wlo + OFF_DOWN);
    split_w_kernel<<<1024, 256>>>(m1_w,   whi + OFF_M1,    wlo + OFF_M1,    SZ_M1 / 4);
    split_w_kernel<<<1024, 256>>>(m2_w,   whi + OFF_M2,    wlo + OFF_M2,    SZ_M2 / 4);

    init_kernel<<<(S_TOK + 255) / 256, 256>>>();
    gather_pixels<<<512, 256>>>(pixel_values);

    run_gemm(pxhi, pxlo, whi + OFF_PATCH, wlo + OFF_PATCH, nullptr, x, S_TOK, HID, PIXF, 0);

    for (int i = 0; i < DEPTH; i++) {
        long oq = OFF_QKV + (long)i * QKV3 * HID;
        long op = OFF_PROJ + (long)i * HID * HID;
        long og = OFF_GATE + (long)i * INTER * HID;
        long ou = OFF_UP + (long)i * INTER * HID;
        long od = OFF_DOWN + (long)i * HID * INTER_P;
        const float* qb = qkv_b + (size_t)i * QKV3;
        const float* pb = proj_b + (size_t)i * HID;
        const float* n1 = norm1_w + (size_t)i * HID;
        const float* n2 = norm2_w + (size_t)i * HID;
        const float* gb = gate_b + (size_t)i * INTER;
        const float* ub = up_b + (size_t)i * INTER;
        const float* db = down_b + (size_t)i * HID;

        rmsnorm_kernel<<<S_TOK, 256>>>(x, n1, hhi, hlo);
        run_gemm(hhi, hlo, whi + oq, wlo + oq, qb, qkv, S_TOK, QKV3, HID, 0);
        rope_kernel<<<S_TOK, 256>>>();
        int windowed = (i == 3 || i == 7) ? 0 : 1;
        attn_kernel<<<dim3(NTILE64, HEADS), 256, attn_smem>>>(qkv, athi, atlo, windowed);
        run_gemm(athi, atlo, whi + op, wlo + op, pb, x, S_TOK, HID, HID, 1);

        rmsnorm_kernel<<<S_TOK, 256>>>(x, n2, hhi, hlo);
        run_gemm(hhi, hlo, whi + og, wlo + og, gb, gate, S_TOK, INTER, HID, 0);
        run_gemm(hhi, hlo, whi + ou, wlo + ou, ub, up, S_TOK, INTER, HID, 0);
        silu_mul_kernel<<<1024, 256>>>(gate, up, achi, aclo);
        run_gemm(achi, aclo, whi + od, wlo + od, db, x, S_TOK, HID, INTER_P, 1);
    }

    rmsnorm_kernel<<<S_TOK, 256>>>(x, ln_q_w, hhi, hlo);
    run_gemm(hhi, hlo, whi + OFF_M1, wlo + OFF_M1, m1_b, gate, GROUPS, MERGED, MERGED, 0);
    gelu_kernel<<<512, 256>>>(gate, achi, aclo, (long)GROUPS * MERGED);
    run_gemm(achi, aclo, whi + OFF_M2, wlo + OFF_M2, m2_b, qkv, GROUPS, OUTDIM, MERGED, 0);
    scatter_out_kernel<<<512, 256>>>(qkv, out);
}

// round 6
// speedup vs baseline: 2.2528x; 1.0800x over previous
#include <cuda_runtime.h>
#include <cuda_bf16.h>
#include <math.h>

// ---------------- Problem constants (fixed by setup_inputs) ----------------
#define S_TOK   2304
#define HID     1280
#define HEADS   16
#define HD      80
#define DEPTH   8
#define INTER   3420
#define INTER_P 3424     // padded to 16B-aligned rows (3424*2 = 6848 = 428*16)
#define OUTDIM  3584
#define QKV3    3840
#define GROUPS  576
#define PIXF    1176
#define MERGED  5120
#define NTILE64 36

// ---------------- Weight arena offsets (elements) ---------------------------
#define OFF_PATCH 0L
#define SZ_PATCH  (1280L*1176)
#define OFF_QKV   (OFF_PATCH + SZ_PATCH)
#define SZ_QKV    (8L*3840*1280)
#define OFF_PROJ  (OFF_QKV + SZ_QKV)
#define SZ_PROJ   (8L*1280*1280)
#define OFF_GATE  (OFF_PROJ + SZ_PROJ)
#define SZ_GATE   (8L*3420*1280)
#define OFF_UP    (OFF_GATE + SZ_GATE)
#define SZ_UP     (8L*3420*1280)
#define OFF_DOWN  (OFF_UP + SZ_UP)
#define SZ_DOWN   (8L*1280*INTER_P)     // padded K stride
#define OFF_M1    (OFF_DOWN + SZ_DOWN)
#define SZ_M1     (5120L*5120)
#define OFF_M2    (OFF_M1 + SZ_M1)
#define SZ_M2     (3584L*5120)
#define W_TOTAL   (OFF_M2 + SZ_M2)

// ---------------- Scratch (device globals) ----------------------------------
__device__ __nv_bfloat16 g_whi[W_TOTAL];
__device__ __nv_bfloat16 g_wlo[W_TOTAL];
__device__ float g_x[S_TOK * HID];
__device__ float g_qkv[S_TOK * QKV3];      // reused for m2 output
__device__ float g_gate[S_TOK * INTER];    // reused for m1 output
__device__ float g_up[S_TOK * INTER];
__device__ __nv_bfloat16 g_hhi[S_TOK * HID],  g_hlo[S_TOK * HID];
__device__ __nv_bfloat16 g_athi[S_TOK * HID], g_atlo[S_TOK * HID];
__device__ __nv_bfloat16 g_achi[S_TOK * INTER_P], g_aclo[S_TOK * INTER_P];
__device__ __nv_bfloat16 g_pxhi[S_TOK * PIXF], g_pxlo[S_TOK * PIXF];
__device__ float g_cos[S_TOK * HD];
__device__ float g_sin[S_TOK * HD];
__device__ int   g_orig[S_TOK];
__device__ int   g_wingrp[GROUPS];

// ---------------- helpers ----------------------------------------------------
__device__ __forceinline__ void split1(float v, __nv_bfloat16& h, __nv_bfloat16& l) {
    h = __float2bfloat16(v);
    l = __float2bfloat16(v - __bfloat162float(h));
}

// packed f32x2 helpers (sm_100+ base ISA)
__device__ __forceinline__ unsigned long long pk2(float a, float b) {
    unsigned long long r;
    asm("mov.b64 %0, {%1, %2};" : "=l"(r) : "f"(a), "f"(b));
    return r;
}
__device__ __forceinline__ void upk2(unsigned long long v, float& a, float& b) {
    asm("mov.b64 {%0, %1}, %2;" : "=f"(a), "=f"(b) : "l"(v));
}
__device__ __forceinline__ unsigned long long fma2(unsigned long long a,
                                                   unsigned long long b,
                                                   unsigned long long c) {
    unsigned long long d;
    asm("fma.rn.f32x2 %0, %1, %2, %3;" : "=l"(d) : "l"(a), "l"(b), "l"(c));
    return d;
}
__device__ __forceinline__ unsigned long long mul2(unsigned long long a,
                                                   unsigned long long b) {
    unsigned long long d;
    asm("mul.rn.f32x2 %0, %1, %2;" : "=l"(d) : "l"(a), "l"(b));
    return d;
}

// ---------------- Index + rotary precompute ---------------------------------
__global__ void init_kernel() {
    int s = blockIdx.x * blockDim.x + threadIdx.x;
    if (s >= S_TOK) return;
    int g = s >> 2, r = s & 3;
    int hb = g / 96, wb = (g / 16) % 6, hr = (g % 16) / 4, wr = g & 3;
    int og = (hb * 4 + hr) * 24 + (wb * 4 + wr);
    g_orig[s] = og * 4 + r;
    if (r == 0) g_wingrp[g] = og;
    int hg = og / 24, wg = og % 24;
    int hh = hg * 2 + (r >> 1), ww = wg * 2 + (r & 1);
    for (int j = 0; j < 40; j++) {
        float invf = powf(10000.f, -(float)(j % 20) / 20.f);
        float ang = (float)((j < 20) ? hh : ww) * invf;
        float c = cosf(ang), sn = sinf(ang);
        g_cos[s * HD + j] = c;  g_cos[s * HD + 40 + j] = c;
        g_sin[s * HD + j] = sn; g_sin[s * HD + 40 + j] = sn;
    }
}

__global__ void gather_pixels(const float* __restrict__ pix) {
    for (long i = blockIdx.x * (long)blockDim.x + threadIdx.x;
         i < (long)S_TOK * PIXF; i += (long)gridDim.x * blockDim.x) {
        int s = (int)(i / PIXF), c = (int)(i % PIXF);
        split1(pix[(long)g_orig[s] * PIXF + c], g_pxhi[i], g_pxlo[i]);
    }
}

// ---------------- Weight split (fp32 -> bf16 hi/lo) --------------------------
__global__ void split_w_kernel(const float* __restrict__ src,
                               __nv_bfloat16* __restrict__ hi,
                               __nv_bfloat16* __restrict__ lo, long n4) {
    for (long i = blockIdx.x * (long)blockDim.x + threadIdx.x; i < n4;
         i += (long)gridDim.x * blockDim.x) {
        float4 v = ((const float4*)src)[i];
        __nv_bfloat16 h0, h1, h2, h3, l0, l1, l2, l3;
        split1(v.x, h0, l0); split1(v.y, h1, l1);
        split1(v.z, h2, l2); split1(v.w, h3, l3);
        ((__nv_bfloat162*)hi)[2*i]   = __nv_bfloat162(h0, h1);
        ((__nv_bfloat162*)hi)[2*i+1] = __nv_bfloat162(h2, h3);
        ((__nv_bfloat162*)lo)[2*i]   = __nv_bfloat162(l0, l1);
        ((__nv_bfloat162*)lo)[2*i+1] = __nv_bfloat162(l2, l3);
    }
}

// down_w: split with row padding 3420 -> 3424 (pad = zeros)
__global__ void split_down_kernel(const float* __restrict__ src,
                                  __nv_bfloat16* __restrict__ hi,
                                  __nv_bfloat16* __restrict__ lo) {
    long total = 8L * 1280 * INTER_P;
    for (long i = blockIdx.x * (long)blockDim.x + threadIdx.x; i < total;
         i += (long)gridDim.x * blockDim.x) {
        long row = i / INTER_P;
        int col = (int)(i % INTER_P);
        float v = (col < INTER) ? src[row * INTER + col] : 0.f;
        split1(v, hi[i], lo[i]);
    }
}

// ============ Split-bf16 tensor-core GEMM ====================================
// C[M,N] (+)= A[M,K] @ B[N,K]^T + bias, A/B pre-split bf16 hi/lo.
#define GBM 128
#define GBN 128
#define GBK 32
#define SKA 40
#define STG (4 * 128 * SKA)

__device__ __forceinline__ void mma16816(float* c, const unsigned* a, const unsigned* b) {
    asm volatile(
        "mma.sync.aligned.m16n8k16.row.col.f32.bf16.bf16.f32 "
        "{%0,%1,%2,%3}, {%4,%5,%6,%7}, {%8,%9}, {%0,%1,%2,%3};\n"
        : "+f"(c[0]), "+f"(c[1]), "+f"(c[2]), "+f"(c[3])
        : "r"(a[0]), "r"(a[1]), "r"(a[2]), "r"(a[3]), "r"(b[0]), "r"(b[1]));
}

__device__ __forceinline__ void cpa16(__nv_bfloat16* dst, const __nv_bfloat16* src, int sz) {
    unsigned d = (unsigned)__cvta_generic_to_shared(dst);
    asm volatile("cp.async.cg.shared.global [%0], [%1], 16, %2;\n"
                 :: "r"(d), "l"(src), "r"(sz));
}

__global__ __launch_bounds__(256, 2)
void gemm_tc_kernel(const __nv_bfloat16* __restrict__ Ahi, const __nv_bfloat16* __restrict__ Alo,
                    const __nv_bfloat16* __restrict__ Bhi, const __nv_bfloat16* __restrict__ Blo,
                    const float* __restrict__ bias, float* __restrict__ C,
                    int M, int N, int K, int addFlag) {
    extern __shared__ __nv_bfloat16 smem[];
    int bm = blockIdx.y * GBM, bn = blockIdx.x * GBN;
    int tid = threadIdx.x;
    int wid = tid >> 5, lane = tid & 31;
    int wm = (wid & 1) * 64;
    int wn = (wid >> 1) * 32;
    int gid = lane >> 2, qid = lane & 3;

    float acc[4][4][4];
#pragma unroll
    for (int mi = 0; mi < 4; mi++)
#pragma unroll
        for (int ni = 0; ni < 4; ni++)
#pragma unroll
            for (int r = 0; r < 4; r++) acc[mi][ni][r] = 0.f;

    int nT = (K + GBK - 1) / GBK;

    auto load_tile = [&](int k0, int st) {
        __nv_bfloat16* base = smem + st * STG;
#pragma unroll
        for (int it = 0; it < 2; it++) {
            int c = tid + it * 256;
            int row = c >> 2, seg = c & 3;
            int kk = k0 + seg * 8;
            int rem = K - kk;
            int ksz = rem >= 8 ? 16 : (rem >= 4 ? 8 : 0);
            int gm = bm + row;
            int szA = (gm < M) ? ksz : 0;
            size_t offA = szA ? ((size_t)gm * K + kk) : 0;
            int gn = bn + row;
            int szB = (gn < N) ? ksz : 0;
            size_t offB = szB ? ((size_t)gn * K + kk) : 0;
            int so = row * SKA + seg * 8;
            cpa16(base + so,                 Ahi + offA, szA);
            cpa16(base + 128 * SKA + so,     Alo + offA, szA);
            cpa16(base + 2 * 128 * SKA + so, Bhi + offB, szB);
            cpa16(base + 3 * 128 * SKA + so, Blo + offB, szB);
        }
        asm volatile("cp.async.commit_group;\n" ::);
    };

    load_tile(0, 0);

    for (int t = 0; t < nT; t++) {
        asm volatile("cp.async.wait_group 0;\n" ::);
        __syncthreads();
        if (t + 1 < nT) load_tile((t + 1) * GBK, (t + 1) & 1);

        const __nv_bfloat16* sAh = smem + (t & 1) * STG;
        const __nv_bfloat16* sAl = sAh + 128 * SKA;
        const __nv_bfloat16* sBh = sAh + 2 * 128 * SKA;
        const __nv_bfloat16* sBl = sAh + 3 * 128 * SKA;

#pragma unroll
        for (int ks = 0; ks < GBK; ks += 16) {
            unsigned ah[4][4], al[4][4], bh[4][2], bl[4][2];
            int c0 = ks + qid * 2;
#pragma unroll
            for (int mi = 0; mi < 4; mi++) {
                int r0 = wm + mi * 16 + gid;
                ah[mi][0] = *(const unsigned*)(sAh + r0 * SKA + c0);
                ah[mi][1] = *(const unsigned*)(sAh + (r0 + 8) * SKA + c0);
                ah[mi][2] = *(const unsigned*)(sAh + r0 * SKA + c0 + 8);
                ah[mi][3] = *(const unsigned*)(sAh + (r0 + 8) * SKA + c0 + 8);
                al[mi][0] = *(const unsigned*)(sAl + r0 * SKA + c0);
                al[mi][1] = *(const unsigned*)(sAl + (r0 + 8) * SKA + c0);
                al[mi][2] = *(const unsigned*)(sAl + r0 * SKA + c0 + 8);
                al[mi][3] = *(const unsigned*)(sAl + (r0 + 8) * SKA + c0 + 8);
            }
#pragma unroll
            for (int ni = 0; ni < 4; ni++) {
                int n0 = wn + ni * 8 + gid;
                bh[ni][0] = *(const unsigned*)(sBh + n0 * SKA + c0);
                bh[ni][1] = *(const unsigned*)(sBh + n0 * SKA + c0 + 8);
                bl[ni][0] = *(const unsigned*)(sBl + n0 * SKA + c0);
                bl[ni][1] = *(const unsigned*)(sBl + n0 * SKA + c0 + 8);
            }
#pragma unroll
            for (int mi = 0; mi < 4; mi++)
#pragma unroll
                for (int ni = 0; ni < 4; ni++) {
                    mma16816(acc[mi][ni], ah[mi], bh[ni]);
                    mma16816(acc[mi][ni], al[mi], bh[ni]);
                    mma16816(acc[mi][ni], ah[mi], bl[ni]);
                }
        }
        __syncthreads();
    }

#pragma unroll
    for (int mi = 0; mi < 4; mi++) {
#pragma unroll
        for (int rr = 0; rr < 2; rr++) {
            int m = bm + wm + mi * 16 + gid + rr * 8;
            if (m >= M) continue;
#pragma unroll
            for (int ni = 0; ni < 4; ni++) {
                int n = bn + wn + ni * 8 + qid * 2;
                if (n >= N) continue;
                float v0 = acc[mi][ni][rr * 2]     + (bias ? bias[n] : 0.f);
                float v1 = acc[mi][ni][rr * 2 + 1] + (bias ? bias[n + 1] : 0.f);
                float* p = C + (size_t)m * N + n;
                if (addFlag) { p[0] += v0; p[1] += v1; }
                else { *(float2*)p = make_float2(v0, v1); }
            }
        }
    }
}

// ---------------- RMSNorm -> bf16 hi/lo --------------------------------------
__global__ void rmsnorm_kernel(const float* __restrict__ x, const float* __restrict__ w,
                               __nv_bfloat16* __restrict__ hi, __nv_bfloat16* __restrict__ lo) {
    int s = blockIdx.x;
    const float* xr = x + (size_t)s * HID;
    float ss = 0.f;
    for (int i = threadIdx.x; i < HID; i += 256) { float v = xr[i]; ss += v * v; }
#pragma unroll
    for (int o = 16; o; o >>= 1) ss += __shfl_xor_sync(0xffffffffu, ss, o);
    __shared__ float red[8];
    if ((threadIdx.x & 31) == 0) red[threadIdx.x >> 5] = ss;
    __syncthreads();
    if (threadIdx.x < 8) {
        float v = red[threadIdx.x];
#pragma unroll
        for (int o = 4; o; o >>= 1) v += __shfl_xor_sync(0xffu, v, o);
        if (threadIdx.x == 0) red[0] = v;
    }
    __syncthreads();
    float scale = rsqrtf(red[0] * (1.f / HID) + 1e-6f);
    for (int i = threadIdx.x; i < HID; i += 256)
        split1(xr[i] * scale * w[i], hi[(size_t)s * HID + i], lo[(size_t)s * HID + i]);
}

// ---------------- RoPE on q,k inside g_qkv ----------------------------------
__global__ void rope_kernel() {
    int s = blockIdx.x;
    size_t base = (size_t)s * QKV3;
    for (int p = threadIdx.x; p < 2 * HEADS * 40; p += 256) {
        int part = p / (HEADS * 40);
        int rem = p % (HEADS * 40);
        int head = rem / 40, d = rem % 40;
        size_t off = base + part * HID + head * HD + d;
        float c = g_cos[s * HD + d], sn = g_sin[s * HD + d];
        float v0 = g_qkv[off], v1 = g_qkv[off + 40];
        g_qkv[off]      = v0 * c - v1 * sn;
        g_qkv[off + 40] = v1 * c + v0 * sn;
    }
}

// ---------------- Attention (flash-style; windowed or full; f32x2 math) -----
#define QP 84
__global__ void attn_kernel(const float* __restrict__ qkv,
                            __nv_bfloat16* __restrict__ ohi, __nv_bfloat16* __restrict__ olo,
                            int windowed) {
    extern __shared__ float sm[];
    float* Qs = sm;
    float* Ks = Qs + 64 * QP;
    float* Vs = Ks + 64 * QP;
    float* Ss = Vs + 64 * QP;
    int qt = blockIdx.x, head = blockIdx.y;
    int tid = threadIdx.x;
    int row = tid >> 2, l4 = tid & 3;

    for (int i = tid; i < 64 * HD; i += 256) {
        int r = i / HD, d = i % HD;
        Qs[r * QP + d] = qkv[(size_t)(qt * 64 + r) * QKV3 + head * HD + d];
    }
    float M = -1e30f, L = 0.f;
    unsigned long long O2[10];
#pragma unroll
    for (int i = 0; i < 10; i++) O2[i] = 0ull;

    int t0 = windowed ? qt : 0;
    int t1 = windowed ? qt + 1 : NTILE64;
    for (int t = t0; t < t1; t++) {
        __syncthreads();
        for (int i = tid; i < 64 * HD; i += 256) {
            int r = i / HD, d = i % HD;
            size_t base = (size_t)(t * 64 + r) * QKV3 + head * HD + d;
            Ks[r * QP + d] = qkv[base + HID];
            Vs[r * QP + d] = qkv[base + 2 * HID];
        }
        __syncthreads();

        // ---- QK^T via packed f32x2 (d-pairs) ----
        unsigned long long acc2[16];
#pragma unroll
        for (int j = 0; j < 16; j++) acc2[j] = 0ull;
        const unsigned long long* qrow = (const unsigned long long*)(Qs + row * QP);
        for (int d2 = 0; d2 < HD / 2; d2++) {
            unsigned long long q2 = qrow[d2];
#pragma unroll
            for (int j = 0; j < 16; j++) {
                unsigned long long k2 =
                    *(const unsigned long long*)(Ks + (l4 * 16 + j) * QP + d2 * 2);
                acc2[j] = fma2(q2, k2, acc2[j]);
            }
        }
        float dots[16];
        float tmax = -1e30f;
#pragma unroll
        for (int j = 0; j < 16; j++) {
            float a, b; upk2(acc2[j], a, b);
            dots[j] = (a + b) * 0.11180339887498949f;   // 80^-0.5
            tmax = fmaxf(tmax, dots[j]);
        }
        tmax = fmaxf(tmax, __shfl_xor_sync(0xffffffffu, tmax, 1));
        tmax = fmaxf(tmax, __shfl_xor_sync(0xffffffffu, tmax, 2));
        float Mnew = fmaxf(M, tmax);
        float alpha = __expf(M - Mnew);
        float lsum = 0.f;
#pragma unroll
        for (int j = 0; j < 16; j++) {
            float p = __expf(dots[j] - Mnew);
            Ss[row * 65 + l4 * 16 + j] = p;
            lsum += p;
        }
        lsum += __shfl_xor_sync(0xffffffffu, lsum, 1);
        lsum += __shfl_xor_sync(0xffffffffu, lsum, 2);
        L = L * alpha + lsum;
        M = Mnew;
        unsigned long long al2 = pk2(alpha, alpha);
#pragma unroll
        for (int i = 0; i < 10; i++) O2[i] = mul2(O2[i], al2);
        __syncwarp();
        // ---- P @ V via packed f32x2 (i-pairs) ----
        for (int key = 0; key < 64; key++) {
            float p = Ss[row * 65 + key];
            unsigned long long pp = pk2(p, p);
            const unsigned long long* vrow =
                (const unsigned long long*)(Vs + key * QP + l4 * 20);
#pragma unroll
            for (int i = 0; i < 10; i++) O2[i] = fma2(pp, vrow[i], O2[i]);
        }
    }
    float inv = 1.f / L;
    int token = qt * 64 + row;
#pragma unroll
    for (int i = 0; i < 10; i++) {
        float a, b; upk2(O2[i], a, b);
        size_t off = (size_t)token * HID + head * HD + l4 * 20 + 2 * i;
        split1(a * inv, ohi[off], olo[off]);
        split1(b * inv, ohi[off + 1], olo[off + 1]);
    }
}

// ---------------- Elementwise producers --------------------------------------
__global__ void silu_mul_kernel(const float* __restrict__ gate, const float* __restrict__ up,
                                __nv_bfloat16* __restrict__ hi, __nv_bfloat16* __restrict__ lo) {
    long total = (long)S_TOK * INTER_P;
    for (long i = blockIdx.x * (long)blockDim.x + threadIdx.x; i < total;
         i += (long)gridDim.x * blockDim.x) {
        long row = i / INTER_P;
        int col = (int)(i % INTER_P);
        float v = 0.f;
        if (col < INTER) {
            float g = gate[row * INTER + col];
            v = g / (1.f + __expf(-g)) * up[row * INTER + col];
        }
        split1(v, hi[i], lo[i]);
    }
}
__global__ void gelu_kernel(const float* __restrict__ x,
                            __nv_bfloat16* __restrict__ hi, __nv_bfloat16* __restrict__ lo,
                            long n) {
    for (long i = blockIdx.x * (long)blockDim.x + threadIdx.x; i < n;
         i += (long)gridDim.x * blockDim.x) {
        float v = x[i];
        split1(0.5f * v * (1.f + erff(v * 0.70710678118654752f)), hi[i], lo[i]);
    }
}
__global__ void scatter_out_kernel(const float* __restrict__ src, float* __restrict__ dst) {
    for (long i = blockIdx.x * (long)blockDim.x + threadIdx.x;
         i < (long)GROUPS * OUTDIM; i += (long)gridDim.x * blockDim.x) {
        int g = (int)(i / OUTDIM), n = (int)(i % OUTDIM);
        dst[(size_t)g_wingrp[g] * OUTDIM + n] = src[i];
    }
}

// ---------------- Host orchestration -----------------------------------------
#define GEMM_SMEM (2 * STG * (int)sizeof(__nv_bfloat16))

static void run_gemm(const __nv_bfloat16* Ahi, const __nv_bfloat16* Alo,
                     const __nv_bfloat16* Bhi, const __nv_bfloat16* Blo,
                     const float* bias, float* C, int M, int N, int K, int add) {
    dim3 grid((N + GBN - 1) / GBN, (M + GBM - 1) / GBM);
    gemm_tc_kernel<<<grid, 256, GEMM_SMEM>>>(Ahi, Alo, Bhi, Blo, bias, C, M, N, K, add);
}

extern "C" void kernel_launch(void* const* d_in, const int* in_sizes, int n_in,
                              void* d_out, int out_size) {
    const float* pixel_values = (const float*)d_in[0];
    const float* patch_w = (const float*)d_in[1];
    const float* qkv_w   = (const float*)d_in[2];
    const float* qkv_b   = (const float*)d_in[3];
    const float* proj_w  = (const float*)d_in[4];
    const float* proj_b  = (const float*)d_in[5];
    const float* norm1_w = (const float*)d_in[6];
    const float* norm2_w = (const float*)d_in[7];
    const float* gate_w  = (const float*)d_in[8];
    const float* gate_b  = (const float*)d_in[9];
    const float* up_w    = (const float*)d_in[10];
    const float* up_b    = (const float*)d_in[11];
    const float* down_w  = (const float*)d_in[12];
    const float* down_b  = (const float*)d_in[13];
    const float* ln_q_w  = (const float*)d_in[14];
    const float* m1_w    = (const float*)d_in[15];
    const float* m1_b    = (const float*)d_in[16];
    const float* m2_w    = (const float*)d_in[17];
    const float* m2_b    = (const float*)d_in[18];
    float* out = (float*)d_out;

    __nv_bfloat16 *whi, *wlo, *hhi, *hlo, *athi, *atlo, *achi, *aclo, *pxhi, *pxlo;
    float *x, *qkv, *gate, *up;
    cudaGetSymbolAddress((void**)&whi, g_whi);
    cudaGetSymbolAddress((void**)&wlo, g_wlo);
    cudaGetSymbolAddress((void**)&hhi, g_hhi);
    cudaGetSymbolAddress((void**)&hlo, g_hlo);
    cudaGetSymbolAddress((void**)&athi, g_athi);
    cudaGetSymbolAddress((void**)&atlo, g_atlo);
    cudaGetSymbolAddress((void**)&achi, g_achi);
    cudaGetSymbolAddress((void**)&aclo, g_aclo);
    cudaGetSymbolAddress((void**)&pxhi, g_pxhi);
    cudaGetSymbolAddress((void**)&pxlo, g_pxlo);
    cudaGetSymbolAddress((void**)&x,    g_x);
    cudaGetSymbolAddress((void**)&qkv,  g_qkv);
    cudaGetSymbolAddress((void**)&gate, g_gate);
    cudaGetSymbolAddress((void**)&up,   g_up);

    static int attr_set = 0;
    int attn_smem = (3 * 64 * QP + 64 * 65) * (int)sizeof(float);
    if (!attr_set) {
        cudaFuncSetAttribute(attn_kernel, cudaFuncAttributeMaxDynamicSharedMemorySize, attn_smem);
        cudaFuncSetAttribute(gemm_tc_kernel, cudaFuncAttributeMaxDynamicSharedMemorySize, GEMM_SMEM);
        attr_set = 1;
    }

    split_w_kernel<<<512, 256>>>(patch_w, whi + OFF_PATCH, wlo + OFF_PATCH, SZ_PATCH / 4);
    split_w_kernel<<<1024, 256>>>(qkv_w,  whi + OFF_QKV,   wlo + OFF_QKV,   SZ_QKV / 4);
    split_w_kernel<<<512, 256>>>(proj_w,  whi + OFF_PROJ,  wlo + OFF_PROJ,  SZ_PROJ / 4);
    split_w_kernel<<<1024, 256>>>(gate_w, whi + OFF_GATE,  wlo + OFF_GATE,  SZ_GATE / 4);
    split_w_kernel<<<1024, 256>>>(up_w,   whi + OFF_UP,    wlo + OFF_UP,    SZ_UP / 4);
    split_down_kernel<<<1024, 256>>>(down_w, whi + OFF_DOWN, wlo + OFF_DOWN);
    split_w_kernel<<<1024, 256>>>(m1_w,   whi + OFF_M1,    wlo + OFF_M1,    SZ_M1 / 4);
    split_w_kernel<<<1024, 256>>>(m2_w,   whi + OFF_M2,    wlo + OFF_M2,    SZ_M2 / 4);

    init_kernel<<<(S_TOK + 255) / 256, 256>>>();
    gather_pixels<<<512, 256>>>(pixel_values);

    run_gemm(pxhi, pxlo, whi + OFF_PATCH, wlo + OFF_PATCH, nullptr, x, S_TOK, HID, PIXF, 0);

    for (int i = 0; i < DEPTH; i++) {
        long oq = OFF_QKV + (long)i * QKV3 * HID;
        long op = OFF_PROJ + (long)i * HID * HID;
        long og = OFF_GATE + (long)i * INTER * HID;
        long ou = OFF_UP + (long)i * INTER * HID;
        long od = OFF_DOWN + (long)i * HID * INTER_P;
        const float* qb = qkv_b + (size_t)i * QKV3;
        const float* pb = proj_b + (size_t)i * HID;
        const float* n1 = norm1_w + (size_t)i * HID;
        const float* n2 = norm2_w + (size_t)i * HID;
        const float* gb = gate_b + (size_t)i * INTER;
        const float* ub = up_b + (size_t)i * INTER;
        const float* db = down_b + (size_t)i * HID;

        rmsnorm_kernel<<<S_TOK, 256>>>(x, n1, hhi, hlo);
        run_gemm(hhi, hlo, whi + oq, wlo + oq, qb, qkv, S_TOK, QKV3, HID, 0);
        rope_kernel<<<S_TOK, 256>>>();
        int windowed = (i == 3 || i == 7) ? 0 : 1;
        attn_kernel<<<dim3(NTILE64, HEADS), 256, attn_smem>>>(qkv, athi, atlo, windowed);
        run_gemm(athi, atlo, whi + op, wlo + op, pb, x, S_TOK, HID, HID, 1);

        rmsnorm_kernel<<<S_TOK, 256>>>(x, n2, hhi, hlo);
        run_gemm(hhi, hlo, whi + og, wlo + og, gb, gate, S_TOK, INTER, HID, 0);
        run_gemm(hhi, hlo, whi + ou, wlo + ou, ub, up, S_TOK, INTER, HID, 0);
        silu_mul_kernel<<<1024, 256>>>(gate, up, achi, aclo);
        run_gemm(achi, aclo, whi + od, wlo + od, db, x, S_TOK, HID, INTER_P, 1);
    }

    rmsnorm_kernel<<<S_TOK, 256>>>(x, ln_q_w, hhi, hlo);
    run_gemm(hhi, hlo, whi + OFF_M1, wlo + OFF_M1, m1_b, gate, GROUPS, MERGED, MERGED, 0);
    gelu_kernel<<<512, 256>>>(gate, achi, aclo, (long)GROUPS * MERGED);
    run_gemm(achi, aclo, whi + OFF_M2, wlo + OFF_M2, m2_b, qkv, GROUPS, OUTDIM, MERGED, 0);
    scatter_out_kernel<<<512, 256>>>(qkv, out);
}

// round 8
// speedup vs baseline: 2.3008x; 1.0213x over previous
#include <cuda_runtime.h>
#include <cuda_bf16.h>
#include <math.h>

// ---------------- Problem constants (fixed by setup_inputs) ----------------
#define S_TOK   2304
#define HID     1280
#define HEADS   16
#define HD      80
#define DEPTH   8
#define INTER   3420
#define INTER_P 3424     // padded to 16B-aligned rows (3424*2 = 6848 = 428*16)
#define OUTDIM  3584
#define QKV3    3840
#define GROUPS  576
#define PIXF    1176
#define MERGED  5120
#define NTILE64 36

// ---------------- Weight arena offsets (elements) ---------------------------
#define OFF_PATCH 0L
#define SZ_PATCH  (1280L*1176)
#define OFF_QKV   (OFF_PATCH + SZ_PATCH)
#define SZ_QKV    (8L*3840*1280)
#define OFF_PROJ  (OFF_QKV + SZ_QKV)
#define SZ_PROJ   (8L*1280*1280)
#define OFF_GATE  (OFF_PROJ + SZ_PROJ)
#define SZ_GATE   (8L*3420*1280)
#define OFF_UP    (OFF_GATE + SZ_GATE)
#define SZ_UP     (8L*3420*1280)
#define OFF_DOWN  (OFF_UP + SZ_UP)
#define SZ_DOWN   (8L*1280*INTER_P)     // padded K stride
#define OFF_M1    (OFF_DOWN + SZ_DOWN)
#define SZ_M1     (5120L*5120)
#define OFF_M2    (OFF_M1 + SZ_M1)
#define SZ_M2     (3584L*5120)
#define W_TOTAL   (OFF_M2 + SZ_M2)

// ---------------- Scratch (device globals) ----------------------------------
__device__ __nv_bfloat16 g_whi[W_TOTAL];
__device__ __nv_bfloat16 g_wlo[W_TOTAL];
__device__ float g_x[S_TOK * HID];
__device__ float g_qkv[S_TOK * QKV3];      // reused for m2 output
__device__ float g_gate[S_TOK * INTER];    // reused for m1 output
__device__ float g_up[S_TOK * INTER];
__device__ __nv_bfloat16 g_hhi[S_TOK * HID],  g_hlo[S_TOK * HID];
__device__ __nv_bfloat16 g_athi[S_TOK * HID], g_atlo[S_TOK * HID];
__device__ __nv_bfloat16 g_achi[S_TOK * INTER_P], g_aclo[S_TOK * INTER_P];
__device__ __nv_bfloat16 g_pxhi[S_TOK * PIXF], g_pxlo[S_TOK * PIXF];
__device__ float g_cos[S_TOK * HD];
__device__ float g_sin[S_TOK * HD];
__device__ int   g_orig[S_TOK];
__device__ int   g_wingrp[GROUPS];

// ---------------- helpers ----------------------------------------------------
__device__ __forceinline__ void split1(float v, __nv_bfloat16& h, __nv_bfloat16& l) {
    h = __float2bfloat16(v);
    l = __float2bfloat16(v - __bfloat162float(h));
}

// packed f32x2 helpers (sm_100+ base ISA)
__device__ __forceinline__ unsigned long long pk2(float a, float b) {
    unsigned long long r;
    asm("mov.b64 %0, {%1, %2};" : "=l"(r) : "f"(a), "f"(b));
    return r;
}
__device__ __forceinline__ void upk2(unsigned long long v, float& a, float& b) {
    asm("mov.b64 {%0, %1}, %2;" : "=f"(a), "=f"(b) : "l"(v));
}
__device__ __forceinline__ unsigned long long fma2(unsigned long long a,
                                                   unsigned long long b,
                                                   unsigned long long c) {
    unsigned long long d;
    asm("fma.rn.f32x2 %0, %1, %2, %3;" : "=l"(d) : "l"(a), "l"(b), "l"(c));
    return d;
}
__device__ __forceinline__ unsigned long long mul2(unsigned long long a,
                                                   unsigned long long b) {
    unsigned long long d;
    asm("mul.rn.f32x2 %0, %1, %2;" : "=l"(d) : "l"(a), "l"(b));
    return d;
}

// ---------------- Index + rotary precompute ---------------------------------
__global__ void init_kernel() {
    int s = blockIdx.x * blockDim.x + threadIdx.x;
    if (s >= S_TOK) return;
    int g = s >> 2, r = s & 3;
    int hb = g / 96, wb = (g / 16) % 6, hr = (g % 16) / 4, wr = g & 3;
    int og = (hb * 4 + hr) * 24 + (wb * 4 + wr);
    g_orig[s] = og * 4 + r;
    if (r == 0) g_wingrp[g] = og;
    int hg = og / 24, wg = og % 24;
    int hh = hg * 2 + (r >> 1), ww = wg * 2 + (r & 1);
    for (int j = 0; j < 40; j++) {
        float invf = powf(10000.f, -(float)(j % 20) / 20.f);
        float ang = (float)((j < 20) ? hh : ww) * invf;
        float c = cosf(ang), sn = sinf(ang);
        g_cos[s * HD + j] = c;  g_cos[s * HD + 40 + j] = c;
        g_sin[s * HD + j] = sn; g_sin[s * HD + 40 + j] = sn;
    }
}

__global__ void gather_pixels(const float* __restrict__ pix) {
    for (long i = blockIdx.x * (long)blockDim.x + threadIdx.x;
         i < (long)S_TOK * PIXF; i += (long)gridDim.x * blockDim.x) {
        int s = (int)(i / PIXF), c = (int)(i % PIXF);
        split1(pix[(long)g_orig[s] * PIXF + c], g_pxhi[i], g_pxlo[i]);
    }
}

// ---------------- Weight split (fp32 -> bf16 hi/lo) --------------------------
__global__ void split_w_kernel(const float* __restrict__ src,
                               __nv_bfloat16* __restrict__ hi,
                               __nv_bfloat16* __restrict__ lo, long n4) {
    for (long i = blockIdx.x * (long)blockDim.x + threadIdx.x; i < n4;
         i += (long)gridDim.x * blockDim.x) {
        float4 v = ((const float4*)src)[i];
        __nv_bfloat16 h0, h1, h2, h3, l0, l1, l2, l3;
        split1(v.x, h0, l0); split1(v.y, h1, l1);
        split1(v.z, h2, l2); split1(v.w, h3, l3);
        ((__nv_bfloat162*)hi)[2*i]   = __nv_bfloat162(h0, h1);
        ((__nv_bfloat162*)hi)[2*i+1] = __nv_bfloat162(h2, h3);
        ((__nv_bfloat162*)lo)[2*i]   = __nv_bfloat162(l0, l1);
        ((__nv_bfloat162*)lo)[2*i+1] = __nv_bfloat162(l2, l3);
    }
}

// down_w: split with row padding 3420 -> 3424 (pad = zeros)
__global__ void split_down_kernel(const float* __restrict__ src,
                                  __nv_bfloat16* __restrict__ hi,
                                  __nv_bfloat16* __restrict__ lo) {
    long total = 8L * 1280 * INTER_P;
    for (long i = blockIdx.x * (long)blockDim.x + threadIdx.x; i < total;
         i += (long)gridDim.x * blockDim.x) {
        long row = i / INTER_P;
        int col = (int)(i % INTER_P);
        float v = (col < INTER) ? src[row * INTER + col] : 0.f;
        split1(v, hi[i], lo[i]);
    }
}

// ============ Split-bf16 tensor-core GEMM (ldmatrix operand loads) ===========
// C[M,N] (+)= A[M,K] @ B[N,K]^T + bias, A/B pre-split bf16 hi/lo.
#define GBM 128
#define GBN 128
#define GBK 32
#define SKA 40
#define STG (4 * 128 * SKA)

__device__ __forceinline__ void mma16816(float* c, const unsigned* a, const unsigned* b) {
    asm volatile(
        "mma.sync.aligned.m16n8k16.row.col.f32.bf16.bf16.f32 "
        "{%0,%1,%2,%3}, {%4,%5,%6,%7}, {%8,%9}, {%0,%1,%2,%3};\n"
        : "+f"(c[0]), "+f"(c[1]), "+f"(c[2]), "+f"(c[3])
        : "r"(a[0]), "r"(a[1]), "r"(a[2]), "r"(a[3]), "r"(b[0]), "r"(b[1]));
}

__device__ __forceinline__ void ldsm4(unsigned* r, unsigned saddr) {
    asm volatile("ldmatrix.sync.aligned.m8n8.x4.shared.b16 {%0,%1,%2,%3}, [%4];"
                 : "=r"(r[0]), "=r"(r[1]), "=r"(r[2]), "=r"(r[3]) : "r"(saddr));
}

__device__ __forceinline__ void cpa16(__nv_bfloat16* dst, const __nv_bfloat16* src, int sz) {
    unsigned d = (unsigned)__cvta_generic_to_shared(dst);
    asm volatile("cp.async.cg.shared.global [%0], [%1], 16, %2;\n"
                 :: "r"(d), "l"(src), "r"(sz));
}

__global__ __launch_bounds__(256, 2)
void gemm_tc_kernel(const __nv_bfloat16* __restrict__ Ahi, const __nv_bfloat16* __restrict__ Alo,
                    const __nv_bfloat16* __restrict__ Bhi, const __nv_bfloat16* __restrict__ Blo,
                    const float* __restrict__ bias, float* __restrict__ C,
                    int M, int N, int K, int addFlag) {
    extern __shared__ __nv_bfloat16 smem[];
    int bm = blockIdx.y * GBM, bn = blockIdx.x * GBN;
    int tid = threadIdx.x;
    int wid = tid >> 5, lane = tid & 31;
    int wm = (wid & 1) * 64;
    int wn = (wid >> 1) * 32;
    int gid = lane >> 2, qid = lane & 3;

    // ldmatrix lane->row/col offsets (element units)
    int a_row = lane & 15;               // row within 16-row frag
    int a_coff = (lane >> 4) << 3;       // 0 or 8 (k offset)
    int b_row = ((lane >> 4) << 3) + (lane & 7);   // row within 16-n pair
    int b_coff = ((lane >> 3) & 1) << 3; // 0 or 8 (k offset)

    unsigned smem_base = (unsigned)__cvta_generic_to_shared(smem);

    float acc[4][4][4];
#pragma unroll
    for (int mi = 0; mi < 4; mi++)
#pragma unroll
        for (int ni = 0; ni < 4; ni++)
#pragma unroll
            for (int r = 0; r < 4; r++) acc[mi][ni][r] = 0.f;

    int nT = (K + GBK - 1) / GBK;

    auto load_tile = [&](int k0, int st) {
        __nv_bfloat16* base = smem + st * STG;
#pragma unroll
        for (int it = 0; it < 2; it++) {
            int c = tid + it * 256;
            int row = c >> 2, seg = c & 3;
            int kk = k0 + seg * 8;
            int rem = K - kk;
            int ksz = rem >= 8 ? 16 : (rem >= 4 ? 8 : 0);
            int gm = bm + row;
            int szA = (gm < M) ? ksz : 0;
            size_t offA = szA ? ((size_t)gm * K + kk) : 0;
            int gn = bn + row;
            int szB = (gn < N) ? ksz : 0;
            size_t offB = szB ? ((size_t)gn * K + kk) : 0;
            int so = row * SKA + seg * 8;
            cpa16(base + so,                 Ahi + offA, szA);
            cpa16(base + 128 * SKA + so,     Alo + offA, szA);
            cpa16(base + 2 * 128 * SKA + so, Bhi + offB, szB);
            cpa16(base + 3 * 128 * SKA + so, Blo + offB, szB);
        }
        asm volatile("cp.async.commit_group;\n" ::);
    };

    load_tile(0, 0);

    for (int t = 0; t < nT; t++) {
        asm volatile("cp.async.wait_group 0;\n" ::);
        __syncthreads();
        if (t + 1 < nT) load_tile((t + 1) * GBK, (t + 1) & 1);

        unsigned stg = smem_base + (t & 1) * STG * 2;   // byte offset
        unsigned sAh = stg;
        unsigned sAl = stg + 128 * SKA * 2;
        unsigned sBh = stg + 2 * 128 * SKA * 2;
        unsigned sBl = stg + 3 * 128 * SKA * 2;

#pragma unroll
        for (int ks = 0; ks < GBK; ks += 16) {
            unsigned ah[4][4], al[4][4], bh[4][2], bl[4][2];
            // A fragments: one ldmatrix.x4 per mi per (hi|lo)
#pragma unroll
            for (int mi = 0; mi < 4; mi++) {
                unsigned off = (unsigned)(((wm + mi * 16 + a_row) * SKA
                                          + ks + a_coff) * 2);
                ldsm4(ah[mi], sAh + off);
                ldsm4(al[mi], sAl + off);
            }
            // B fragments: one ldmatrix.x4 per ni-PAIR per (hi|lo)
#pragma unroll
            for (int np = 0; np < 2; np++) {
                unsigned off = (unsigned)(((wn + np * 16 + b_row) * SKA
                                          + ks + b_coff) * 2);
                unsigned rh[4], rl[4];
                ldsm4(rh, sBh + off);
                ldsm4(rl, sBl + off);
                bh[np * 2][0] = rh[0];     bh[np * 2][1] = rh[1];
                bh[np * 2 + 1][0] = rh[2]; bh[np * 2 + 1][1] = rh[3];
                bl[np * 2][0] = rl[0];     bl[np * 2][1] = rl[1];
                bl[np * 2 + 1][0] = rl[2]; bl[np * 2 + 1][1] = rl[3];
            }
#pragma unroll
            for (int mi = 0; mi < 4; mi++)
#pragma unroll
                for (int ni = 0; ni < 4; ni++) {
                    mma16816(acc[mi][ni], ah[mi], bh[ni]);
                    mma16816(acc[mi][ni], al[mi], bh[ni]);
                    mma16816(acc[mi][ni], ah[mi], bl[ni]);
                }
        }
        __syncthreads();
    }

#pragma unroll
    for (int mi = 0; mi < 4; mi++) {
#pragma unroll
        for (int rr = 0; rr < 2; rr++) {
            int m = bm + wm + mi * 16 + gid + rr * 8;
            if (m >= M) continue;
#pragma unroll
            for (int ni = 0; ni < 4; ni++) {
                int n = bn + wn + ni * 8 + qid * 2;
                if (n >= N) continue;
                float v0 = acc[mi][ni][rr * 2]     + (bias ? bias[n] : 0.f);
                float v1 = acc[mi][ni][rr * 2 + 1] + (bias ? bias[n + 1] : 0.f);
                float* p = C + (size_t)m * N + n;
                if (addFlag) { p[0] += v0; p[1] += v1; }
                else { *(float2*)p = make_float2(v0, v1); }
            }
        }
    }
}

// ---------------- RMSNorm -> bf16 hi/lo --------------------------------------
__global__ void rmsnorm_kernel(const float* __restrict__ x, const float* __restrict__ w,
                               __nv_bfloat16* __restrict__ hi, __nv_bfloat16* __restrict__ lo) {
    int s = blockIdx.x;
    const float* xr = x + (size_t)s * HID;
    float ss = 0.f;
    for (int i = threadIdx.x; i < HID; i += 256) { float v = xr[i]; ss += v * v; }
#pragma unroll
    for (int o = 16; o; o >>= 1) ss += __shfl_xor_sync(0xffffffffu, ss, o);
    __shared__ float red[8];
    if ((threadIdx.x & 31) == 0) red[threadIdx.x >> 5] = ss;
    __syncthreads();
    if (threadIdx.x < 8) {
        float v = red[threadIdx.x];
#pragma unroll
        for (int o = 4; o; o >>= 1) v += __shfl_xor_sync(0xffu, v, o);
        if (threadIdx.x == 0) red[0] = v;
    }
    __syncthreads();
    float scale = rsqrtf(red[0] * (1.f / HID) + 1e-6f);
    for (int i = threadIdx.x; i < HID; i += 256)
        split1(xr[i] * scale * w[i], hi[(size_t)s * HID + i], lo[(size_t)s * HID + i]);
}

// ---------------- RoPE on q,k inside g_qkv ----------------------------------
__global__ void rope_kernel() {
    int s = blockIdx.x;
    size_t base = (size_t)s * QKV3;
    for (int p = threadIdx.x; p < 2 * HEADS * 40; p += 256) {
        int part = p / (HEADS * 40);
        int rem = p % (HEADS * 40);
        int head = rem / 40, d = rem % 40;
        size_t off = base + part * HID + head * HD + d;
        float c = g_cos[s * HD + d], sn = g_sin[s * HD + d];
        float v0 = g_qkv[off], v1 = g_qkv[off + 40];
        g_qkv[off]      = v0 * c - v1 * sn;
        g_qkv[off + 40] = v1 * c + v0 * sn;
    }
}

// ---------------- Attention (flash-style; windowed or full; f32x2 math) -----
#define QP 84
__global__ void attn_kernel(const float* __restrict__ qkv,
                            __nv_bfloat16* __restrict__ ohi, __nv_bfloat16* __restrict__ olo,
                            int windowed) {
    extern __shared__ float sm[];
    float* Qs = sm;
    float* Ks = Qs + 64 * QP;
    float* Vs = Ks + 64 * QP;
    float* Ss = Vs + 64 * QP;
    int qt = blockIdx.x, head = blockIdx.y;
    int tid = threadIdx.x;
    int row = tid >> 2, l4 = tid & 3;

    for (int i = tid; i < 64 * HD; i += 256) {
        int r = i / HD, d = i % HD;
        Qs[r * QP + d] = qkv[(size_t)(qt * 64 + r) * QKV3 + head * HD + d];
    }
    float M = -1e30f, L = 0.f;
    unsigned long long O2[10];
#pragma unroll
    for (int i = 0; i < 10; i++) O2[i] = 0ull;

    int t0 = windowed ? qt : 0;
    int t1 = windowed ? qt + 1 : NTILE64;
    for (int t = t0; t < t1; t++) {
        __syncthreads();
        for (int i = tid; i < 64 * HD; i += 256) {
            int r = i / HD, d = i % HD;
            size_t base = (size_t)(t * 64 + r) * QKV3 + head * HD + d;
            Ks[r * QP + d] = qkv[base + HID];
            Vs[r * QP + d] = qkv[base + 2 * HID];
        }
        __syncthreads();

        unsigned long long acc2[16];
#pragma unroll
        for (int j = 0; j < 16; j++) acc2[j] = 0ull;
        const unsigned long long* qrow = (const unsigned long long*)(Qs + row * QP);
        for (int d2 = 0; d2 < HD / 2; d2++) {
            unsigned long long q2 = qrow[d2];
#pragma unroll
            for (int j = 0; j < 16; j++) {
                unsigned long long k2 =
                    *(const unsigned long long*)(Ks + (l4 * 16 + j) * QP + d2 * 2);
                acc2[j] = fma2(q2, k2, acc2[j]);
            }
        }
        float dots[16];
        float tmax = -1e30f;
#pragma unroll
        for (int j = 0; j < 16; j++) {
            float a, b; upk2(acc2[j], a, b);
            dots[j] = (a + b) * 0.11180339887498949f;
            tmax = fmaxf(tmax, dots[j]);
        }
        tmax = fmaxf(tmax, __shfl_xor_sync(0xffffffffu, tmax, 1));
        tmax = fmaxf(tmax, __shfl_xor_sync(0xffffffffu, tmax, 2));
        float Mnew = fmaxf(M, tmax);
        float alpha = __expf(M - Mnew);
        float lsum = 0.f;
#pragma unroll
        for (int j = 0; j < 16; j++) {
            float p = __expf(dots[j] - Mnew);
            Ss[row * 65 + l4 * 16 + j] = p;
            lsum += p;
        }
        lsum += __shfl_xor_sync(0xffffffffu, lsum, 1);
        lsum += __shfl_xor_sync(0xffffffffu, lsum, 2);
        L = L * alpha + lsum;
        M = Mnew;
        unsigned long long al2 = pk2(alpha, alpha);
#pragma unroll
        for (int i = 0; i < 10; i++) O2[i] = mul2(O2[i], al2);
        __syncwarp();
        for (int key = 0; key < 64; key++) {
            float p = Ss[row * 65 + key];
            unsigned long long pp = pk2(p, p);
            const unsigned long long* vrow =
                (const unsigned long long*)(Vs + key * QP + l4 * 20);
#pragma unroll
            for (int i = 0; i < 10; i++) O2[i] = fma2(pp, vrow[i], O2[i]);
        }
    }
    float inv = 1.f / L;
    int token = qt * 64 + row;
#pragma unroll
    for (int i = 0; i < 10; i++) {
        float a, b; upk2(O2[i], a, b);
        size_t off = (size_t)token * HID + head * HD + l4 * 20 + 2 * i;
        split1(a * inv, ohi[off], olo[off]);
        split1(b * inv, ohi[off + 1], olo[off + 1]);
    }
}

// ---------------- Elementwise producers --------------------------------------
__global__ void silu_mul_kernel(const float* __restrict__ gate, const float* __restrict__ up,
                                __nv_bfloat16* __restrict__ hi, __nv_bfloat16* __restrict__ lo) {
    long total = (long)S_TOK * INTER_P;
    for (long i = blockIdx.x * (long)blockDim.x + threadIdx.x; i < total;
         i += (long)gridDim.x * blockDim.x) {
        long row = i / INTER_P;
        int col = (int)(i % INTER_P);
        float v = 0.f;
        if (col < INTER) {
            float g = gate[row * INTER + col];
            v = g / (1.f + __expf(-g)) * up[row * INTER + col];
        }
        split1(v, hi[i], lo[i]);
    }
}
__global__ void gelu_kernel(const float* __restrict__ x,
                            __nv_bfloat16* __restrict__ hi, __nv_bfloat16* __restrict__ lo,
                            long n) {
    for (long i = blockIdx.x * (long)blockDim.x + threadIdx.x; i < n;
         i += (long)gridDim.x * blockDim.x) {
        float v = x[i];
        split1(0.5f * v * (1.f + erff(v * 0.70710678118654752f)), hi[i], lo[i]);
    }
}
__global__ void scatter_out_kernel(const float* __restrict__ src, float* __restrict__ dst) {
    for (long i = blockIdx.x * (long)blockDim.x + threadIdx.x;
         i < (long)GROUPS * OUTDIM; i += (long)gridDim.x * blockDim.x) {
        int g = (int)(i / OUTDIM), n = (int)(i % OUTDIM);
        dst[(size_t)g_wingrp[g] * OUTDIM + n] = src[i];
    }
}

// ---------------- Host orchestration -----------------------------------------
#define GEMM_SMEM (2 * STG * (int)sizeof(__nv_bfloat16))

static void run_gemm(const __nv_bfloat16* Ahi, const __nv_bfloat16* Alo,
                     const __nv_bfloat16* Bhi, const __nv_bfloat16* Blo,
                     const float* bias, float* C, int M, int N, int K, int add) {
    dim3 grid((N + GBN - 1) / GBN, (M + GBM - 1) / GBM);
    gemm_tc_kernel<<<grid, 256, GEMM_SMEM>>>(Ahi, Alo, Bhi, Blo, bias, C, M, N, K, add);
}

extern "C" void kernel_launch(void* const* d_in, const int* in_sizes, int n_in,
                              void* d_out, int out_size) {
    const float* pixel_values = (const float*)d_in[0];
    const float* patch_w = (const float*)d_in[1];
    const float* qkv_w   = (const float*)d_in[2];
    const float* qkv_b   = (const float*)d_in[3];
    const float* proj_w  = (const float*)d_in[4];
    const float* proj_b  = (const float*)d_in[5];
    const float* norm1_w = (const float*)d_in[6];
    const float* norm2_w = (const float*)d_in[7];
    const float* gate_w  = (const float*)d_in[8];
    const float* gate_b  = (const float*)d_in[9];
    const float* up_w    = (const float*)d_in[10];
    const float* up_b    = (const float*)d_in[11];
    const float* down_w  = (const float*)d_in[12];
    const float* down_b  = (const float*)d_in[13];
    const float* ln_q_w  = (const float*)d_in[14];
    const float* m1_w    = (const float*)d_in[15];
    const float* m1_b    = (const float*)d_in[16];
    const float* m2_w    = (const float*)d_in[17];
    const float* m2_b    = (const float*)d_in[18];
    float* out = (float*)d_out;

    __nv_bfloat16 *whi, *wlo, *hhi, *hlo, *athi, *atlo, *achi, *aclo, *pxhi, *pxlo;
    float *x, *qkv, *gate, *up;
    cudaGetSymbolAddress((void**)&whi, g_whi);
    cudaGetSymbolAddress((void**)&wlo, g_wlo);
    cudaGetSymbolAddress((void**)&hhi, g_hhi);
    cudaGetSymbolAddress((void**)&hlo, g_hlo);
    cudaGetSymbolAddress((void**)&athi, g_athi);
    cudaGetSymbolAddress((void**)&atlo, g_atlo);
    cudaGetSymbolAddress((void**)&achi, g_achi);
    cudaGetSymbolAddress((void**)&aclo, g_aclo);
    cudaGetSymbolAddress((void**)&pxhi, g_pxhi);
    cudaGetSymbolAddress((void**)&pxlo, g_pxlo);
    cudaGetSymbolAddress((void**)&x,    g_x);
    cudaGetSymbolAddress((void**)&qkv,  g_qkv);
    cudaGetSymbolAddress((void**)&gate, g_gate);
    cudaGetSymbolAddress((void**)&up,   g_up);

    static int attr_set = 0;
    int attn_smem = (3 * 64 * QP + 64 * 65) * (int)sizeof(float);
    if (!attr_set) {
        cudaFuncSetAttribute(attn_kernel, cudaFuncAttributeMaxDynamicSharedMemorySize, attn_smem);
        cudaFuncSetAttribute(gemm_tc_kernel, cudaFuncAttributeMaxDynamicSharedMemorySize, GEMM_SMEM);
        attr_set = 1;
    }

    split_w_kernel<<<512, 256>>>(patch_w, whi + OFF_PATCH, wlo + OFF_PATCH, SZ_PATCH / 4);
    split_w_kernel<<<1024, 256>>>(qkv_w,  whi + OFF_QKV,   wlo + OFF_QKV,   SZ_QKV / 4);
    split_w_kernel<<<512, 256>>>(proj_w,  whi + OFF_PROJ,  wlo + OFF_PROJ,  SZ_PROJ / 4);
    split_w_kernel<<<1024, 256>>>(gate_w, whi + OFF_GATE,  wlo + OFF_GATE,  SZ_GATE / 4);
    split_w_kernel<<<1024, 256>>>(up_w,   whi + OFF_UP,    wlo + OFF_UP,    SZ_UP / 4);
    split_down_kernel<<<1024, 256>>>(down_w, whi + OFF_DOWN, wlo + OFF_DOWN);
    split_w_kernel<<<1024, 256>>>(m1_w,   whi + OFF_M1,    wlo + OFF_M1,    SZ_M1 / 4);
    split_w_kernel<<<1024, 256>>>(m2_w,   whi + OFF_M2,    wlo + OFF_M2,    SZ_M2 / 4);

    init_kernel<<<(S_TOK + 255) / 256, 256>>>();
    gather_pixels<<<512, 256>>>(pixel_values);

    run_gemm(pxhi, pxlo, whi + OFF_PATCH, wlo + OFF_PATCH, nullptr, x, S_TOK, HID, PIXF, 0);

    for (int i = 0; i < DEPTH; i++) {
        long oq = OFF_QKV + (long)i * QKV3 * HID;
        long op = OFF_PROJ + (long)i * HID * HID;
        long og = OFF_GATE + (long)i * INTER * HID;
        long ou = OFF_UP + (long)i * INTER * HID;
        long od = OFF_DOWN + (long)i * HID * INTER_P;
        const float* qb = qkv_b + (size_t)i * QKV3;
        const float* pb = proj_b + (size_t)i * HID;
        const float* n1 = norm1_w + (size_t)i * HID;
        const float* n2 = norm2_w + (size_t)i * HID;
        const float* gb = gate_b + (size_t)i * INTER;
        const float* ub = up_b + (size_t)i * INTER;
        const float* db = down_b + (size_t)i * HID;

        rmsnorm_kernel<<<S_TOK, 256>>>(x, n1, hhi, hlo);
        run_gemm(hhi, hlo, whi + oq, wlo + oq, qb, qkv, S_TOK, QKV3, HID, 0);
        rope_kernel<<<S_TOK, 256>>>();
        int windowed = (i == 3 || i == 7) ? 0 : 1;
        attn_kernel<<<dim3(NTILE64, HEADS), 256, attn_smem>>>(qkv, athi, atlo, windowed);
        run_gemm(athi, atlo, whi + op, wlo + op, pb, x, S_TOK, HID, HID, 1);

        rmsnorm_kernel<<<S_TOK, 256>>>(x, n2, hhi, hlo);
        run_gemm(hhi, hlo, whi + og, wlo + og, gb, gate, S_TOK, INTER, HID, 0);
        run_gemm(hhi, hlo, whi + ou, wlo + ou, ub, up, S_TOK, INTER, HID, 0);
        silu_mul_kernel<<<1024, 256>>>(gate, up, achi, aclo);
        run_gemm(achi, aclo, whi + od, wlo + od, db, x, S_TOK, HID, INTER_P, 1);
    }

    rmsnorm_kernel<<<S_TOK, 256>>>(x, ln_q_w, hhi, hlo);
    run_gemm(hhi, hlo, whi + OFF_M1, wlo + OFF_M1, m1_b, gate, GROUPS, MERGED, MERGED, 0);
    gelu_kernel<<<512, 256>>>(gate, achi, aclo, (long)GROUPS * MERGED);
    run_gemm(achi, aclo, whi + OFF_M2, wlo + OFF_M2, m2_b, qkv, GROUPS, OUTDIM, MERGED, 0);
    scatter_out_kernel<<<512, 256>>>(qkv, out);
}

// round 10
// speedup vs baseline: 2.3036x; 1.0012x over previous
#include <cuda_runtime.h>
#include <cuda_bf16.h>
#include <math.h>

// ---------------- Problem constants (fixed by setup_inputs) ----------------
#define S_TOK   2304
#define HID     1280
#define HEADS   16
#define HD      80
#define DEPTH   8
#define INTER   3420
#define INTER_P 3424     // padded to 16B-aligned rows (3424*2 = 6848 = 428*16)
#define OUTDIM  3584
#define QKV3    3840
#define GROUPS  576
#define PIXF    1176
#define MERGED  5120
#define NTILE64 36

// ---------------- Weight arena offsets (elements) ---------------------------
#define OFF_PATCH 0L
#define SZ_PATCH  (1280L*1176)
#define OFF_QKV   (OFF_PATCH + SZ_PATCH)
#define SZ_QKV    (8L*3840*1280)
#define OFF_PROJ  (OFF_QKV + SZ_QKV)
#define SZ_PROJ   (8L*1280*1280)
#define OFF_GATE  (OFF_PROJ + SZ_PROJ)
#define SZ_GATE   (8L*3420*1280)
#define OFF_UP    (OFF_GATE + SZ_GATE)
#define SZ_UP     (8L*3420*1280)
#define OFF_DOWN  (OFF_UP + SZ_UP)
#define SZ_DOWN   (8L*1280*INTER_P)     // padded K stride
#define OFF_M1    (OFF_DOWN + SZ_DOWN)
#define SZ_M1     (5120L*5120)
#define OFF_M2    (OFF_M1 + SZ_M1)
#define SZ_M2     (3584L*5120)
#define W_TOTAL   (OFF_M2 + SZ_M2)

// ---------------- Scratch (device globals) ----------------------------------
__device__ __nv_bfloat16 g_whi[W_TOTAL];
__device__ __nv_bfloat16 g_wlo[W_TOTAL];
__device__ float g_x[S_TOK * HID];
__device__ float g_qkv[S_TOK * QKV3];      // reused for m2 output
__device__ float g_gate[S_TOK * INTER];    // reused for m1 output
__device__ float g_up[S_TOK * INTER];
__device__ __nv_bfloat16 g_hhi[S_TOK * HID],  g_hlo[S_TOK * HID];
__device__ __nv_bfloat16 g_athi[S_TOK * HID], g_atlo[S_TOK * HID];
__device__ __nv_bfloat16 g_achi[S_TOK * INTER_P], g_aclo[S_TOK * INTER_P];
__device__ __nv_bfloat16 g_pxhi[S_TOK * PIXF], g_pxlo[S_TOK * PIXF];
__device__ float g_cos[S_TOK * HD];
__device__ float g_sin[S_TOK * HD];
__device__ int   g_orig[S_TOK];
__device__ int   g_wingrp[GROUPS];

// ---------------- helpers ----------------------------------------------------
__device__ __forceinline__ void split1(float v, __nv_bfloat16& h, __nv_bfloat16& l) {
    h = __float2bfloat16(v);
    l = __float2bfloat16(v - __bfloat162float(h));
}

// FMA-only fast exp (rel err ~1e-7); avoids MUFU EX2. Safe for x = -1e30.
__device__ __forceinline__ float fexpf(float x) {
    float t = x * 1.4426950408889634f;            // x*log2(e)
    t = fmaxf(fminf(t, 126.f), -126.f);
    float nf = rintf(t);
    float f = t - nf;                              // f in [-0.5, 0.5]
    float y = f * 0.6931471805599453f;             // f*ln2 in [-0.347, 0.347]
    float p = 1.3888889e-3f;
    p = fmaf(p, y, 8.3333338e-3f);
    p = fmaf(p, y, 4.1666668e-2f);
    p = fmaf(p, y, 1.6666667e-1f);
    p = fmaf(p, y, 5.0e-1f);
    p = fmaf(p, y, 1.0f);
    p = fmaf(p, y, 1.0f);
    int ni = (int)nf;
    float s = __int_as_float((ni + 127) << 23);
    return p * s;
}

// packed f32x2 helpers (sm_100+ base ISA)
__device__ __forceinline__ unsigned long long pk2(float a, float b) {
    unsigned long long r;
    asm("mov.b64 %0, {%1, %2};" : "=l"(r) : "f"(a), "f"(b));
    return r;
}
__device__ __forceinline__ void upk2(unsigned long long v, float& a, float& b) {
    asm("mov.b64 {%0, %1}, %2;" : "=f"(a), "=f"(b) : "l"(v));
}
__device__ __forceinline__ unsigned long long fma2(unsigned long long a,
                                                   unsigned long long b,
                                                   unsigned long long c) {
    unsigned long long d;
    asm("fma.rn.f32x2 %0, %1, %2, %3;" : "=l"(d) : "l"(a), "l"(b), "l"(c));
    return d;
}
__device__ __forceinline__ unsigned long long mul2(unsigned long long a,
                                                   unsigned long long b) {
    unsigned long long d;
    asm("mul.rn.f32x2 %0, %1, %2;" : "=l"(d) : "l"(a), "l"(b));
    return d;
}

// ---------------- Index + rotary precompute ---------------------------------
__global__ void init_kernel() {
    int s = blockIdx.x * blockDim.x + threadIdx.x;
    if (s >= S_TOK) return;
    int g = s >> 2, r = s & 3;
    int hb = g / 96, wb = (g / 16) % 6, hr = (g % 16) / 4, wr = g & 3;
    int og = (hb * 4 + hr) * 24 + (wb * 4 + wr);
    g_orig[s] = og * 4 + r;
    if (r == 0) g_wingrp[g] = og;
    int hg = og / 24, wg = og % 24;
    int hh = hg * 2 + (r >> 1), ww = wg * 2 + (r & 1);
    for (int j = 0; j < 40; j++) {
        float invf = powf(10000.f, -(float)(j % 20) / 20.f);
        float ang = (float)((j < 20) ? hh : ww) * invf;
        float c = cosf(ang), sn = sinf(ang);
        g_cos[s * HD + j] = c;  g_cos[s * HD + 40 + j] = c;
        g_sin[s * HD + j] = sn; g_sin[s * HD + 40 + j] = sn;
    }
}

__global__ void gather_pixels(const float* __restrict__ pix) {
    for (long i = blockIdx.x * (long)blockDim.x + threadIdx.x;
         i < (long)S_TOK * PIXF; i += (long)gridDim.x * blockDim.x) {
        int s = (int)(i / PIXF), c = (int)(i % PIXF);
        split1(pix[(long)g_orig[s] * PIXF + c], g_pxhi[i], g_pxlo[i]);
    }
}

// ---------------- Weight split (fp32 -> bf16 hi/lo) --------------------------
__global__ void split_w_kernel(const float* __restrict__ src,
                               __nv_bfloat16* __restrict__ hi,
                               __nv_bfloat16* __restrict__ lo, long n4) {
    for (long i = blockIdx.x * (long)blockDim.x + threadIdx.x; i < n4;
         i += (long)gridDim.x * blockDim.x) {
        float4 v = ((const float4*)src)[i];
        __nv_bfloat16 h0, h1, h2, h3, l0, l1, l2, l3;
        split1(v.x, h0, l0); split1(v.y, h1, l1);
        split1(v.z, h2, l2); split1(v.w, h3, l3);
        ((__nv_bfloat162*)hi)[2*i]   = __nv_bfloat162(h0, h1);
        ((__nv_bfloat162*)hi)[2*i+1] = __nv_bfloat162(h2, h3);
        ((__nv_bfloat162*)lo)[2*i]   = __nv_bfloat162(l0, l1);
        ((__nv_bfloat162*)lo)[2*i+1] = __nv_bfloat162(l2, l3);
    }
}

// down_w: split with row padding 3420 -> 3424 (pad = zeros)
__global__ void split_down_kernel(const float* __restrict__ src,
                                  __nv_bfloat16* __restrict__ hi,
                                  __nv_bfloat16* __restrict__ lo) {
    long total = 8L * 1280 * INTER_P;
    for (long i = blockIdx.x * (long)blockDim.x + threadIdx.x; i < total;
         i += (long)gridDim.x * blockDim.x) {
        long row = i / INTER_P;
        int col = (int)(i % INTER_P);
        float v = (col < INTER) ? src[row * INTER + col] : 0.f;
        split1(v, hi[i], lo[i]);
    }
}

// ============ Split-bf16 tensor-core GEMM (ldmatrix operand loads) ===========
// C[M,N] (+)= A[M,K] @ B[N,K]^T + bias, A/B pre-split bf16 hi/lo.
#define GBM 128
#define GBN 128
#define GBK 32
#define SKA 40
#define STG (4 * 128 * SKA)

__device__ __forceinline__ void mma16816(float* c, const unsigned* a, const unsigned* b) {
    asm volatile(
        "mma.sync.aligned.m16n8k16.row.col.f32.bf16.bf16.f32 "
        "{%0,%1,%2,%3}, {%4,%5,%6,%7}, {%8,%9}, {%0,%1,%2,%3};\n"
        : "+f"(c[0]), "+f"(c[1]), "+f"(c[2]), "+f"(c[3])
        : "r"(a[0]), "r"(a[1]), "r"(a[2]), "r"(a[3]), "r"(b[0]), "r"(b[1]));
}

__device__ __forceinline__ void ldsm4(unsigned* r, unsigned saddr) {
    asm volatile("ldmatrix.sync.aligned.m8n8.x4.shared.b16 {%0,%1,%2,%3}, [%4];"
                 : "=r"(r[0]), "=r"(r[1]), "=r"(r[2]), "=r"(r[3]) : "r"(saddr));
}

__device__ __forceinline__ void cpa16(__nv_bfloat16* dst, const __nv_bfloat16* src, int sz) {
    unsigned d = (unsigned)__cvta_generic_to_shared(dst);
    asm volatile("cp.async.cg.shared.global [%0], [%1], 16, %2;\n"
                 :: "r"(d), "l"(src), "r"(sz));
}

__global__ __launch_bounds__(256, 2)
void gemm_tc_kernel(const __nv_bfloat16* __restrict__ Ahi, const __nv_bfloat16* __restrict__ Alo,
                    const __nv_bfloat16* __restrict__ Bhi, const __nv_bfloat16* __restrict__ Blo,
                    const float* __restrict__ bias, float* __restrict__ C,
                    int M, int N, int K, int addFlag) {
    extern __shared__ __nv_bfloat16 smem[];
    int bm = blockIdx.y * GBM, bn = blockIdx.x * GBN;
    int tid = threadIdx.x;
    int wid = tid >> 5, lane = tid & 31;
    int wm = (wid & 1) * 64;
    int wn = (wid >> 1) * 32;
    int gid = lane >> 2, qid = lane & 3;

    int a_row = lane & 15;
    int a_coff = (lane >> 4) << 3;
    int b_row = ((lane >> 4) << 3) + (lane & 7);
    int b_coff = ((lane >> 3) & 1) << 3;

    unsigned smem_base = (unsigned)__cvta_generic_to_shared(smem);

    float acc[4][4][4];
#pragma unroll
    for (int mi = 0; mi < 4; mi++)
#pragma unroll
        for (int ni = 0; ni < 4; ni++)
#pragma unroll
            for (int r = 0; r < 4; r++) acc[mi][ni][r] = 0.f;

    int nT = (K + GBK - 1) / GBK;

    auto load_tile = [&](int k0, int st) {
        __nv_bfloat16* base = smem + st * STG;
#pragma unroll
        for (int it = 0; it < 2; it++) {
            int c = tid + it * 256;
            int row = c >> 2, seg = c & 3;
            int kk = k0 + seg * 8;
            int rem = K - kk;
            int ksz = rem >= 8 ? 16 : (rem >= 4 ? 8 : 0);
            int gm = bm + row;
            int szA = (gm < M) ? ksz : 0;
            size_t offA = szA ? ((size_t)gm * K + kk) : 0;
            int gn = bn + row;
            int szB = (gn < N) ? ksz : 0;
            size_t offB = szB ? ((size_t)gn * K + kk) : 0;
            int so = row * SKA + seg * 8;
            cpa16(base + so,                 Ahi + offA, szA);
            cpa16(base + 128 * SKA + so,     Alo + offA, szA);
            cpa16(base + 2 * 128 * SKA + so, Bhi + offB, szB);
            cpa16(base + 3 * 128 * SKA + so, Blo + offB, szB);
        }
        asm volatile("cp.async.commit_group;\n" ::);
    };

    load_tile(0, 0);

    for (int t = 0; t < nT; t++) {
        asm volatile("cp.async.wait_group 0;\n" ::);
        __syncthreads();
        if (t + 1 < nT) load_tile((t + 1) * GBK, (t + 1) & 1);

        unsigned stg = smem_base + (t & 1) * STG * 2;
        unsigned sAh = stg;
        unsigned sAl = stg + 128 * SKA * 2;
        unsigned sBh = stg + 2 * 128 * SKA * 2;
        unsigned sBl = stg + 3 * 128 * SKA * 2;

#pragma unroll
        for (int ks = 0; ks < GBK; ks += 16) {
            unsigned ah[4][4], al[4][4], bh[4][2], bl[4][2];
#pragma unroll
            for (int mi = 0; mi < 4; mi++) {
                unsigned off = (unsigned)(((wm + mi * 16 + a_row) * SKA
                                          + ks + a_coff) * 2);
                ldsm4(ah[mi], sAh + off);
                ldsm4(al[mi], sAl + off);
            }
#pragma unroll
            for (int np = 0; np < 2; np++) {
                unsigned off = (unsigned)(((wn + np * 16 + b_row) * SKA
                                          + ks + b_coff) * 2);
                unsigned rh[4], rl[4];
                ldsm4(rh, sBh + off);
                ldsm4(rl, sBl + off);
                bh[np * 2][0] = rh[0];     bh[np * 2][1] = rh[1];
                bh[np * 2 + 1][0] = rh[2]; bh[np * 2 + 1][1] = rh[3];
                bl[np * 2][0] = rl[0];     bl[np * 2][1] = rl[1];
                bl[np * 2 + 1][0] = rl[2]; bl[np * 2 + 1][1] = rl[3];
            }
#pragma unroll
            for (int mi = 0; mi < 4; mi++)
#pragma unroll
                for (int ni = 0; ni < 4; ni++) {
                    mma16816(acc[mi][ni], ah[mi], bh[ni]);
                    mma16816(acc[mi][ni], al[mi], bh[ni]);
                    mma16816(acc[mi][ni], ah[mi], bl[ni]);
                }
        }
        __syncthreads();
    }

#pragma unroll
    for (int mi = 0; mi < 4; mi++) {
#pragma unroll
        for (int rr = 0; rr < 2; rr++) {
            int m = bm + wm + mi * 16 + gid + rr * 8;
            if (m >= M) continue;
#pragma unroll
            for (int ni = 0; ni < 4; ni++) {
                int n = bn + wn + ni * 8 + qid * 2;
                if (n >= N) continue;
                float v0 = acc[mi][ni][rr * 2]     + (bias ? bias[n] : 0.f);
                float v1 = acc[mi][ni][rr * 2 + 1] + (bias ? bias[n + 1] : 0.f);
                float* p = C + (size_t)m * N + n;
                if (addFlag) { p[0] += v0; p[1] += v1; }
                else { *(float2*)p = make_float2(v0, v1); }
            }
        }
    }
}

// ---------------- RMSNorm -> bf16 hi/lo --------------------------------------
__global__ void rmsnorm_kernel(const float* __restrict__ x, const float* __restrict__ w,
                               __nv_bfloat16* __restrict__ hi, __nv_bfloat16* __restrict__ lo) {
    int s = blockIdx.x;
    const float* xr = x + (size_t)s * HID;
    float ss = 0.f;
    for (int i = threadIdx.x; i < HID; i += 256) { float v = xr[i]; ss += v * v; }
#pragma unroll
    for (int o = 16; o; o >>= 1) ss += __shfl_xor_sync(0xffffffffu, ss, o);
    __shared__ float red[8];
    if ((threadIdx.x & 31) == 0) red[threadIdx.x >> 5] = ss;
    __syncthreads();
    if (threadIdx.x < 8) {
        float v = red[threadIdx.x];
#pragma unroll
        for (int o = 4; o; o >>= 1) v += __shfl_xor_sync(0xffu, v, o);
        if (threadIdx.x == 0) red[0] = v;
    }
    __syncthreads();
    float scale = rsqrtf(red[0] * (1.f / HID) + 1e-6f);
    for (int i = threadIdx.x; i < HID; i += 256)
        split1(xr[i] * scale * w[i], hi[(size_t)s * HID + i], lo[(size_t)s * HID + i]);
}

// ---------------- RoPE on q,k inside g_qkv ----------------------------------
__global__ void rope_kernel() {
    int s = blockIdx.x;
    size_t base = (size_t)s * QKV3;
    for (int p = threadIdx.x; p < 2 * HEADS * 40; p += 256) {
        int part = p / (HEADS * 40);
        int rem = p % (HEADS * 40);
        int head = rem / 40, d = rem % 40;
        size_t off = base + part * HID + head * HD + d;
        float c = g_cos[s * HD + d], sn = g_sin[s * HD + d];
        float v0 = g_qkv[off], v1 = g_qkv[off + 40];
        g_qkv[off]      = v0 * c - v1 * sn;
        g_qkv[off + 40] = v1 * c + v0 * sn;
    }
}

// ---------------- Attention (flash-style; windowed or full; f32x2 + FMA exp) -
#define QP 84
__global__ void attn_kernel(const float* __restrict__ qkv,
                            __nv_bfloat16* __restrict__ ohi, __nv_bfloat16* __restrict__ olo,
                            int windowed) {
    extern __shared__ float sm[];
    float* Qs = sm;
    float* Ks = Qs + 64 * QP;
    float* Vs = Ks + 64 * QP;
    float* Ss = Vs + 64 * QP;
    int qt = blockIdx.x, head = blockIdx.y;
    int tid = threadIdx.x;
    int row = tid >> 2, l4 = tid & 3;

    for (int i = tid; i < 64 * HD; i += 256) {
        int r = i / HD, d = i % HD;
        Qs[r * QP + d] = qkv[(size_t)(qt * 64 + r) * QKV3 + head * HD + d];
    }
    float M = -1e30f, L = 0.f;
    unsigned long long O2[10];
#pragma unroll
    for (int i = 0; i < 10; i++) O2[i] = 0ull;

    int t0 = windowed ? qt : 0;
    int t1 = windowed ? qt + 1 : NTILE64;
    for (int t = t0; t < t1; t++) {
        __syncthreads();
        for (int i = tid; i < 64 * HD; i += 256) {
            int r = i / HD, d = i % HD;
            size_t base = (size_t)(t * 64 + r) * QKV3 + head * HD + d;
            Ks[r * QP + d] = qkv[base + HID];
            Vs[r * QP + d] = qkv[base + 2 * HID];
        }
        __syncthreads();

        unsigned long long acc2[16];
#pragma unroll
        for (int j = 0; j < 16; j++) acc2[j] = 0ull;
        const unsigned long long* qrow = (const unsigned long long*)(Qs + row * QP);
        for (int d2 = 0; d2 < HD / 2; d2++) {
            unsigned long long q2 = qrow[d2];
#pragma unroll
            for (int j = 0; j < 16; j++) {
                unsigned long long k2 =
                    *(const unsigned long long*)(Ks + (l4 * 16 + j) * QP + d2 * 2);
                acc2[j] = fma2(q2, k2, acc2[j]);
            }
        }
        float dots[16];
        float tmax = -1e30f;
#pragma unroll
        for (int j = 0; j < 16; j++) {
            float a, b; upk2(acc2[j], a, b);
            dots[j] = (a + b) * 0.11180339887498949f;
            tmax = fmaxf(tmax, dots[j]);
        }
        tmax = fmaxf(tmax, __shfl_xor_sync(0xffffffffu, tmax, 1));
        tmax = fmaxf(tmax, __shfl_xor_sync(0xffffffffu, tmax, 2));
        float Mnew = fmaxf(M, tmax);
        float alpha = fexpf(M - Mnew);
        float lsum = 0.f;
#pragma unroll
        for (int j = 0; j < 16; j++) {
            float p = fexpf(dots[j] - Mnew);
            Ss[row * 65 + l4 * 16 + j] = p;
            lsum += p;
        }
        lsum += __shfl_xor_sync(0xffffffffu, lsum, 1);
        lsum += __shfl_xor_sync(0xffffffffu, lsum, 2);
        L = L * alpha + lsum;
        M = Mnew;
        unsigned long long al2 = pk2(alpha, alpha);
#pragma unroll
        for (int i = 0; i < 10; i++) O2[i] = mul2(O2[i], al2);
        __syncwarp();
        for (int key = 0; key < 64; key++) {
            float p = Ss[row * 65 + key];
            unsigned long long pp = pk2(p, p);
            const unsigned long long* vrow =
                (const unsigned long long*)(Vs + key * QP + l4 * 20);
#pragma unroll
            for (int i = 0; i < 10; i++) O2[i] = fma2(pp, vrow[i], O2[i]);
        }
    }
    float inv = 1.f / L;
    int token = qt * 64 + row;
#pragma unroll
    for (int i = 0; i < 10; i++) {
        float a, b; upk2(O2[i], a, b);
        size_t off = (size_t)token * HID + head * HD + l4 * 20 + 2 * i;
        split1(a * inv, ohi[off], olo[off]);
        split1(b * inv, ohi[off + 1], olo[off + 1]);
    }
}

// ---------------- Elementwise producers --------------------------------------
__global__ void silu_mul_kernel(const float* __restrict__ gate, const float* __restrict__ up,
                                __nv_bfloat16* __restrict__ hi, __nv_bfloat16* __restrict__ lo) {
    long total = (long)S_TOK * INTER_P;
    for (long i = blockIdx.x * (long)blockDim.x + threadIdx.x; i < total;
         i += (long)gridDim.x * blockDim.x) {
        long row = i / INTER_P;
        int col = (int)(i % INTER_P);
        float v = 0.f;
        if (col < INTER) {
            float g = gate[row * INTER + col];
            float e = fexpf(-g);
            v = __fdividef(g, 1.f + e) * up[row * INTER + col];
        }
        split1(v, hi[i], lo[i]);
    }
}
__global__ void gelu_kernel(const float* __restrict__ x,
                            __nv_bfloat16* __restrict__ hi, __nv_bfloat16* __restrict__ lo,
                            long n) {
    for (long i = blockIdx.x * (long)blockDim.x + threadIdx.x; i < n;
         i += (long)gridDim.x * blockDim.x) {
        float v = x[i];
        split1(0.5f * v * (1.f + erff(v * 0.70710678118654752f)), hi[i], lo[i]);
    }
}
__global__ void scatter_out_kernel(const float* __restrict__ src, float* __restrict__ dst) {
    for (long i = blockIdx.x * (long)blockDim.x + threadIdx.x;
         i < (long)GROUPS * OUTDIM; i += (long)gridDim.x * blockDim.x) {
        int g = (int)(i / OUTDIM), n = (int)(i % OUTDIM);
        dst[(size_t)g_wingrp[g] * OUTDIM + n] = src[i];
    }
}

// ---------------- Host orchestration -----------------------------------------
#define GEMM_SMEM (2 * STG * (int)sizeof(__nv_bfloat16))

static void run_gemm(const __nv_bfloat16* Ahi, const __nv_bfloat16* Alo,
                     const __nv_bfloat16* Bhi, const __nv_bfloat16* Blo,
                     const float* bias, float* C, int M, int N, int K, int add) {
    dim3 grid((N + GBN - 1) / GBN, (M + GBM - 1) / GBM);
    gemm_tc_kernel<<<grid, 256, GEMM_SMEM>>>(Ahi, Alo, Bhi, Blo, bias, C, M, N, K, add);
}

extern "C" void kernel_launch(void* const* d_in, const int* in_sizes, int n_in,
                              void* d_out, int out_size) {
    const float* pixel_values = (const float*)d_in[0];
    const float* patch_w = (const float*)d_in[1];
    const float* qkv_w   = (const float*)d_in[2];
    const float* qkv_b   = (const float*)d_in[3];
    const float* proj_w  = (const float*)d_in[4];
    const float* proj_b  = (const float*)d_in[5];
    const float* norm1_w = (const float*)d_in[6];
    const float* norm2_w = (const float*)d_in[7];
    const float* gate_w  = (const float*)d_in[8];
    const float* gate_b  = (const float*)d_in[9];
    const float* up_w    = (const float*)d_in[10];
    const float* up_b    = (const float*)d_in[11];
    const float* down_w  = (const float*)d_in[12];
    const float* down_b  = (const float*)d_in[13];
    const float* ln_q_w  = (const float*)d_in[14];
    const float* m1_w    = (const float*)d_in[15];
    const float* m1_b    = (const float*)d_in[16];
    const float* m2_w    = (const float*)d_in[17];
    const float* m2_b    = (const float*)d_in[18];
    float* out = (float*)d_out;

    __nv_bfloat16 *whi, *wlo, *hhi, *hlo, *athi, *atlo, *achi, *aclo, *pxhi, *pxlo;
    float *x, *qkv, *gate, *up;
    cudaGetSymbolAddress((void**)&whi, g_whi);
    cudaGetSymbolAddress((void**)&wlo, g_wlo);
    cudaGetSymbolAddress((void**)&hhi, g_hhi);
    cudaGetSymbolAddress((void**)&hlo, g_hlo);
    cudaGetSymbolAddress((void**)&athi, g_athi);
    cudaGetSymbolAddress((void**)&atlo, g_atlo);
    cudaGetSymbolAddress((void**)&achi, g_achi);
    cudaGetSymbolAddress((void**)&aclo, g_aclo);
    cudaGetSymbolAddress((void**)&pxhi, g_pxhi);
    cudaGetSymbolAddress((void**)&pxlo, g_pxlo);
    cudaGetSymbolAddress((void**)&x,    g_x);
    cudaGetSymbolAddress((void**)&qkv,  g_qkv);
    cudaGetSymbolAddress((void**)&gate, g_gate);
    cudaGetSymbolAddress((void**)&up,   g_up);

    static int attr_set = 0;
    int attn_smem = (3 * 64 * QP + 64 * 65) * (int)sizeof(float);
    if (!attr_set) {
        cudaFuncSetAttribute(attn_kernel, cudaFuncAttributeMaxDynamicSharedMemorySize, attn_smem);
        cudaFuncSetAttribute(gemm_tc_kernel, cudaFuncAttributeMaxDynamicSharedMemorySize, GEMM_SMEM);
        attr_set = 1;
    }

    split_w_kernel<<<512, 256>>>(patch_w, whi + OFF_PATCH, wlo + OFF_PATCH, SZ_PATCH / 4);
    split_w_kernel<<<1024, 256>>>(qkv_w,  whi + OFF_QKV,   wlo + OFF_QKV,   SZ_QKV / 4);
    split_w_kernel<<<512, 256>>>(proj_w,  whi + OFF_PROJ,  wlo + OFF_PROJ,  SZ_PROJ / 4);
    split_w_kernel<<<1024, 256>>>(gate_w, whi + OFF_GATE,  wlo + OFF_GATE,  SZ_GATE / 4);
    split_w_kernel<<<1024, 256>>>(up_w,   whi + OFF_UP,    wlo + OFF_UP,    SZ_UP / 4);
    split_down_kernel<<<1024, 256>>>(down_w, whi + OFF_DOWN, wlo + OFF_DOWN);
    split_w_kernel<<<1024, 256>>>(m1_w,   whi + OFF_M1,    wlo + OFF_M1,    SZ_M1 / 4);
    split_w_kernel<<<1024, 256>>>(m2_w,   whi + OFF_M2,    wlo + OFF_M2,    SZ_M2 / 4);

    init_kernel<<<(S_TOK + 255) / 256, 256>>>();
    gather_pixels<<<512, 256>>>(pixel_values);

    run_gemm(pxhi, pxlo, whi + OFF_PATCH, wlo + OFF_PATCH, nullptr, x, S_TOK, HID, PIXF, 0);

    for (int i = 0; i < DEPTH; i++) {
        long oq = OFF_QKV + (long)i * QKV3 * HID;
        long op = OFF_PROJ + (long)i * HID * HID;
        long og = OFF_GATE + (long)i * INTER * HID;
        long ou = OFF_UP + (long)i * INTER * HID;
        long od = OFF_DOWN + (long)i * HID * INTER_P;
        const float* qb = qkv_b + (size_t)i * QKV3;
        const float* pb = proj_b + (size_t)i * HID;
        const float* n1 = norm1_w + (size_t)i * HID;
        const float* n2 = norm2_w + (size_t)i * HID;
        const float* gb = gate_b + (size_t)i * INTER;
        const float* ub = up_b + (size_t)i * INTER;
        const float* db = down_b + (size_t)i * HID;

        rmsnorm_kernel<<<S_TOK, 256>>>(x, n1, hhi, hlo);
        run_gemm(hhi, hlo, whi + oq, wlo + oq, qb, qkv, S_TOK, QKV3, HID, 0);
        rope_kernel<<<S_TOK, 256>>>();
        int windowed = (i == 3 || i == 7) ? 0 : 1;
        attn_kernel<<<dim3(NTILE64, HEADS), 256, attn_smem>>>(qkv, athi, atlo, windowed);
        run_gemm(athi, atlo, whi + op, wlo + op, pb, x, S_TOK, HID, HID, 1);

        rmsnorm_kernel<<<S_TOK, 256>>>(x, n2, hhi, hlo);
        run_gemm(hhi, hlo, whi + og, wlo + og, gb, gate, S_TOK, INTER, HID, 0);
        run_gemm(hhi, hlo, whi + ou, wlo + ou, ub, up, S_TOK, INTER, HID, 0);
        silu_mul_kernel<<<1024, 256>>>(gate, up, achi, aclo);
        run_gemm(achi, aclo, whi + od, wlo + od, db, x, S_TOK, HID, INTER_P, 1);
    }

    rmsnorm_kernel<<<S_TOK, 256>>>(x, ln_q_w, hhi, hlo);
    run_gemm(hhi, hlo, whi + OFF_M1, wlo + OFF_M1, m1_b, gate, GROUPS, MERGED, MERGED, 0);
    gelu_kernel<<<512, 256>>>(gate, achi, aclo, (long)GROUPS * MERGED);
    run_gemm(achi, aclo, whi + OFF_M2, wlo + OFF_M2, m2_b, qkv, GROUPS, OUTDIM, MERGED, 0);
    scatter_out_kernel<<<512, 256>>>(qkv, out);
}

// round 12
// speedup vs baseline: 2.3639x; 1.0262x over previous
#include <cuda_runtime.h>
#include <cuda_fp16.h>
#include <math.h>

// ---------------- Problem constants (fixed by setup_inputs) ----------------
#define S_TOK   2304
#define HID     1280
#define HEADS   16
#define HD      80
#define DEPTH   8
#define INTER   3420
#define INTER_P 3424
#define OUTDIM  3584
#define QKV3    3840
#define GROUPS  576
#define PIXF    1176
#define MERGED  5120
#define NTILE64 36

// ---------------- Weight arena offsets (elements) ---------------------------
#define OFF_PATCH 0L
#define SZ_PATCH  (1280L*1176)
#define OFF_QKV   (OFF_PATCH + SZ_PATCH)
#define SZ_QKV    (8L*3840*1280)
#define OFF_PROJ  (OFF_QKV + SZ_QKV)
#define SZ_PROJ   (8L*1280*1280)
#define OFF_GATE  (OFF_PROJ + SZ_PROJ)
#define SZ_GATE   (8L*3420*1280)
#define OFF_UP    (OFF_GATE + SZ_GATE)
#define SZ_UP     (8L*3420*1280)
#define OFF_DOWN  (OFF_UP + SZ_UP)
#define SZ_DOWN   (8L*1280*INTER_P)
#define OFF_M1    (OFF_DOWN + SZ_DOWN)
#define SZ_M1     (5120L*5120)
#define OFF_M2    (OFF_M1 + SZ_M1)
#define SZ_M2     (3584L*5120)
#define W_TOTAL   (OFF_M2 + SZ_M2)

// ---------------- Scratch (device globals) ----------------------------------
__device__ __half g_whi[W_TOTAL];
__device__ __half g_wlo[W_TOTAL];
__device__ float g_x[S_TOK * HID];
__device__ float g_qkv[S_TOK * QKV3];
__device__ float g_gate[S_TOK * INTER];
__device__ float g_up[S_TOK * INTER];
__device__ __half g_hhi[S_TOK * HID],  g_hlo[S_TOK * HID];
__device__ __half g_athi[S_TOK * HID], g_atlo[S_TOK * HID];
__device__ __half g_achi[S_TOK * INTER_P], g_aclo[S_TOK * INTER_P];
__device__ __half g_pxhi[S_TOK * PIXF], g_pxlo[S_TOK * PIXF];
__device__ float g_cos[S_TOK * HD];
__device__ float g_sin[S_TOK * HD];
__device__ int   g_orig[S_TOK];
__device__ int   g_wingrp[GROUPS];

// ---------------- helpers ----------------------------------------------------
__device__ __forceinline__ void split1(float v, __half& h, __half& l) {
    h = __float2half_rn(v);
    l = __float2half_rn(v - __half2float(h));
}

// FMA-only fast exp (rel err ~1e-7)
__device__ __forceinline__ float fexpf(float x) {
    float t = x * 1.4426950408889634f;
    t = fmaxf(fminf(t, 126.f), -126.f);
    float nf = rintf(t);
    float f = t - nf;
    float y = f * 0.6931471805599453f;
    float p = 1.3888889e-3f;
    p = fmaf(p, y, 8.3333338e-3f);
    p = fmaf(p, y, 4.1666668e-2f);
    p = fmaf(p, y, 1.6666667e-1f);
    p = fmaf(p, y, 5.0e-1f);
    p = fmaf(p, y, 1.0f);
    p = fmaf(p, y, 1.0f);
    int ni = (int)nf;
    float s = __int_as_float((ni + 127) << 23);
    return p * s;
}

// packed f32x2 helpers
__device__ __forceinline__ unsigned long long pk2(float a, float b) {
    unsigned long long r;
    asm("mov.b64 %0, {%1, %2};" : "=l"(r) : "f"(a), "f"(b));
    return r;
}
__device__ __forceinline__ void upk2(unsigned long long v, float& a, float& b) {
    asm("mov.b64 {%0, %1}, %2;" : "=f"(a), "=f"(b) : "l"(v));
}
__device__ __forceinline__ unsigned long long fma2(unsigned long long a,
                                                   unsigned long long b,
                                                   unsigned long long c) {
    unsigned long long d;
    asm("fma.rn.f32x2 %0, %1, %2, %3;" : "=l"(d) : "l"(a), "l"(b), "l"(c));
    return d;
}
__device__ __forceinline__ unsigned long long mul2(unsigned long long a,
                                                   unsigned long long b) {
    unsigned long long d;
    asm("mul.rn.f32x2 %0, %1, %2;" : "=l"(d) : "l"(a), "l"(b));
    return d;
}

// ---------------- Index + rotary precompute ---------------------------------
__global__ void init_kernel() {
    int s = blockIdx.x * blockDim.x + threadIdx.x;
    if (s >= S_TOK) return;
    int g = s >> 2, r = s & 3;
    int hb = g / 96, wb = (g / 16) % 6, hr = (g % 16) / 4, wr = g & 3;
    int og = (hb * 4 + hr) * 24 + (wb * 4 + wr);
    g_orig[s] = og * 4 + r;
    if (r == 0) g_wingrp[g] = og;
    int hg = og / 24, wg = og % 24;
    int hh = hg * 2 + (r >> 1), ww = wg * 2 + (r & 1);
    for (int j = 0; j < 40; j++) {
        float invf = powf(10000.f, -(float)(j % 20) / 20.f);
        float ang = (float)((j < 20) ? hh : ww) * invf;
        float c = cosf(ang), sn = sinf(ang);
        g_cos[s * HD + j] = c;  g_cos[s * HD + 40 + j] = c;
        g_sin[s * HD + j] = sn; g_sin[s * HD + 40 + j] = sn;
    }
}

__global__ void gather_pixels(const float* __restrict__ pix) {
    for (long i = blockIdx.x * (long)blockDim.x + threadIdx.x;
         i < (long)S_TOK * PIXF; i += (long)gridDim.x * blockDim.x) {
        int s = (int)(i / PIXF), c = (int)(i % PIXF);
        split1(pix[(long)g_orig[s] * PIXF + c], g_pxhi[i], g_pxlo[i]);
    }
}

// ---------------- Weight split (fp32 -> fp16 hi/lo) --------------------------
__global__ void split_w_kernel(const float* __restrict__ src,
                               __half* __restrict__ hi,
                               __half* __restrict__ lo, long n4) {
    for (long i = blockIdx.x * (long)blockDim.x + threadIdx.x; i < n4;
         i += (long)gridDim.x * blockDim.x) {
        float4 v = ((const float4*)src)[i];
        __half h0, h1, h2, h3, l0, l1, l2, l3;
        split1(v.x, h0, l0); split1(v.y, h1, l1);
        split1(v.z, h2, l2); split1(v.w, h3, l3);
        ((__half2*)hi)[2*i]   = __halves2half2(h0, h1);
        ((__half2*)hi)[2*i+1] = __halves2half2(h2, h3);
        ((__half2*)lo)[2*i]   = __halves2half2(l0, l1);
        ((__half2*)lo)[2*i+1] = __halves2half2(l2, l3);
    }
}

__global__ void split_down_kernel(const float* __restrict__ src,
                                  __half* __restrict__ hi,
                                  __half* __restrict__ lo) {
    long total = 8L * 1280 * INTER_P;
    for (long i = blockIdx.x * (long)blockDim.x + threadIdx.x; i < total;
         i += (long)gridDim.x * blockDim.x) {
        long row = i / INTER_P;
        int col = (int)(i % INTER_P);
        float v = (col < INTER) ? src[row * INTER + col] : 0.f;
        split1(v, hi[i], lo[i]);
    }
}

// ============ Split-fp16 tensor-core GEMM ====================================
// Main term: f32 acc. Two correction terms: chained f16 acc (one per subtile).
#define GBM 128
#define GBN 64
#define GBK 32
#define SKA 40
#define STG (384 * SKA)          // Ahi(128)|Alo(128)|Bhi(64)|Blo(64) rows

__device__ __forceinline__ void mma_f32(float* c, const unsigned* a, const unsigned* b) {
    asm volatile(
        "mma.sync.aligned.m16n8k16.row.col.f32.f16.f16.f32 "
        "{%0,%1,%2,%3}, {%4,%5,%6,%7}, {%8,%9}, {%0,%1,%2,%3};\n"
        : "+f"(c[0]), "+f"(c[1]), "+f"(c[2]), "+f"(c[3])
        : "r"(a[0]), "r"(a[1]), "r"(a[2]), "r"(a[3]), "r"(b[0]), "r"(b[1]));
}
__device__ __forceinline__ void mma_f16(unsigned* c, const unsigned* a, const unsigned* b) {
    asm volatile(
        "mma.sync.aligned.m16n8k16.row.col.f16.f16.f16.f16 "
        "{%0,%1}, {%2,%3,%4,%5}, {%6,%7}, {%0,%1};\n"
        : "+r"(c[0]), "+r"(c[1])
        : "r"(a[0]), "r"(a[1]), "r"(a[2]), "r"(a[3]), "r"(b[0]), "r"(b[1]));
}

__device__ __forceinline__ void ldsm4(unsigned* r, unsigned saddr) {
    asm volatile("ldmatrix.sync.aligned.m8n8.x4.shared.b16 {%0,%1,%2,%3}, [%4];"
                 : "=r"(r[0]), "=r"(r[1]), "=r"(r[2]), "=r"(r[3]) : "r"(saddr));
}

__device__ __forceinline__ void cpa16(__half* dst, const __half* src, int sz) {
    unsigned d = (unsigned)__cvta_generic_to_shared(dst);
    asm volatile("cp.async.cg.shared.global [%0], [%1], 16, %2;\n"
                 :: "r"(d), "l"(src), "r"(sz));
}

__global__ __launch_bounds__(256, 2)
void gemm_tc_kernel(const __half* __restrict__ Ahi, const __half* __restrict__ Alo,
                    const __half* __restrict__ Bhi, const __half* __restrict__ Blo,
                    const float* __restrict__ bias, float* __restrict__ C,
                    int M, int N, int K, int addFlag) {
    extern __shared__ __half smem[];
    int bm = blockIdx.y * GBM, bn = blockIdx.x * GBN;
    int tid = threadIdx.x;
    int wid = tid >> 5, lane = tid & 31;
    int wm = (wid & 3) * 32;          // 4 warps in m
    int wn = (wid >> 2) * 32;         // 2 warps in n
    int gid = lane >> 2, qid = lane & 3;

    int a_row = lane & 15;
    int a_coff = (lane >> 4) << 3;
    int b_row = ((lane >> 4) << 3) + (lane & 7);
    int b_coff = ((lane >> 3) & 1) << 3;

    unsigned smem_base = (unsigned)__cvta_generic_to_shared(smem);

    float acc[2][4][4];
    unsigned acc16[2][4][2];
#pragma unroll
    for (int mi = 0; mi < 2; mi++)
#pragma unroll
        for (int ni = 0; ni < 4; ni++) {
#pragma unroll
            for (int r = 0; r < 4; r++) acc[mi][ni][r] = 0.f;
            acc16[mi][ni][0] = 0u; acc16[mi][ni][1] = 0u;
        }

    int nT = (K + GBK - 1) / GBK;

    auto load_tile = [&](int k0, int st) {
        __half* base = smem + st * STG;
#pragma unroll
        for (int j = 0; j < 6; j++) {
            int idx = tid + j * 256;               // 0..1535
            const __half* src; __half* dst;
            int row, seg, rbase, lim;
            if (idx < 1024) {
                int t = idx & 511; row = t >> 2; seg = t & 3;
                src = (idx < 512) ? Ahi : Alo;
                dst = base + ((idx < 512) ? 0 : 128 * SKA);
                rbase = bm; lim = M;
            } else {
                int u = idx - 1024; int t = u & 255; row = t >> 2; seg = t & 3;
                src = (u < 256) ? Bhi : Blo;
                dst = base + 256 * SKA + ((u < 256) ? 0 : 64 * SKA);
                rbase = bn; lim = N;
            }
            int kk = k0 + seg * 8;
            int rem = K - kk;
            int ksz = rem >= 8 ? 16 : (rem >= 4 ? 8 : 0);
            int gr = rbase + row;
            int sz = (gr < lim) ? ksz : 0;
            size_t off = sz ? ((size_t)gr * K + kk) : 0;
            cpa16(dst + row * SKA + seg * 8, src + off, sz);
        }
        asm volatile("cp.async.commit_group;\n" ::);
    };

    load_tile(0, 0);

    for (int t = 0; t < nT; t++) {
        asm volatile("cp.async.wait_group 0;\n" ::);
        __syncthreads();
        if (t + 1 < nT) load_tile((t + 1) * GBK, (t + 1) & 1);

        unsigned stg = smem_base + (t & 1) * STG * 2;
        unsigned sAh = stg;
        unsigned sAl = stg + 128 * SKA * 2;
        unsigned sBh = stg + 256 * SKA * 2;
        unsigned sBl = stg + 320 * SKA * 2;

#pragma unroll
        for (int ks = 0; ks < GBK; ks += 16) {
            unsigned ah[2][4], al[2][4], bh[4][2], bl[4][2];
#pragma unroll
            for (int mi = 0; mi < 2; mi++) {
                unsigned off = (unsigned)(((wm + mi * 16 + a_row) * SKA
                                          + ks + a_coff) * 2);
                ldsm4(ah[mi], sAh + off);
                ldsm4(al[mi], sAl + off);
            }
#pragma unroll
            for (int np = 0; np < 2; np++) {
                unsigned off = (unsigned)(((wn + np * 16 + b_row) * SKA
                                          + ks + b_coff) * 2);
                unsigned rh[4], rl[4];
                ldsm4(rh, sBh + off);
                ldsm4(rl, sBl + off);
                bh[np * 2][0] = rh[0];     bh[np * 2][1] = rh[1];
                bh[np * 2 + 1][0] = rh[2]; bh[np * 2 + 1][1] = rh[3];
                bl[np * 2][0] = rl[0];     bl[np * 2][1] = rl[1];
                bl[np * 2 + 1][0] = rl[2]; bl[np * 2 + 1][1] = rl[3];
            }
#pragma unroll
            for (int mi = 0; mi < 2; mi++)
#pragma unroll
                for (int ni = 0; ni < 4; ni++) {
                    mma_f32(acc[mi][ni], ah[mi], bh[ni]);
                    mma_f16(acc16[mi][ni], al[mi], bh[ni]);
                    mma_f16(acc16[mi][ni], ah[mi], bl[ni]);
                }
        }
        __syncthreads();
    }

#pragma unroll
    for (int mi = 0; mi < 2; mi++) {
#pragma unroll
        for (int rr = 0; rr < 2; rr++) {
            int m = bm + wm + mi * 16 + gid + rr * 8;
            if (m >= M) continue;
#pragma unroll
            for (int ni = 0; ni < 4; ni++) {
                int n = bn + wn + ni * 8 + qid * 2;
                if (n >= N) continue;
                float2 corr = __half22float2(
                    *reinterpret_cast<__half2*>(&acc16[mi][ni][rr]));
                float v0 = acc[mi][ni][rr * 2]     + corr.x + (bias ? bias[n] : 0.f);
                float v1 = acc[mi][ni][rr * 2 + 1] + corr.y + (bias ? bias[n + 1] : 0.f);
                float* p = C + (size_t)m * N + n;
                if (addFlag) { p[0] += v0; p[1] += v1; }
                else { *(float2*)p = make_float2(v0, v1); }
            }
        }
    }
}

// ---------------- RMSNorm -> fp16 hi/lo --------------------------------------
__global__ void rmsnorm_kernel(const float* __restrict__ x, const float* __restrict__ w,
                               __half* __restrict__ hi, __half* __restrict__ lo) {
    int s = blockIdx.x;
    const float* xr = x + (size_t)s * HID;
    float ss = 0.f;
    for (int i = threadIdx.x; i < HID; i += 256) { float v = xr[i]; ss += v * v; }
#pragma unroll
    for (int o = 16; o; o >>= 1) ss += __shfl_xor_sync(0xffffffffu, ss, o);
    __shared__ float red[8];
    if ((threadIdx.x & 31) == 0) red[threadIdx.x >> 5] = ss;
    __syncthreads();
    if (threadIdx.x < 8) {
        float v = red[threadIdx.x];
#pragma unroll
        for (int o = 4; o; o >>= 1) v += __shfl_xor_sync(0xffu, v, o);
        if (threadIdx.x == 0) red[0] = v;
    }
    __syncthreads();
    float scale = rsqrtf(red[0] * (1.f / HID) + 1e-6f);
    for (int i = threadIdx.x; i < HID; i += 256)
        split1(xr[i] * scale * w[i], hi[(size_t)s * HID + i], lo[(size_t)s * HID + i]);
}

// ---------------- RoPE on q,k inside g_qkv ----------------------------------
__global__ void rope_kernel() {
    int s = blockIdx.x;
    size_t base = (size_t)s * QKV3;
    for (int p = threadIdx.x; p < 2 * HEADS * 40; p += 256) {
        int part = p / (HEADS * 40);
        int rem = p % (HEADS * 40);
        int head = rem / 40, d = rem % 40;
        size_t off = base + part * HID + head * HD + d;
        float c = g_cos[s * HD + d], sn = g_sin[s * HD + d];
        float v0 = g_qkv[off], v1 = g_qkv[off + 40];
        g_qkv[off]      = v0 * c - v1 * sn;
        g_qkv[off + 40] = v1 * c + v0 * sn;
    }
}

// ---------------- Attention (flash-style; f32x2 + FMA exp) -------------------
#define QP 84
__global__ void attn_kernel(const float* __restrict__ qkv,
                            __half* __restrict__ ohi, __half* __restrict__ olo,
                            int windowed) {
    extern __shared__ float sm[];
    float* Qs = sm;
    float* Ks = Qs + 64 * QP;
    float* Vs = Ks + 64 * QP;
    float* Ss = Vs + 64 * QP;
    int qt = blockIdx.x, head = blockIdx.y;
    int tid = threadIdx.x;
    int row = tid >> 2, l4 = tid & 3;

    for (int i = tid; i < 64 * HD; i += 256) {
        int r = i / HD, d = i % HD;
        Qs[r * QP + d] = qkv[(size_t)(qt * 64 + r) * QKV3 + head * HD + d];
    }
    float M = -1e30f, L = 0.f;
    unsigned long long O2[10];
#pragma unroll
    for (int i = 0; i < 10; i++) O2[i] = 0ull;

    int t0 = windowed ? qt : 0;
    int t1 = windowed ? qt + 1 : NTILE64;
    for (int t = t0; t < t1; t++) {
        __syncthreads();
        for (int i = tid; i < 64 * HD; i += 256) {
            int r = i / HD, d = i % HD;
            size_t base = (size_t)(t * 64 + r) * QKV3 + head * HD + d;
            Ks[r * QP + d] = qkv[base + HID];
            Vs[r * QP + d] = qkv[base + 2 * HID];
        }
        __syncthreads();

        unsigned long long acc2[16];
#pragma unroll
        for (int j = 0; j < 16; j++) acc2[j] = 0ull;
        const unsigned long long* qrow = (const unsigned long long*)(Qs + row * QP);
        for (int d2 = 0; d2 < HD / 2; d2++) {
            unsigned long long q2 = qrow[d2];
#pragma unroll
            for (int j = 0; j < 16; j++) {
                unsigned long long k2 =
                    *(const unsigned long long*)(Ks + (l4 * 16 + j) * QP + d2 * 2);
                acc2[j] = fma2(q2, k2, acc2[j]);
            }
        }
        float dots[16];
        float tmax = -1e30f;
#pragma unroll
        for (int j = 0; j < 16; j++) {
            float a, b; upk2(acc2[j], a, b);
            dots[j] = (a + b) * 0.11180339887498949f;
            tmax = fmaxf(tmax, dots[j]);
        }
        tmax = fmaxf(tmax, __shfl_xor_sync(0xffffffffu, tmax, 1));
        tmax = fmaxf(tmax, __shfl_xor_sync(0xffffffffu, tmax, 2));
        float Mnew = fmaxf(M, tmax);
        float alpha = fexpf(M - Mnew);
        float lsum = 0.f;
#pragma unroll
        for (int j = 0; j < 16; j++) {
            float p = fexpf(dots[j] - Mnew);
            Ss[row * 65 + l4 * 16 + j] = p;
            lsum += p;
        }
        lsum += __shfl_xor_sync(0xffffffffu, lsum, 1);
        lsum += __shfl_xor_sync(0xffffffffu, lsum, 2);
        L = L * alpha + lsum;
        M = Mnew;
        unsigned long long al2 = pk2(alpha, alpha);
#pragma unroll
        for (int i = 0; i < 10; i++) O2[i] = mul2(O2[i], al2);
        __syncwarp();
        for (int key = 0; key < 64; key++) {
            float p = Ss[row * 65 + key];
            unsigned long long pp = pk2(p, p);
            const unsigned long long* vrow =
                (const unsigned long long*)(Vs + key * QP + l4 * 20);
#pragma unroll
            for (int i = 0; i < 10; i++) O2[i] = fma2(pp, vrow[i], O2[i]);
        }
    }
    float inv = 1.f / L;
    int token = qt * 64 + row;
#pragma unroll
    for (int i = 0; i < 10; i++) {
        float a, b; upk2(O2[i], a, b);
        size_t off = (size_t)token * HID + head * HD + l4 * 20 + 2 * i;
        split1(a * inv, ohi[off], olo[off]);
        split1(b * inv, ohi[off + 1], olo[off + 1]);
    }
}

// ---------------- Elementwise producers --------------------------------------
__global__ void silu_mul_kernel(const float* __restrict__ gate, const float* __restrict__ up,
                                __half* __restrict__ hi, __half* __restrict__ lo) {
    long total = (long)S_TOK * INTER_P;
    for (long i = blockIdx.x * (long)blockDim.x + threadIdx.x; i < total;
         i += (long)gridDim.x * blockDim.x) {
        long row = i / INTER_P;
        int col = (int)(i % INTER_P);
        float v = 0.f;
        if (col < INTER) {
            float g = gate[row * INTER + col];
            float e = fexpf(-g);
            v = __fdividef(g, 1.f + e) * up[row * INTER + col];
        }
        split1(v, hi[i], lo[i]);
    }
}
__global__ void gelu_kernel(const float* __restrict__ x,
                            __half* __restrict__ hi, __half* __restrict__ lo,
                            long n) {
    for (long i = blockIdx.x * (long)blockDim.x + threadIdx.x; i < n;
         i += (long)gridDim.x * blockDim.x) {
        float v = x[i];
        split1(0.5f * v * (1.f + erff(v * 0.70710678118654752f)), hi[i], lo[i]);
    }
}
__global__ void scatter_out_kernel(const float* __restrict__ src, float* __restrict__ dst) {
    for (long i = blockIdx.x * (long)blockDim.x + threadIdx.x;
         i < (long)GROUPS * OUTDIM; i += (long)gridDim.x * blockDim.x) {
        int g = (int)(i / OUTDIM), n = (int)(i % OUTDIM);
        dst[(size_t)g_wingrp[g] * OUTDIM + n] = src[i];
    }
}

// ---------------- Host orchestration -----------------------------------------
#define GEMM_SMEM (2 * STG * (int)sizeof(__half))   // 61440 B

static void run_gemm(const __half* Ahi, const __half* Alo,
                     const __half* Bhi, const __half* Blo,
                     const float* bias, float* C, int M, int N, int K, int add,
                     cudaStream_t st = 0) {
    dim3 grid((N + GBN - 1) / GBN, (M + GBM - 1) / GBM);
    gemm_tc_kernel<<<grid, 256, GEMM_SMEM, st>>>(Ahi, Alo, Bhi, Blo, bias, C, M, N, K, add);
}

extern "C" void kernel_launch(void* const* d_in, const int* in_sizes, int n_in,
                              void* d_out, int out_size) {
    const float* pixel_values = (const float*)d_in[0];
    const float* patch_w = (const float*)d_in[1];
    const float* qkv_w   = (const float*)d_in[2];
    const float* qkv_b   = (const float*)d_in[3];
    const float* proj_w  = (const float*)d_in[4];
    const float* proj_b  = (const float*)d_in[5];
    const float* norm1_w = (const float*)d_in[6];
    const float* norm2_w = (const float*)d_in[7];
    const float* gate_w  = (const float*)d_in[8];
    const float* gate_b  = (const float*)d_in[9];
    const float* up_w    = (const float*)d_in[10];
    const float* up_b    = (const float*)d_in[11];
    const float* down_w  = (const float*)d_in[12];
    const float* down_b  = (const float*)d_in[13];
    const float* ln_q_w  = (const float*)d_in[14];
    const float* m1_w    = (const float*)d_in[15];
    const float* m1_b    = (const float*)d_in[16];
    const float* m2_w    = (const float*)d_in[17];
    const float* m2_b    = (const float*)d_in[18];
    float* out = (float*)d_out;

    __half *whi, *wlo, *hhi, *hlo, *athi, *atlo, *achi, *aclo, *pxhi, *pxlo;
    float *x, *qkv, *gate, *up;
    cudaGetSymbolAddress((void**)&whi, g_whi);
    cudaGetSymbolAddress((void**)&wlo, g_wlo);
    cudaGetSymbolAddress((void**)&hhi, g_hhi);
    cudaGetSymbolAddress((void**)&hlo, g_hlo);
    cudaGetSymbolAddress((void**)&athi, g_athi);
    cudaGetSymbolAddress((void**)&atlo, g_atlo);
    cudaGetSymbolAddress((void**)&achi, g_achi);
    cudaGetSymbolAddress((void**)&aclo, g_aclo);
    cudaGetSymbolAddress((void**)&pxhi, g_pxhi);
    cudaGetSymbolAddress((void**)&pxlo, g_pxlo);
    cudaGetSymbolAddress((void**)&x,    g_x);
    cudaGetSymbolAddress((void**)&qkv,  g_qkv);
    cudaGetSymbolAddress((void**)&gate, g_gate);
    cudaGetSymbolAddress((void**)&up,   g_up);

    static int attr_set = 0;
    static cudaStream_t s2 = 0;
    static cudaEvent_t evFork = 0, evJoin = 0;
    int attn_smem = (3 * 64 * QP + 64 * 65) * (int)sizeof(float);
    if (!attr_set) {
        cudaFuncSetAttribute(attn_kernel, cudaFuncAttributeMaxDynamicSharedMemorySize, attn_smem);
        cudaFuncSetAttribute(gemm_tc_kernel, cudaFuncAttributeMaxDynamicSharedMemorySize, GEMM_SMEM);
        cudaStreamCreateWithFlags(&s2, cudaStreamNonBlocking);
        cudaEventCreateWithFlags(&evFork, cudaEventDisableTiming);
        cudaEventCreateWithFlags(&evJoin, cudaEventDisableTiming);
        attr_set = 1;
    }

    // ---- fork: bulk weight splits on side stream (no deps on early compute) --
    cudaEventRecord(evFork, 0);
    cudaStreamWaitEvent(s2, evFork, 0);
    split_w_kernel<<<512, 256, 0, s2>>>(proj_w,  whi + OFF_PROJ,  wlo + OFF_PROJ,  SZ_PROJ / 4);
    split_w_kernel<<<1024, 256, 0, s2>>>(gate_w, whi + OFF_GATE,  wlo + OFF_GATE,  SZ_GATE / 4);
    split_w_kernel<<<1024, 256, 0, s2>>>(up_w,   whi + OFF_UP,    wlo + OFF_UP,    SZ_UP / 4);
    split_down_kernel<<<1024, 256, 0, s2>>>(down_w, whi + OFF_DOWN, wlo + OFF_DOWN);
    split_w_kernel<<<1024, 256, 0, s2>>>(m1_w,   whi + OFF_M1,    wlo + OFF_M1,    SZ_M1 / 4);
    split_w_kernel<<<1024, 256, 0, s2>>>(m2_w,   whi + OFF_M2,    wlo + OFF_M2,    SZ_M2 / 4);
    cudaEventRecord(evJoin, s2);

    // ---- main stream: immediately-needed work --------------------------------
    split_w_kernel<<<512, 256>>>(patch_w, whi + OFF_PATCH, wlo + OFF_PATCH, SZ_PATCH / 4);
    split_w_kernel<<<1024, 256>>>(qkv_w,  whi + OFF_QKV,   wlo + OFF_QKV,   SZ_QKV / 4);
    init_kernel<<<(S_TOK + 255) / 256, 256>>>();
    gather_pixels<<<512, 256>>>(pixel_values);

    run_gemm(pxhi, pxlo, whi + OFF_PATCH, wlo + OFF_PATCH, nullptr, x, S_TOK, HID, PIXF, 0);

    for (int i = 0; i < DEPTH; i++) {
        long oq = OFF_QKV + (long)i * QKV3 * HID;
        long op = OFF_PROJ + (long)i * HID * HID;
        long og = OFF_GATE + (long)i * INTER * HID;
        long ou = OFF_UP + (long)i * INTER * HID;
        long od = OFF_DOWN + (long)i * HID * INTER_P;
        const float* qb = qkv_b + (size_t)i * QKV3;
        const float* pb = proj_b + (size_t)i * HID;
        const float* n1 = norm1_w + (size_t)i * HID;
        const float* n2 = norm2_w + (size_t)i * HID;
        const float* gb = gate_b + (size_t)i * INTER;
        const float* ub = up_b + (size_t)i * INTER;
        const float* db = down_b + (size_t)i * HID;

        rmsnorm_kernel<<<S_TOK, 256>>>(x, n1, hhi, hlo);
        run_gemm(hhi, hlo, whi + oq, wlo + oq, qb, qkv, S_TOK, QKV3, HID, 0);
        rope_kernel<<<S_TOK, 256>>>();
        int windowed = (i == 3 || i == 7) ? 0 : 1;
        attn_kernel<<<dim3(NTILE64, HEADS), 256, attn_smem>>>(qkv, athi, atlo, windowed);
        if (i == 0) cudaStreamWaitEvent(0, evJoin, 0);   // join before first proj use
        run_gemm(athi, atlo, whi + op, wlo + op, pb, x, S_TOK, HID, HID, 1);

        rmsnorm_kernel<<<S_TOK, 256>>>(x, n2, hhi, hlo);
        run_gemm(hhi, hlo, whi + og, wlo + og, gb, gate, S_TOK, INTER, HID, 0);
        run_gemm(hhi, hlo, whi + ou, wlo + ou, ub, up, S_TOK, INTER, HID, 0);
        silu_mul_kernel<<<1024, 256>>>(gate, up, achi, aclo);
        run_gemm(achi, aclo, whi + od, wlo + od, db, x, S_TOK, HID, INTER_P, 1);
    }

    rmsnorm_kernel<<<S_TOK, 256>>>(x, ln_q_w, hhi, hlo);
    run_gemm(hhi, hlo, whi + OFF_M1, wlo + OFF_M1, m1_b, gate, GROUPS, MERGED, MERGED, 0);
    gelu_kernel<<<512, 256>>>(gate, achi, aclo, (long)GROUPS * MERGED);
    run_gemm(achi, aclo, whi + OFF_M2, wlo + OFF_M2, m2_b, qkv, GROUPS, OUTDIM, MERGED, 0);
    scatter_out_kernel<<<512, 256>>>(qkv, out);
}

// round 13
// speedup vs baseline: 2.4257x; 1.0261x over previous
#include <cuda_runtime.h>
#include <cuda_fp16.h>
#include <math.h>

// ---------------- Problem constants ----------------
#define S_TOK   2304
#define HID     1280
#define HEADS   16
#define HD      80
#define DEPTH   8
#define INTER   3420
#define INTER_P 3424
#define GU_N    6840          // merged gate|up N
#define OUTDIM  3584
#define QKV3    3840
#define GROUPS  576
#define PIXF    1176
#define MERGED  5120
#define NTILE64 36

// ---------------- Weight arena offsets (elements) ---------------------------
#define OFF_PATCH 0L
#define SZ_PATCH  (1280L*1176)
#define OFF_QKV   (OFF_PATCH + SZ_PATCH)
#define SZ_QKV    (8L*3840*1280)
#define OFF_PROJ  (OFF_QKV + SZ_QKV)
#define SZ_PROJ   (8L*1280*1280)
#define OFF_GU    (OFF_PROJ + SZ_PROJ)
#define SZ_GU     (8L*GU_N*1280)
#define OFF_DOWN  (OFF_GU + SZ_GU)
#define SZ_DOWN   (8L*1280*INTER_P)
#define OFF_M1    (OFF_DOWN + SZ_DOWN)
#define SZ_M1     (5120L*5120)
#define OFF_M2    (OFF_M1 + SZ_M1)
#define SZ_M2     (3584L*5120)
#define W_TOTAL   (OFF_M2 + SZ_M2)

// ---------------- Scratch (device globals) ----------------------------------
__device__ __half g_whi[W_TOTAL];
__device__ __half g_wlo[W_TOTAL];
__device__ float g_x[S_TOK * HID];
__device__ float g_qkv[S_TOK * QKV3];
__device__ float g_gu[(long)S_TOK * GU_N];       // merged gate|up; also m2 out
__device__ float g_part[3L * S_TOK * HID];       // split-K partials (8.85M)
__device__ __half g_hhi[S_TOK * HID],  g_hlo[S_TOK * HID];
__device__ __half g_athi[S_TOK * HID], g_atlo[S_TOK * HID];
__device__ __half g_achi[S_TOK * INTER_P], g_aclo[S_TOK * INTER_P];
__device__ __half g_pxhi[S_TOK * PIXF], g_pxlo[S_TOK * PIXF];
__device__ float g_cos[S_TOK * HD];
__device__ float g_sin[S_TOK * HD];
__device__ int   g_orig[S_TOK];
__device__ int   g_wingrp[GROUPS];

// ---------------- helpers ----------------------------------------------------
__device__ __forceinline__ void split1(float v, __half& h, __half& l) {
    h = __float2half_rn(v);
    l = __float2half_rn(v - __half2float(h));
}

__device__ __forceinline__ float fexpf(float x) {
    float t = x * 1.4426950408889634f;
    t = fmaxf(fminf(t, 126.f), -126.f);
    float nf = rintf(t);
    float y = (t - nf) * 0.6931471805599453f;
    float p = 1.3888889e-3f;
    p = fmaf(p, y, 8.3333338e-3f);
    p = fmaf(p, y, 4.1666668e-2f);
    p = fmaf(p, y, 1.6666667e-1f);
    p = fmaf(p, y, 5.0e-1f);
    p = fmaf(p, y, 1.0f);
    p = fmaf(p, y, 1.0f);
    return p * __int_as_float(((int)nf + 127) << 23);
}

__device__ __forceinline__ unsigned long long pk2(float a, float b) {
    unsigned long long r;
    asm("mov.b64 %0, {%1, %2};" : "=l"(r) : "f"(a), "f"(b));
    return r;
}
__device__ __forceinline__ void upk2(unsigned long long v, float& a, float& b) {
    asm("mov.b64 {%0, %1}, %2;" : "=f"(a), "=f"(b) : "l"(v));
}
__device__ __forceinline__ unsigned long long fma2(unsigned long long a,
                                                   unsigned long long b,
                                                   unsigned long long c) {
    unsigned long long d;
    asm("fma.rn.f32x2 %0, %1, %2, %3;" : "=l"(d) : "l"(a), "l"(b), "l"(c));
    return d;
}
__device__ __forceinline__ unsigned long long mul2(unsigned long long a,
                                                   unsigned long long b) {
    unsigned long long d;
    asm("mul.rn.f32x2 %0, %1, %2;" : "=l"(d) : "l"(a), "l"(b));
    return d;
}

// ---------------- Index + rotary precompute ---------------------------------
__global__ void init_kernel() {
    int s = blockIdx.x * blockDim.x + threadIdx.x;
    if (s >= S_TOK) return;
    int g = s >> 2, r = s & 3;
    int hb = g / 96, wb = (g / 16) % 6, hr = (g % 16) / 4, wr = g & 3;
    int og = (hb * 4 + hr) * 24 + (wb * 4 + wr);
    g_orig[s] = og * 4 + r;
    if (r == 0) g_wingrp[g] = og;
    int hg = og / 24, wg = og % 24;
    int hh = hg * 2 + (r >> 1), ww = wg * 2 + (r & 1);
    for (int j = 0; j < 40; j++) {
        float invf = powf(10000.f, -(float)(j % 20) / 20.f);
        float ang = (float)((j < 20) ? hh : ww) * invf;
        float c = cosf(ang), sn = sinf(ang);
        g_cos[s * HD + j] = c;  g_cos[s * HD + 40 + j] = c;
        g_sin[s * HD + j] = sn; g_sin[s * HD + 40 + j] = sn;
    }
}

__global__ void gather_pixels(const float* __restrict__ pix) {
    for (long i = blockIdx.x * (long)blockDim.x + threadIdx.x;
         i < (long)S_TOK * PIXF; i += (long)gridDim.x * blockDim.x) {
        int s = (int)(i / PIXF), c = (int)(i % PIXF);
        split1(pix[(long)g_orig[s] * PIXF + c], g_pxhi[i], g_pxlo[i]);
    }
}

// ---------------- Weight splits ----------------------------------------------
__global__ void split_w_kernel(const float* __restrict__ src,
                               __half* __restrict__ hi,
                               __half* __restrict__ lo, long n4) {
    for (long i = blockIdx.x * (long)blockDim.x + threadIdx.x; i < n4;
         i += (long)gridDim.x * blockDim.x) {
        float4 v = ((const float4*)src)[i];
        __half h0, h1, h2, h3, l0, l1, l2, l3;
        split1(v.x, h0, l0); split1(v.y, h1, l1);
        split1(v.z, h2, l2); split1(v.w, h3, l3);
        ((__half2*)hi)[2*i]   = __halves2half2(h0, h1);
        ((__half2*)hi)[2*i+1] = __halves2half2(h2, h3);
        ((__half2*)lo)[2*i]   = __halves2half2(l0, l1);
        ((__half2*)lo)[2*i+1] = __halves2half2(l2, l3);
    }
}

// merged gate|up split: dst layer stride GU_N*1280, rows 0..3419 gate, rest up
__global__ void split_gu_kernel(const float* __restrict__ gate_w,
                                const float* __restrict__ up_w,
                                __half* __restrict__ hi, __half* __restrict__ lo) {
    long n4 = SZ_GU / 4;
    for (long i = blockIdx.x * (long)blockDim.x + threadIdx.x; i < n4;
         i += (long)gridDim.x * blockDim.x) {
        long row = i / 320;            // 1280/4
        int c4 = (int)(i % 320);
        int l = (int)(row / GU_N);
        int r = (int)(row % GU_N);
        const float* srcrow = (r < INTER)
            ? gate_w + ((size_t)l * INTER + r) * HID
            : up_w   + ((size_t)l * INTER + (r - INTER)) * HID;
        float4 v = ((const float4*)srcrow)[c4];
        __half h0, h1, h2, h3, l0, l1, l2, l3;
        split1(v.x, h0, l0); split1(v.y, h1, l1);
        split1(v.z, h2, l2); split1(v.w, h3, l3);
        ((__half2*)hi)[2*i]   = __halves2half2(h0, h1);
        ((__half2*)hi)[2*i+1] = __halves2half2(h2, h3);
        ((__half2*)lo)[2*i]   = __halves2half2(l0, l1);
        ((__half2*)lo)[2*i+1] = __halves2half2(l2, l3);
    }
}

__global__ void split_down_kernel(const float* __restrict__ src,
                                  __half* __restrict__ hi,
                                  __half* __restrict__ lo) {
    long total = 8L * 1280 * INTER_P;
    for (long i = blockIdx.x * (long)blockDim.x + threadIdx.x; i < total;
         i += (long)gridDim.x * blockDim.x) {
        long row = i / INTER_P;
        int col = (int)(i % INTER_P);
        float v = (col < INTER) ? src[row * INTER + col] : 0.f;
        split1(v, hi[i], lo[i]);
    }
}

// ============ Split-fp16 tensor-core GEMM (split-K capable) ==================
#define GBM 128
#define GBN 64
#define GBK 32
#define SKA 40
#define STG (384 * SKA)

__device__ __forceinline__ void mma_f32(float* c, const unsigned* a, const unsigned* b) {
    asm volatile(
        "mma.sync.aligned.m16n8k16.row.col.f32.f16.f16.f32 "
        "{%0,%1,%2,%3}, {%4,%5,%6,%7}, {%8,%9}, {%0,%1,%2,%3};\n"
        : "+f"(c[0]), "+f"(c[1]), "+f"(c[2]), "+f"(c[3])
        : "r"(a[0]), "r"(a[1]), "r"(a[2]), "r"(a[3]), "r"(b[0]), "r"(b[1]));
}
__device__ __forceinline__ void mma_f16(unsigned* c, const unsigned* a, const unsigned* b) {
    asm volatile(
        "mma.sync.aligned.m16n8k16.row.col.f16.f16.f16.f16 "
        "{%0,%1}, {%2,%3,%4,%5}, {%6,%7}, {%0,%1};\n"
        : "+r"(c[0]), "+r"(c[1])
        : "r"(a[0]), "r"(a[1]), "r"(a[2]), "r"(a[3]), "r"(b[0]), "r"(b[1]));
}
__device__ __forceinline__ void ldsm4(unsigned* r, unsigned saddr) {
    asm volatile("ldmatrix.sync.aligned.m8n8.x4.shared.b16 {%0,%1,%2,%3}, [%4];"
                 : "=r"(r[0]), "=r"(r[1]), "=r"(r[2]), "=r"(r[3]) : "r"(saddr));
}
__device__ __forceinline__ void cpa16(__half* dst, const __half* src, int sz) {
    unsigned d = (unsigned)__cvta_generic_to_shared(dst);
    asm volatile("cp.async.cg.shared.global [%0], [%1], 16, %2;\n"
                 :: "r"(d), "l"(src), "r"(sz));
}

__global__ __launch_bounds__(256, 2)
void gemm_tc_kernel(const __half* __restrict__ Ahi, const __half* __restrict__ Alo,
                    const __half* __restrict__ Bhi, const __half* __restrict__ Blo,
                    const float* __restrict__ bias, float* __restrict__ C,
                    int M, int N, int K, int addFlag, int nsplit) {
    extern __shared__ __half smem[];
    int bm = blockIdx.y * GBM, bn = blockIdx.x * GBN;
    int z = blockIdx.z;
    int tid = threadIdx.x;
    int wid = tid >> 5, lane = tid & 31;
    int wm = (wid & 3) * 32;
    int wn = (wid >> 2) * 32;
    int gid = lane >> 2, qid = lane & 3;

    int a_row = lane & 15;
    int a_coff = (lane >> 4) << 3;
    int b_row = ((lane >> 4) << 3) + (lane & 7);
    int b_coff = ((lane >> 3) & 1) << 3;

    unsigned smem_base = (unsigned)__cvta_generic_to_shared(smem);

    float acc[2][4][4];
    unsigned acc16[2][4][2];
#pragma unroll
    for (int mi = 0; mi < 2; mi++)
#pragma unroll
        for (int ni = 0; ni < 4; ni++) {
#pragma unroll
            for (int r = 0; r < 4; r++) acc[mi][ni][r] = 0.f;
            acc16[mi][ni][0] = 0u; acc16[mi][ni][1] = 0u;
        }

    int ktiles = (K + GBK - 1) / GBK;
    int per = (ktiles + nsplit - 1) / nsplit;
    int tB = z * per;
    int tE = min(ktiles, tB + per);
    if (nsplit > 1) C += (size_t)z * M * N;

    auto load_tile = [&](int kt, int st) {
        int k0 = kt * GBK;
        __half* base = smem + st * STG;
#pragma unroll
        for (int j = 0; j < 6; j++) {
            int idx = tid + j * 256;
            const __half* src; __half* dst;
            int row, seg, rbase, lim;
            if (idx < 1024) {
                int t = idx & 511; row = t >> 2; seg = t & 3;
                src = (idx < 512) ? Ahi : Alo;
                dst = base + ((idx < 512) ? 0 : 128 * SKA);
                rbase = bm; lim = M;
            } else {
                int u = idx - 1024; int t = u & 255; row = t >> 2; seg = t & 3;
                src = (u < 256) ? Bhi : Blo;
                dst = base + 256 * SKA + ((u < 256) ? 0 : 64 * SKA);
                rbase = bn; lim = N;
            }
            int kk = k0 + seg * 8;
            int rem = K - kk;
            int ksz = rem >= 8 ? 16 : (rem >= 4 ? 8 : 0);
            int gr = rbase + row;
            int sz = (gr < lim) ? ksz : 0;
            size_t off = sz ? ((size_t)gr * K + kk) : 0;
            cpa16(dst + row * SKA + seg * 8, src + off, sz);
        }
        asm volatile("cp.async.commit_group;\n" ::);
    };

    load_tile(tB, 0);

    for (int t = tB; t < tE; t++) {
        asm volatile("cp.async.wait_group 0;\n" ::);
        __syncthreads();
        if (t + 1 < tE) load_tile(t + 1, (t + 1) & 1);

        unsigned stg = smem_base + (t & 1) * STG * 2;
        unsigned sAh = stg;
        unsigned sAl = stg + 128 * SKA * 2;
        unsigned sBh = stg + 256 * SKA * 2;
        unsigned sBl = stg + 320 * SKA * 2;

#pragma unroll
        for (int ks = 0; ks < GBK; ks += 16) {
            unsigned ah[2][4], al[2][4], bh[4][2], bl[4][2];
#pragma unroll
            for (int mi = 0; mi < 2; mi++) {
                unsigned off = (unsigned)(((wm + mi * 16 + a_row) * SKA
                                          + ks + a_coff) * 2);
                ldsm4(ah[mi], sAh + off);
                ldsm4(al[mi], sAl + off);
            }
#pragma unroll
            for (int np = 0; np < 2; np++) {
                unsigned off = (unsigned)(((wn + np * 16 + b_row) * SKA
                                          + ks + b_coff) * 2);
                unsigned rh[4], rl[4];
                ldsm4(rh, sBh + off);
                ldsm4(rl, sBl + off);
                bh[np * 2][0] = rh[0];     bh[np * 2][1] = rh[1];
                bh[np * 2 + 1][0] = rh[2]; bh[np * 2 + 1][1] = rh[3];
                bl[np * 2][0] = rl[0];     bl[np * 2][1] = rl[1];
                bl[np * 2 + 1][0] = rl[2]; bl[np * 2 + 1][1] = rl[3];
            }
#pragma unroll
            for (int mi = 0; mi < 2; mi++)
#pragma unroll
                for (int ni = 0; ni < 4; ni++) {
                    mma_f32(acc[mi][ni], ah[mi], bh[ni]);
                    mma_f16(acc16[mi][ni], al[mi], bh[ni]);
                    mma_f16(acc16[mi][ni], ah[mi], bl[ni]);
                }
        }
        __syncthreads();
    }

#pragma unroll
    for (int mi = 0; mi < 2; mi++) {
#pragma unroll
        for (int rr = 0; rr < 2; rr++) {
            int m = bm + wm + mi * 16 + gid + rr * 8;
            if (m >= M) continue;
#pragma unroll
            for (int ni = 0; ni < 4; ni++) {
                int n = bn + wn + ni * 8 + qid * 2;
                if (n >= N) continue;
                float2 corr = __half22float2(
                    *reinterpret_cast<__half2*>(&acc16[mi][ni][rr]));
                float v0 = acc[mi][ni][rr * 2]     + corr.x + (bias ? bias[n] : 0.f);
                float v1 = acc[mi][ni][rr * 2 + 1] + corr.y + (bias ? bias[n + 1] : 0.f);
                float* p = C + (size_t)m * N + n;
                if (addFlag) { p[0] += v0; p[1] += v1; }
                else { *(float2*)p = make_float2(v0, v1); }
            }
        }
    }
}

// ---------------- split-K reduces --------------------------------------------
__global__ void reduce3_add_kernel(float* __restrict__ x, const float* __restrict__ P,
                                   const float* __restrict__ bias) {
    const long sz = (long)S_TOK * HID;
    for (long i = blockIdx.x * (long)blockDim.x + threadIdx.x; i < sz;
         i += (long)gridDim.x * blockDim.x) {
        int col = (int)(i % HID);
        x[i] += P[i] + P[i + sz] + P[i + 2 * sz] + bias[col];
    }
}
__global__ void reduce2_gelu_kernel(const float* __restrict__ P, const float* __restrict__ bias,
                                    __half* __restrict__ hi, __half* __restrict__ lo) {
    const long sz = (long)GROUPS * MERGED;
    for (long i = blockIdx.x * (long)blockDim.x + threadIdx.x; i < sz;
         i += (long)gridDim.x * blockDim.x) {
        int col = (int)(i % MERGED);
        float v = P[i] + P[i + sz] + bias[col];
        v = 0.5f * v * (1.f + erff(v * 0.70710678118654752f));
        split1(v, hi[i], lo[i]);
    }
}

// ---------------- RMSNorm -> fp16 hi/lo --------------------------------------
__global__ void rmsnorm_kernel(const float* __restrict__ x, const float* __restrict__ w,
                               __half* __restrict__ hi, __half* __restrict__ lo) {
    int s = blockIdx.x;
    const float* xr = x + (size_t)s * HID;
    float ss = 0.f;
    for (int i = threadIdx.x; i < HID; i += 256) { float v = xr[i]; ss += v * v; }
#pragma unroll
    for (int o = 16; o; o >>= 1) ss += __shfl_xor_sync(0xffffffffu, ss, o);
    __shared__ float red[8];
    if ((threadIdx.x & 31) == 0) red[threadIdx.x >> 5] = ss;
    __syncthreads();
    if (threadIdx.x < 8) {
        float v = red[threadIdx.x];
#pragma unroll
        for (int o = 4; o; o >>= 1) v += __shfl_xor_sync(0xffu, v, o);
        if (threadIdx.x == 0) red[0] = v;
    }
    __syncthreads();
    float scale = rsqrtf(red[0] * (1.f / HID) + 1e-6f);
    for (int i = threadIdx.x; i < HID; i += 256)
        split1(xr[i] * scale * w[i], hi[(size_t)s * HID + i], lo[(size_t)s * HID + i]);
}

// ---------------- RoPE on q,k inside g_qkv ----------------------------------
__global__ void rope_kernel() {
    int s = blockIdx.x;
    size_t base = (size_t)s * QKV3;
    for (int p = threadIdx.x; p < 2 * HEADS * 40; p += 256) {
        int part = p / (HEADS * 40);
        int rem = p % (HEADS * 40);
        int head = rem / 40, d = rem % 40;
        size_t off = base + part * HID + head * HD + d;
        float c = g_cos[s * HD + d], sn = g_sin[s * HD + d];
        float v0 = g_qkv[off], v1 = g_qkv[off + 40];
        g_qkv[off]      = v0 * c - v1 * sn;
        g_qkv[off + 40] = v1 * c + v0 * sn;
    }
}

// ---------------- Attention ---------------------------------------------------
#define QP 84
__global__ void attn_kernel(const float* __restrict__ qkv,
                            __half* __restrict__ ohi, __half* __restrict__ olo,
                            int windowed) {
    extern __shared__ float sm[];
    float* Qs = sm;
    float* Ks = Qs + 64 * QP;
    float* Vs = Ks + 64 * QP;
    float* Ss = Vs + 64 * QP;
    int qt = blockIdx.x, head = blockIdx.y;
    int tid = threadIdx.x;
    int row = tid >> 2, l4 = tid & 3;

    for (int i = tid; i < 64 * HD; i += 256) {
        int r = i / HD, d = i % HD;
        Qs[r * QP + d] = qkv[(size_t)(qt * 64 + r) * QKV3 + head * HD + d];
    }
    float M = -1e30f, L = 0.f;
    unsigned long long O2[10];
#pragma unroll
    for (int i = 0; i < 10; i++) O2[i] = 0ull;

    int t0 = windowed ? qt : 0;
    int t1 = windowed ? qt + 1 : NTILE64;
    for (int t = t0; t < t1; t++) {
        __syncthreads();
        for (int i = tid; i < 64 * HD; i += 256) {
            int r = i / HD, d = i % HD;
            size_t base = (size_t)(t * 64 + r) * QKV3 + head * HD + d;
            Ks[r * QP + d] = qkv[base + HID];
            Vs[r * QP + d] = qkv[base + 2 * HID];
        }
        __syncthreads();

        unsigned long long acc2[16];
#pragma unroll
        for (int j = 0; j < 16; j++) acc2[j] = 0ull;
        const unsigned long long* qrow = (const unsigned long long*)(Qs + row * QP);
        for (int d2 = 0; d2 < HD / 2; d2++) {
            unsigned long long q2 = qrow[d2];
#pragma unroll
            for (int j = 0; j < 16; j++) {
                unsigned long long k2 =
                    *(const unsigned long long*)(Ks + (l4 * 16 + j) * QP + d2 * 2);
                acc2[j] = fma2(q2, k2, acc2[j]);
            }
        }
        float dots[16];
        float tmax = -1e30f;
#pragma unroll
        for (int j = 0; j < 16; j++) {
            float a, b; upk2(acc2[j], a, b);
            dots[j] = (a + b) * 0.11180339887498949f;
            tmax = fmaxf(tmax, dots[j]);
        }
        tmax = fmaxf(tmax, __shfl_xor_sync(0xffffffffu, tmax, 1));
        tmax = fmaxf(tmax, __shfl_xor_sync(0xffffffffu, tmax, 2));
        float Mnew = fmaxf(M, tmax);
        float alpha = fexpf(M - Mnew);
        float lsum = 0.f;
#pragma unroll
        for (int j = 0; j < 16; j++) {
            float p = fexpf(dots[j] - Mnew);
            Ss[row * 65 + l4 * 16 + j] = p;
            lsum += p;
        }
        lsum += __shfl_xor_sync(0xffffffffu, lsum, 1);
        lsum += __shfl_xor_sync(0xffffffffu, lsum, 2);
        L = L * alpha + lsum;
        M = Mnew;
        unsigned long long al2 = pk2(alpha, alpha);
#pragma unroll
        for (int i = 0; i < 10; i++) O2[i] = mul2(O2[i], al2);
        __syncwarp();
        for (int key = 0; key < 64; key++) {
            float p = Ss[row * 65 + key];
            unsigned long long pp = pk2(p, p);
            const unsigned long long* vrow =
                (const unsigned long long*)(Vs + key * QP + l4 * 20);
#pragma unroll
            for (int i = 0; i < 10; i++) O2[i] = fma2(pp, vrow[i], O2[i]);
        }
    }
    float inv = 1.f / L;
    int token = qt * 64 + row;
#pragma unroll
    for (int i = 0; i < 10; i++) {
        float a, b; upk2(O2[i], a, b);
        size_t off = (size_t)token * HID + head * HD + l4 * 20 + 2 * i;
        split1(a * inv, ohi[off], olo[off]);
        split1(b * inv, ohi[off + 1], olo[off + 1]);
    }
}

// ---------------- silu(gate+gb)*(up+ub) from merged gu buffer ----------------
__global__ void silu_mul_kernel(const float* __restrict__ gu,
                                const float* __restrict__ gb, const float* __restrict__ ub,
                                __half* __restrict__ hi, __half* __restrict__ lo) {
    long total = (long)S_TOK * INTER_P;
    for (long i = blockIdx.x * (long)blockDim.x + threadIdx.x; i < total;
         i += (long)gridDim.x * blockDim.x) {
        long row = i / INTER_P;
        int col = (int)(i % INTER_P);
        float v = 0.f;
        if (col < INTER) {
            float g = gu[row * GU_N + col] + gb[col];
            float u = gu[row * GU_N + INTER + col] + ub[col];
            float e = fexpf(-g);
            v = __fdividef(g, 1.f + e) * u;
        }
        split1(v, hi[i], lo[i]);
    }
}
__global__ void scatter_out_kernel(const float* __restrict__ src, float* __restrict__ dst) {
    for (long i = blockIdx.x * (long)blockDim.x + threadIdx.x;
         i < (long)GROUPS * OUTDIM; i += (long)gridDim.x * blockDim.x) {
        int g = (int)(i / OUTDIM), n = (int)(i % OUTDIM);
        dst[(size_t)g_wingrp[g] * OUTDIM + n] = src[i];
    }
}

// ---------------- Host orchestration -----------------------------------------
#define GEMM_SMEM (2 * STG * (int)sizeof(__half))

static void run_gemm(const __half* Ahi, const __half* Alo,
                     const __half* Bhi, const __half* Blo,
                     const float* bias, float* C, int M, int N, int K, int add,
                     int nsplit = 1) {
    dim3 grid((N + GBN - 1) / GBN, (M + GBM - 1) / GBM, nsplit);
    gemm_tc_kernel<<<grid, 256, GEMM_SMEM>>>(Ahi, Alo, Bhi, Blo, bias, C, M, N, K, add, nsplit);
}

extern "C" void kernel_launch(void* const* d_in, const int* in_sizes, int n_in,
                              void* d_out, int out_size) {
    const float* pixel_values = (const float*)d_in[0];
    const float* patch_w = (const float*)d_in[1];
    const float* qkv_w   = (const float*)d_in[2];
    const float* qkv_b   = (const float*)d_in[3];
    const float* proj_w  = (const float*)d_in[4];
    const float* proj_b  = (const float*)d_in[5];
    const float* norm1_w = (const float*)d_in[6];
    const float* norm2_w = (const float*)d_in[7];
    const float* gate_w  = (const float*)d_in[8];
    const float* gate_b  = (const float*)d_in[9];
    const float* up_w    = (const float*)d_in[10];
    const float* up_b    = (const float*)d_in[11];
    const float* down_w  = (const float*)d_in[12];
    const float* down_b  = (const float*)d_in[13];
    const float* ln_q_w  = (const float*)d_in[14];
    const float* m1_w    = (const float*)d_in[15];
    const float* m1_b    = (const float*)d_in[16];
    const float* m2_w    = (const float*)d_in[17];
    const float* m2_b    = (const float*)d_in[18];
    float* out = (float*)d_out;

    __half *whi, *wlo, *hhi, *hlo, *athi, *atlo, *achi, *aclo, *pxhi, *pxlo;
    float *x, *qkv, *gu, *part;
    cudaGetSymbolAddress((void**)&whi, g_whi);
    cudaGetSymbolAddress((void**)&wlo, g_wlo);
    cudaGetSymbolAddress((void**)&hhi, g_hhi);
    cudaGetSymbolAddress((void**)&hlo, g_hlo);
    cudaGetSymbolAddress((void**)&athi, g_athi);
    cudaGetSymbolAddress((void**)&atlo, g_atlo);
    cudaGetSymbolAddress((void**)&achi, g_achi);
    cudaGetSymbolAddress((void**)&aclo, g_aclo);
    cudaGetSymbolAddress((void**)&pxhi, g_pxhi);
    cudaGetSymbolAddress((void**)&pxlo, g_pxlo);
    cudaGetSymbolAddress((void**)&x,    g_x);
    cudaGetSymbolAddress((void**)&qkv,  g_qkv);
    cudaGetSymbolAddress((void**)&gu,   g_gu);
    cudaGetSymbolAddress((void**)&part, g_part);

    static int attr_set = 0;
    static cudaStream_t s2 = 0;
    static cudaEvent_t evFork = 0, evJoin = 0;
    int attn_smem = (3 * 64 * QP + 64 * 65) * (int)sizeof(float);
    if (!attr_set) {
        cudaFuncSetAttribute(attn_kernel, cudaFuncAttributeMaxDynamicSharedMemorySize, attn_smem);
        cudaFuncSetAttribute(gemm_tc_kernel, cudaFuncAttributeMaxDynamicSharedMemorySize, GEMM_SMEM);
        cudaStreamCreateWithFlags(&s2, cudaStreamNonBlocking);
        cudaEventCreateWithFlags(&evFork, cudaEventDisableTiming);
        cudaEventCreateWithFlags(&evJoin, cudaEventDisableTiming);
        attr_set = 1;
    }

    // ---- fork: bulk weight splits on side stream ----
    cudaEventRecord(evFork, 0);
    cudaStreamWaitEvent(s2, evFork, 0);
    split_w_kernel<<<512, 256, 0, s2>>>(proj_w,  whi + OFF_PROJ,  wlo + OFF_PROJ,  SZ_PROJ / 4);
    split_gu_kernel<<<1024, 256, 0, s2>>>(gate_w, up_w, whi + OFF_GU, wlo + OFF_GU);
    split_down_kernel<<<1024, 256, 0, s2>>>(down_w, whi + OFF_DOWN, wlo + OFF_DOWN);
    split_w_kernel<<<1024, 256, 0, s2>>>(m1_w,   whi + OFF_M1,    wlo + OFF_M1,    SZ_M1 / 4);
    split_w_kernel<<<1024, 256, 0, s2>>>(m2_w,   whi + OFF_M2,    wlo + OFF_M2,    SZ_M2 / 4);
    cudaEventRecord(evJoin, s2);

    // ---- main stream ----
    split_w_kernel<<<512, 256>>>(patch_w, whi + OFF_PATCH, wlo + OFF_PATCH, SZ_PATCH / 4);
    split_w_kernel<<<1024, 256>>>(qkv_w,  whi + OFF_QKV,   wlo + OFF_QKV,   SZ_QKV / 4);
    init_kernel<<<(S_TOK + 255) / 256, 256>>>();
    gather_pixels<<<512, 256>>>(pixel_values);

    run_gemm(pxhi, pxlo, whi + OFF_PATCH, wlo + OFF_PATCH, nullptr, x, S_TOK, HID, PIXF, 0);

    for (int i = 0; i < DEPTH; i++) {
        long oq = OFF_QKV + (long)i * QKV3 * HID;
        long op = OFF_PROJ + (long)i * HID * HID;
        long og = OFF_GU + (long)i * GU_N * HID;
        long od = OFF_DOWN + (long)i * HID * INTER_P;
        const float* qb = qkv_b + (size_t)i * QKV3;
        const float* pb = proj_b + (size_t)i * HID;
        const float* n1 = norm1_w + (size_t)i * HID;
        const float* n2 = norm2_w + (size_t)i * HID;
        const float* gb = gate_b + (size_t)i * INTER;
        const float* ub = up_b + (size_t)i * INTER;
        const float* db = down_b + (size_t)i * HID;

        rmsnorm_kernel<<<S_TOK, 256>>>(x, n1, hhi, hlo);
        run_gemm(hhi, hlo, whi + oq, wlo + oq, qb, qkv, S_TOK, QKV3, HID, 0);
        rope_kernel<<<S_TOK, 256>>>();
        int windowed = (i == 3 || i == 7) ? 0 : 1;
        attn_kernel<<<dim3(NTILE64, HEADS), 256, attn_smem>>>(qkv, athi, atlo, windowed);
        if (i == 0) cudaStreamWaitEvent(0, evJoin, 0);
        // proj: split-K=3 into partials, then fused residual-add reduce
        run_gemm(athi, atlo, whi + op, wlo + op, nullptr, part, S_TOK, HID, HID, 0, 3);
        reduce3_add_kernel<<<512, 256>>>(x, part, pb);

        rmsnorm_kernel<<<S_TOK, 256>>>(x, n2, hhi, hlo);
        // merged gate|up GEMM (biases applied in silu)
        run_gemm(hhi, hlo, whi + og, wlo + og, nullptr, gu, S_TOK, GU_N, HID, 0);
        silu_mul_kernel<<<1024, 256>>>(gu, gb, ub, achi, aclo);
        // down: split-K=3 into partials, then fused residual-add reduce
        run_gemm(achi, aclo, whi + od, wlo + od, nullptr, part, S_TOK, HID, INTER_P, 0, 3);
        reduce3_add_kernel<<<512, 256>>>(x, part, db);
    }

    rmsnorm_kernel<<<S_TOK, 256>>>(x, ln_q_w, hhi, hlo);
    // m1: split-K=2, reduce fused with gelu + split
    run_gemm(hhi, hlo, whi + OFF_M1, wlo + OFF_M1, nullptr, part, GROUPS, MERGED, MERGED, 0, 2);
    reduce2_gelu_kernel<<<512, 256>>>(part, m1_b, achi, aclo);
    run_gemm(achi, aclo, whi + OFF_M2, wlo + OFF_M2, m2_b, gu, GROUPS, OUTDIM, MERGED, 0);
    scatter_out_kernel<<<512, 256>>>(gu, out);
}

// round 15
// speedup vs baseline: 2.4569x; 1.0129x over previous
#include <cuda_runtime.h>
#include <cuda_fp16.h>
#include <math.h>

// ---------------- Problem constants ----------------
#define S_TOK   2304
#define HID     1280
#define HEADS   16
#define HD      80
#define DEPTH   8
#define INTER   3420
#define INTER_P 3424
#define GU_N    6840
#define OUTDIM  3584
#define QKV3    3840
#define GROUPS  576
#define PIXF    1176
#define MERGED  5120
#define NTILE64 36

// ---------------- Weight arena offsets (elements) ---------------------------
#define OFF_PATCH 0L
#define SZ_PATCH  (1280L*1176)
#define OFF_QKV   (OFF_PATCH + SZ_PATCH)
#define SZ_QKV    (8L*3840*1280)
#define OFF_PROJ  (OFF_QKV + SZ_QKV)
#define SZ_PROJ   (8L*1280*1280)
#define OFF_GU    (OFF_PROJ + SZ_PROJ)
#define SZ_GU     (8L*GU_N*1280)
#define OFF_DOWN  (OFF_GU + SZ_GU)
#define SZ_DOWN   (8L*1280*INTER_P)
#define OFF_M1    (OFF_DOWN + SZ_DOWN)
#define SZ_M1     (5120L*5120)
#define OFF_M2    (OFF_M1 + SZ_M1)
#define SZ_M2     (3584L*5120)
#define W_TOTAL   (OFF_M2 + SZ_M2)

// ---------------- Scratch (device globals) ----------------------------------
__device__ __half g_whi[W_TOTAL];
__device__ __half g_wlo[W_TOTAL];
__device__ float g_x[S_TOK * HID];
__device__ float g_qkv[S_TOK * QKV3];
__device__ float g_gu[(long)S_TOK * GU_N];
__device__ float g_part[3L * S_TOK * HID];
__device__ __half g_hhi[S_TOK * HID],  g_hlo[S_TOK * HID];
__device__ __half g_athi[S_TOK * HID], g_atlo[S_TOK * HID];
__device__ __half g_achi[S_TOK * INTER_P], g_aclo[S_TOK * INTER_P];
__device__ __half g_pxhi[S_TOK * PIXF], g_pxlo[S_TOK * PIXF];
__device__ float g_cos[S_TOK * HD];
__device__ float g_sin[S_TOK * HD];
__device__ int   g_orig[S_TOK];
__device__ int   g_wingrp[GROUPS];

// ---------------- helpers ----------------------------------------------------
__device__ __forceinline__ void split1(float v, __half& h, __half& l) {
    h = __float2half_rn(v);
    l = __float2half_rn(v - __half2float(h));
}

__device__ __forceinline__ float fexpf(float x) {
    float t = x * 1.4426950408889634f;
    t = fmaxf(fminf(t, 126.f), -126.f);
    float nf = rintf(t);
    float y = (t - nf) * 0.6931471805599453f;
    float p = 1.3888889e-3f;
    p = fmaf(p, y, 8.3333338e-3f);
    p = fmaf(p, y, 4.1666668e-2f);
    p = fmaf(p, y, 1.6666667e-1f);
    p = fmaf(p, y, 5.0e-1f);
    p = fmaf(p, y, 1.0f);
    p = fmaf(p, y, 1.0f);
    return p * __int_as_float(((int)nf + 127) << 23);
}

__device__ __forceinline__ unsigned long long pk2(float a, float b) {
    unsigned long long r;
    asm("mov.b64 %0, {%1, %2};" : "=l"(r) : "f"(a), "f"(b));
    return r;
}
__device__ __forceinline__ void upk2(unsigned long long v, float& a, float& b) {
    asm("mov.b64 {%0, %1}, %2;" : "=f"(a), "=f"(b) : "l"(v));
}
__device__ __forceinline__ unsigned long long fma2(unsigned long long a,
                                                   unsigned long long b,
                                                   unsigned long long c) {
    unsigned long long d;
    asm("fma.rn.f32x2 %0, %1, %2, %3;" : "=l"(d) : "l"(a), "l"(b), "l"(c));
    return d;
}
__device__ __forceinline__ unsigned long long mul2(unsigned long long a,
                                                   unsigned long long b) {
    unsigned long long d;
    asm("mul.rn.f32x2 %0, %1, %2;" : "=l"(d) : "l"(a), "l"(b));
    return d;
}

// ---------------- Index + rotary precompute ---------------------------------
__global__ void init_kernel() {
    int s = blockIdx.x * blockDim.x + threadIdx.x;
    if (s >= S_TOK) return;
    int g = s >> 2, r = s & 3;
    int hb = g / 96, wb = (g / 16) % 6, hr = (g % 16) / 4, wr = g & 3;
    int og = (hb * 4 + hr) * 24 + (wb * 4 + wr);
    g_orig[s] = og * 4 + r;
    if (r == 0) g_wingrp[g] = og;
    int hg = og / 24, wg = og % 24;
    int hh = hg * 2 + (r >> 1), ww = wg * 2 + (r & 1);
    for (int j = 0; j < 40; j++) {
        float invf = powf(10000.f, -(float)(j % 20) / 20.f);
        float ang = (float)((j < 20) ? hh : ww) * invf;
        float c = cosf(ang), sn = sinf(ang);
        g_cos[s * HD + j] = c;  g_cos[s * HD + 40 + j] = c;
        g_sin[s * HD + j] = sn; g_sin[s * HD + 40 + j] = sn;
    }
}

__global__ void gather_pixels(const float* __restrict__ pix) {
    for (long i = blockIdx.x * (long)blockDim.x + threadIdx.x;
         i < (long)S_TOK * PIXF; i += (long)gridDim.x * blockDim.x) {
        int s = (int)(i / PIXF), c = (int)(i % PIXF);
        split1(pix[(long)g_orig[s] * PIXF + c], g_pxhi[i], g_pxlo[i]);
    }
}

// ---------------- Weight splits ----------------------------------------------
__global__ void split_w_kernel(const float* __restrict__ src,
                               __half* __restrict__ hi,
                               __half* __restrict__ lo, long n4) {
    for (long i = blockIdx.x * (long)blockDim.x + threadIdx.x; i < n4;
         i += (long)gridDim.x * blockDim.x) {
        float4 v = ((const float4*)src)[i];
        __half h0, h1, h2, h3, l0, l1, l2, l3;
        split1(v.x, h0, l0); split1(v.y, h1, l1);
        split1(v.z, h2, l2); split1(v.w, h3, l3);
        ((__half2*)hi)[2*i]   = __halves2half2(h0, h1);
        ((__half2*)hi)[2*i+1] = __halves2half2(h2, h3);
        ((__half2*)lo)[2*i]   = __halves2half2(l0, l1);
        ((__half2*)lo)[2*i+1] = __halves2half2(l2, l3);
    }
}

__global__ void split_gu_kernel(const float* __restrict__ gate_w,
                                const float* __restrict__ up_w,
                                __half* __restrict__ hi, __half* __restrict__ lo) {
    long n4 = SZ_GU / 4;
    for (long i = blockIdx.x * (long)blockDim.x + threadIdx.x; i < n4;
         i += (long)gridDim.x * blockDim.x) {
        long row = i / 320;
        int c4 = (int)(i % 320);
        int l = (int)(row / GU_N);
        int r = (int)(row % GU_N);
        const float* srcrow = (r < INTER)
            ? gate_w + ((size_t)l * INTER + r) * HID
            : up_w   + ((size_t)l * INTER + (r - INTER)) * HID;
        float4 v = ((const float4*)srcrow)[c4];
        __half h0, h1, h2, h3, l0, l1, l2, l3;
        split1(v.x, h0, l0); split1(v.y, h1, l1);
        split1(v.z, h2, l2); split1(v.w, h3, l3);
        ((__half2*)hi)[2*i]   = __halves2half2(h0, h1);
        ((__half2*)hi)[2*i+1] = __halves2half2(h2, h3);
        ((__half2*)lo)[2*i]   = __halves2half2(l0, l1);
        ((__half2*)lo)[2*i+1] = __halves2half2(l2, l3);
    }
}

__global__ void split_down_kernel(const float* __restrict__ src,
                                  __half* __restrict__ hi,
                                  __half* __restrict__ lo) {
    long total = 8L * 1280 * INTER_P;
    for (long i = blockIdx.x * (long)blockDim.x + threadIdx.x; i < total;
         i += (long)gridDim.x * blockDim.x) {
        long row = i / INTER_P;
        int col = (int)(i % INTER_P);
        float v = (col < INTER) ? src[row * INTER + col] : 0.f;
        split1(v, hi[i], lo[i]);
    }
}

// ============ Split-fp16 tensor-core GEMM (split-K capable) ==================
#define GBM 128
#define GBN 64
#define GBK 32
#define SKA 40
#define STG (384 * SKA)

__device__ __forceinline__ void mma_f32(float* c, const unsigned* a, const unsigned* b) {
    asm volatile(
        "mma.sync.aligned.m16n8k16.row.col.f32.f16.f16.f32 "
        "{%0,%1,%2,%3}, {%4,%5,%6,%7}, {%8,%9}, {%0,%1,%2,%3};\n"
        : "+f"(c[0]), "+f"(c[1]), "+f"(c[2]), "+f"(c[3])
        : "r"(a[0]), "r"(a[1]), "r"(a[2]), "r"(a[3]), "r"(b[0]), "r"(b[1]));
}
__device__ __forceinline__ void mma_f16(unsigned* c, const unsigned* a, const unsigned* b) {
    asm volatile(
        "mma.sync.aligned.m16n8k16.row.col.f16.f16.f16.f16 "
        "{%0,%1}, {%2,%3,%4,%5}, {%6,%7}, {%0,%1};\n"
        : "+r"(c[0]), "+r"(c[1])
        : "r"(a[0]), "r"(a[1]), "r"(a[2]), "r"(a[3]), "r"(b[0]), "r"(b[1]));
}
__device__ __forceinline__ void ldsm4(unsigned* r, unsigned saddr) {
    asm volatile("ldmatrix.sync.aligned.m8n8.x4.shared.b16 {%0,%1,%2,%3}, [%4];"
                 : "=r"(r[0]), "=r"(r[1]), "=r"(r[2]), "=r"(r[3]) : "r"(saddr));
}
__device__ __forceinline__ void cpa16(__half* dst, const __half* src, int sz) {
    unsigned d = (unsigned)__cvta_generic_to_shared(dst);
    asm volatile("cp.async.cg.shared.global [%0], [%1], 16, %2;\n"
                 :: "r"(d), "l"(src), "r"(sz));
}

__global__ __launch_bounds__(256, 2)
void gemm_tc_kernel(const __half* __restrict__ Ahi, const __half* __restrict__ Alo,
                    const __half* __restrict__ Bhi, const __half* __restrict__ Blo,
                    const float* __restrict__ bias, float* __restrict__ C,
                    int M, int N, int K, int addFlag, int nsplit) {
    extern __shared__ __half smem[];
    int bm = blockIdx.y * GBM, bn = blockIdx.x * GBN;
    int z = blockIdx.z;
    int tid = threadIdx.x;
    int wid = tid >> 5, lane = tid & 31;
    int wm = (wid & 3) * 32;
    int wn = (wid >> 2) * 32;
    int gid = lane >> 2, qid = lane & 3;

    int a_row = lane & 15;
    int a_coff = (lane >> 4) << 3;
    int b_row = ((lane >> 4) << 3) + (lane & 7);
    int b_coff = ((lane >> 3) & 1) << 3;

    unsigned smem_base = (unsigned)__cvta_generic_to_shared(smem);

    float acc[2][4][4];
    unsigned acc16[2][4][2];
#pragma unroll
    for (int mi = 0; mi < 2; mi++)
#pragma unroll
        for (int ni = 0; ni < 4; ni++) {
#pragma unroll
            for (int r = 0; r < 4; r++) acc[mi][ni][r] = 0.f;
            acc16[mi][ni][0] = 0u; acc16[mi][ni][1] = 0u;
        }

    int ktiles = (K + GBK - 1) / GBK;
    int per = (ktiles + nsplit - 1) / nsplit;
    int tB = z * per;
    int tE = min(ktiles, tB + per);
    if (nsplit > 1) C += (size_t)z * M * N;

    auto load_tile = [&](int kt, int st) {
        int k0 = kt * GBK;
        __half* base = smem + st * STG;
#pragma unroll
        for (int j = 0; j < 6; j++) {
            int idx = tid + j * 256;
            const __half* src; __half* dst;
            int row, seg, rbase, lim;
            if (idx < 1024) {
                int t = idx & 511; row = t >> 2; seg = t & 3;
                src = (idx < 512) ? Ahi : Alo;
                dst = base + ((idx < 512) ? 0 : 128 * SKA);
                rbase = bm; lim = M;
            } else {
                int u = idx - 1024; int t = u & 255; row = t >> 2; seg = t & 3;
                src = (u < 256) ? Bhi : Blo;
                dst = base + 256 * SKA + ((u < 256) ? 0 : 64 * SKA);
                rbase = bn; lim = N;
            }
            int kk = k0 + seg * 8;
            int rem = K - kk;
            int ksz = rem >= 8 ? 16 : (rem >= 4 ? 8 : 0);
            int gr = rbase + row;
            int sz = (gr < lim) ? ksz : 0;
            size_t off = sz ? ((size_t)gr * K + kk) : 0;
            cpa16(dst + row * SKA + seg * 8, src + off, sz);
        }
        asm volatile("cp.async.commit_group;\n" ::);
    };

    load_tile(tB, 0);

    for (int t = tB; t < tE; t++) {
        asm volatile("cp.async.wait_group 0;\n" ::);
        __syncthreads();
        if (t + 1 < tE) load_tile(t + 1, (t + 1) & 1);

        unsigned stg = smem_base + (t & 1) * STG * 2;
        unsigned sAh = stg;
        unsigned sAl = stg + 128 * SKA * 2;
        unsigned sBh = stg + 256 * SKA * 2;
        unsigned sBl = stg + 320 * SKA * 2;

#pragma unroll
        for (int ks = 0; ks < GBK; ks += 16) {
            unsigned ah[2][4], al[2][4], bh[4][2], bl[4][2];
#pragma unroll
            for (int mi = 0; mi < 2; mi++) {
                unsigned off = (unsigned)(((wm + mi * 16 + a_row) * SKA
                                          + ks + a_coff) * 2);
                ldsm4(ah[mi], sAh + off);
                ldsm4(al[mi], sAl + off);
            }
#pragma unroll
            for (int np = 0; np < 2; np++) {
                unsigned off = (unsigned)(((wn + np * 16 + b_row) * SKA
                                          + ks + b_coff) * 2);
                unsigned rh[4], rl[4];
                ldsm4(rh, sBh + off);
                ldsm4(rl, sBl + off);
                bh[np * 2][0] = rh[0];     bh[np * 2][1] = rh[1];
                bh[np * 2 + 1][0] = rh[2]; bh[np * 2 + 1][1] = rh[3];
                bl[np * 2][0] = rl[0];     bl[np * 2][1] = rl[1];
                bl[np * 2 + 1][0] = rl[2]; bl[np * 2 + 1][1] = rl[3];
            }
#pragma unroll
            for (int mi = 0; mi < 2; mi++)
#pragma unroll
                for (int ni = 0; ni < 4; ni++) {
                    mma_f32(acc[mi][ni], ah[mi], bh[ni]);
                    mma_f16(acc16[mi][ni], al[mi], bh[ni]);
                    mma_f16(acc16[mi][ni], ah[mi], bl[ni]);
                }
        }
        __syncthreads();
    }

#pragma unroll
    for (int mi = 0; mi < 2; mi++) {
#pragma unroll
        for (int rr = 0; rr < 2; rr++) {
            int m = bm + wm + mi * 16 + gid + rr * 8;
            if (m >= M) continue;
#pragma unroll
            for (int ni = 0; ni < 4; ni++) {
                int n = bn + wn + ni * 8 + qid * 2;
                if (n >= N) continue;
                float2 corr = __half22float2(
                    *reinterpret_cast<__half2*>(&acc16[mi][ni][rr]));
                float v0 = acc[mi][ni][rr * 2]     + corr.x + (bias ? bias[n] : 0.f);
                float v1 = acc[mi][ni][rr * 2 + 1] + corr.y + (bias ? bias[n + 1] : 0.f);
                float* p = C + (size_t)m * N + n;
                if (addFlag) { p[0] += v0; p[1] += v1; }
                else { *(float2*)p = make_float2(v0, v1); }
            }
        }
    }
}

// ---------- fused: x += P0+P1+P2+bias ; h = rmsnorm(x, w) -> hi/lo -----------
__global__ void reduce_rms_kernel(float* __restrict__ x, const float* __restrict__ P,
                                  const float* __restrict__ bias,
                                  const float* __restrict__ w,
                                  __half* __restrict__ hi, __half* __restrict__ lo) {
    int s = blockIdx.x;
    size_t base = (size_t)s * HID;
    const long sz = (long)S_TOK * HID;
    float vals[5];
    float ss = 0.f;
#pragma unroll
    for (int it = 0; it < 5; it++) {
        int c = threadIdx.x + it * 256;
        float v = x[base + c] + P[base + c] + P[base + c + sz] + P[base + c + 2 * sz]
                + bias[c];
        x[base + c] = v;
        vals[it] = v;
        ss += v * v;
    }
#pragma unroll
    for (int o = 16; o; o >>= 1) ss += __shfl_xor_sync(0xffffffffu, ss, o);
    __shared__ float red[8];
    if ((threadIdx.x & 31) == 0) red[threadIdx.x >> 5] = ss;
    __syncthreads();
    if (threadIdx.x < 8) {
        float v = red[threadIdx.x];
#pragma unroll
        for (int o = 4; o; o >>= 1) v += __shfl_xor_sync(0xffu, v, o);
        if (threadIdx.x == 0) red[0] = v;
    }
    __syncthreads();
    float scale = rsqrtf(red[0] * (1.f / HID) + 1e-6f);
#pragma unroll
    for (int it = 0; it < 5; it++) {
        int c = threadIdx.x + it * 256;
        split1(vals[it] * scale * w[c], hi[base + c], lo[base + c]);
    }
}

__global__ void reduce2_gelu_kernel(const float* __restrict__ P, const float* __restrict__ bias,
                                    __half* __restrict__ hi, __half* __restrict__ lo) {
    const long sz = (long)GROUPS * MERGED;
    for (long i = blockIdx.x * (long)blockDim.x + threadIdx.x; i < sz;
         i += (long)gridDim.x * blockDim.x) {
        int col = (int)(i % MERGED);
        float v = P[i] + P[i + sz] + bias[col];
        v = 0.5f * v * (1.f + erff(v * 0.70710678118654752f));
        split1(v, hi[i], lo[i]);
    }
}

// ---------------- RMSNorm (standalone, layer-0 entry) ------------------------
__global__ void rmsnorm_kernel(const float* __restrict__ x, const float* __restrict__ w,
                               __half* __restrict__ hi, __half* __restrict__ lo) {
    int s = blockIdx.x;
    const float* xr = x + (size_t)s * HID;
    float ss = 0.f;
    for (int i = threadIdx.x; i < HID; i += 256) { float v = xr[i]; ss += v * v; }
#pragma unroll
    for (int o = 16; o; o >>= 1) ss += __shfl_xor_sync(0xffffffffu, ss, o);
    __shared__ float red[8];
    if ((threadIdx.x & 31) == 0) red[threadIdx.x >> 5] = ss;
    __syncthreads();
    if (threadIdx.x < 8) {
        float v = red[threadIdx.x];
#pragma unroll
        for (int o = 4; o; o >>= 1) v += __shfl_xor_sync(0xffu, v, o);
        if (threadIdx.x == 0) red[0] = v;
    }
    __syncthreads();
    float scale = rsqrtf(red[0] * (1.f / HID) + 1e-6f);
    for (int i = threadIdx.x; i < HID; i += 256)
        split1(xr[i] * scale * w[i], hi[(size_t)s * HID + i], lo[(size_t)s * HID + i]);
}

// ---------------- RoPE on q,k inside g_qkv ----------------------------------
__global__ void rope_kernel() {
    int s = blockIdx.x;
    size_t base = (size_t)s * QKV3;
    for (int p = threadIdx.x; p < 2 * HEADS * 40; p += 256) {
        int part = p / (HEADS * 40);
        int rem = p % (HEADS * 40);
        int head = rem / 40, d = rem % 40;
        size_t off = base + part * HID + head * HD + d;
        float c = g_cos[s * HD + d], sn = g_sin[s * HD + d];
        float v0 = g_qkv[off], v1 = g_qkv[off + 40];
        g_qkv[off]      = v0 * c - v1 * sn;
        g_qkv[off + 40] = v1 * c + v0 * sn;
    }
}

// ---------------- Attention ---------------------------------------------------
#define QP 84
__global__ void attn_kernel(const float* __restrict__ qkv,
                            __half* __restrict__ ohi, __half* __restrict__ olo,
                            int windowed) {
    extern __shared__ float sm[];
    float* Qs = sm;
    float* Ks = Qs + 64 * QP;
    float* Vs = Ks + 64 * QP;
    float* Ss = Vs + 64 * QP;
    int qt = blockIdx.x, head = blockIdx.y;
    int tid = threadIdx.x;
    int row = tid >> 2, l4 = tid & 3;

    for (int i = tid; i < 64 * HD; i += 256) {
        int r = i / HD, d = i % HD;
        Qs[r * QP + d] = qkv[(size_t)(qt * 64 + r) * QKV3 + head * HD + d];
    }
    float M = -1e30f, L = 0.f;
    unsigned long long O2[10];
#pragma unroll
    for (int i = 0; i < 10; i++) O2[i] = 0ull;

    int t0 = windowed ? qt : 0;
    int t1 = windowed ? qt + 1 : NTILE64;
    for (int t = t0; t < t1; t++) {
        __syncthreads();
        for (int i = tid; i < 64 * HD; i += 256) {
            int r = i / HD, d = i % HD;
            size_t base = (size_t)(t * 64 + r) * QKV3 + head * HD + d;
            Ks[r * QP + d] = qkv[base + HID];
            Vs[r * QP + d] = qkv[base + 2 * HID];
        }
        __syncthreads();

        unsigned long long acc2[16];
#pragma unroll
        for (int j = 0; j < 16; j++) acc2[j] = 0ull;
        const unsigned long long* qrow = (const unsigned long long*)(Qs + row * QP);
        for (int d2 = 0; d2 < HD / 2; d2++) {
            unsigned long long q2 = qrow[d2];
#pragma unroll
            for (int j = 0; j < 16; j++) {
                unsigned long long k2 =
                    *(const unsigned long long*)(Ks + (l4 * 16 + j) * QP + d2 * 2);
                acc2[j] = fma2(q2, k2, acc2[j]);
            }
        }
        float dots[16];
        float tmax = -1e30f;
#pragma unroll
        for (int j = 0; j < 16; j++) {
            float a, b; upk2(acc2[j], a, b);
            dots[j] = (a + b) * 0.11180339887498949f;
            tmax = fmaxf(tmax, dots[j]);
        }
        tmax = fmaxf(tmax, __shfl_xor_sync(0xffffffffu, tmax, 1));
        tmax = fmaxf(tmax, __shfl_xor_sync(0xffffffffu, tmax, 2));
        float Mnew = fmaxf(M, tmax);
        float alpha = fexpf(M - Mnew);
        float lsum = 0.f;
#pragma unroll
        for (int j = 0; j < 16; j++) {
            float p = fexpf(dots[j] - Mnew);
            Ss[row * 65 + l4 * 16 + j] = p;
            lsum += p;
        }
        lsum += __shfl_xor_sync(0xffffffffu, lsum, 1);
        lsum += __shfl_xor_sync(0xffffffffu, lsum, 2);
        L = L * alpha + lsum;
        M = Mnew;
        unsigned long long al2 = pk2(alpha, alpha);
#pragma unroll
        for (int i = 0; i < 10; i++) O2[i] = mul2(O2[i], al2);
        __syncwarp();
        for (int key = 0; key < 64; key++) {
            float p = Ss[row * 65 + key];
            unsigned long long pp = pk2(p, p);
            const unsigned long long* vrow =
                (const unsigned long long*)(Vs + key * QP + l4 * 20);
#pragma unroll
            for (int i = 0; i < 10; i++) O2[i] = fma2(pp, vrow[i], O2[i]);
        }
    }
    float inv = 1.f / L;
    int token = qt * 64 + row;
#pragma unroll
    for (int i = 0; i < 10; i++) {
        float a, b; upk2(O2[i], a, b);
        size_t off = (size_t)token * HID + head * HD + l4 * 20 + 2 * i;
        split1(a * inv, ohi[off], olo[off]);
        split1(b * inv, ohi[off + 1], olo[off + 1]);
    }
}

// ---------------- silu(gate+gb)*(up+ub) from merged gu buffer ----------------
__global__ void silu_mul_kernel(const float* __restrict__ gu,
                                const float* __restrict__ gb, const float* __restrict__ ub,
                                __half* __restrict__ hi, __half* __restrict__ lo) {
    long total = (long)S_TOK * INTER_P;
    for (long i = blockIdx.x * (long)blockDim.x + threadIdx.x; i < total;
         i += (long)gridDim.x * blockDim.x) {
        long row = i / INTER_P;
        int col = (int)(i % INTER_P);
        float v = 0.f;
        if (col < INTER) {
            float g = gu[row * GU_N + col] + gb[col];
            float u = gu[row * GU_N + INTER + col] + ub[col];
            float e = fexpf(-g);
            v = __fdividef(g, 1.f + e) * u;
        }
        split1(v, hi[i], lo[i]);
    }
}
__global__ void scatter_out_kernel(const float* __restrict__ src, float* __restrict__ dst) {
    for (long i = blockIdx.x * (long)blockDim.x + threadIdx.x;
         i < (long)GROUPS * OUTDIM; i += (long)gridDim.x * blockDim.x) {
        int g = (int)(i / OUTDIM), n = (int)(i % OUTDIM);
        dst[(size_t)g_wingrp[g] * OUTDIM + n] = src[i];
    }
}

// ---------------- Host orchestration -----------------------------------------
#define GEMM_SMEM (2 * STG * (int)sizeof(__half))

static void run_gemm(const __half* Ahi, const __half* Alo,
                     const __half* Bhi, const __half* Blo,
                     const float* bias, float* C, int M, int N, int K, int add,
                     int nsplit = 1) {
    dim3 grid((N + GBN - 1) / GBN, (M + GBM - 1) / GBM, nsplit);
    gemm_tc_kernel<<<grid, 256, GEMM_SMEM>>>(Ahi, Alo, Bhi, Blo, bias, C, M, N, K, add, nsplit);
}

extern "C" void kernel_launch(void* const* d_in, const int* in_sizes, int n_in,
                              void* d_out, int out_size) {
    const float* pixel_values = (const float*)d_in[0];
    const float* patch_w = (const float*)d_in[1];
    const float* qkv_w   = (const float*)d_in[2];
    const float* qkv_b   = (const float*)d_in[3];
    const float* proj_w  = (const float*)d_in[4];
    const float* proj_b  = (const float*)d_in[5];
    const float* norm1_w = (const float*)d_in[6];
    const float* norm2_w = (const float*)d_in[7];
    const float* gate_w  = (const float*)d_in[8];
    const float* gate_b  = (const float*)d_in[9];
    const float* up_w    = (const float*)d_in[10];
    const float* up_b    = (const float*)d_in[11];
    const float* down_w  = (const float*)d_in[12];
    const float* down_b  = (const float*)d_in[13];
    const float* ln_q_w  = (const float*)d_in[14];
    const float* m1_w    = (const float*)d_in[15];
    const float* m1_b    = (const float*)d_in[16];
    const float* m2_w    = (const float*)d_in[17];
    const float* m2_b    = (const float*)d_in[18];
    float* out = (float*)d_out;

    __half *whi, *wlo, *hhi, *hlo, *athi, *atlo, *achi, *aclo, *pxhi, *pxlo;
    float *x, *qkv, *gu, *part;
    cudaGetSymbolAddress((void**)&whi, g_whi);
    cudaGetSymbolAddress((void**)&wlo, g_wlo);
    cudaGetSymbolAddress((void**)&hhi, g_hhi);
    cudaGetSymbolAddress((void**)&hlo, g_hlo);
    cudaGetSymbolAddress((void**)&athi, g_athi);
    cudaGetSymbolAddress((void**)&atlo, g_atlo);
    cudaGetSymbolAddress((void**)&achi, g_achi);
    cudaGetSymbolAddress((void**)&aclo, g_aclo);
    cudaGetSymbolAddress((void**)&pxhi, g_pxhi);
    cudaGetSymbolAddress((void**)&pxlo, g_pxlo);
    cudaGetSymbolAddress((void**)&x,    g_x);
    cudaGetSymbolAddress((void**)&qkv,  g_qkv);
    cudaGetSymbolAddress((void**)&gu,   g_gu);
    cudaGetSymbolAddress((void**)&part, g_part);

    static int attr_set = 0;
    static cudaStream_t s2 = 0;
    static cudaEvent_t evFork = 0, evJoin = 0;
    int attn_smem = (3 * 64 * QP + 64 * 65) * (int)sizeof(float);
    if (!attr_set) {
        cudaFuncSetAttribute(attn_kernel, cudaFuncAttributeMaxDynamicSharedMemorySize, attn_smem);
        cudaFuncSetAttribute(gemm_tc_kernel, cudaFuncAttributeMaxDynamicSharedMemorySize, GEMM_SMEM);
        cudaStreamCreateWithFlags(&s2, cudaStreamNonBlocking);
        cudaEventCreateWithFlags(&evFork, cudaEventDisableTiming);
        cudaEventCreateWithFlags(&evJoin, cudaEventDisableTiming);
        attr_set = 1;
    }

    // ---- fork: bulk weight splits on side stream ----
    cudaEventRecord(evFork, 0);
    cudaStreamWaitEvent(s2, evFork, 0);
    split_w_kernel<<<512, 256, 0, s2>>>(proj_w,  whi + OFF_PROJ,  wlo + OFF_PROJ,  SZ_PROJ / 4);
    split_gu_kernel<<<1024, 256, 0, s2>>>(gate_w, up_w, whi + OFF_GU, wlo + OFF_GU);
    split_down_kernel<<<1024, 256, 0, s2>>>(down_w, whi + OFF_DOWN, wlo + OFF_DOWN);
    split_w_kernel<<<1024, 256, 0, s2>>>(m1_w,   whi + OFF_M1,    wlo + OFF_M1,    SZ_M1 / 4);
    split_w_kernel<<<1024, 256, 0, s2>>>(m2_w,   whi + OFF_M2,    wlo + OFF_M2,    SZ_M2 / 4);
    cudaEventRecord(evJoin, s2);

    // ---- main stream ----
    split_w_kernel<<<512, 256>>>(patch_w, whi + OFF_PATCH, wlo + OFF_PATCH, SZ_PATCH / 4);
    split_w_kernel<<<1024, 256>>>(qkv_w,  whi + OFF_QKV,   wlo + OFF_QKV,   SZ_QKV / 4);
    init_kernel<<<(S_TOK + 255) / 256, 256>>>();
    gather_pixels<<<512, 256>>>(pixel_values);

    run_gemm(pxhi, pxlo, whi + OFF_PATCH, wlo + OFF_PATCH, nullptr, x, S_TOK, HID, PIXF, 0);
    rmsnorm_kernel<<<S_TOK, 256>>>(x, norm1_w, hhi, hlo);   // layer-0 entry norm

    for (int i = 0; i < DEPTH; i++) {
        long oq = OFF_QKV + (long)i * QKV3 * HID;
        long op = OFF_PROJ + (long)i * HID * HID;
        long og = OFF_GU + (long)i * GU_N * HID;
        long od = OFF_DOWN + (long)i * HID * INTER_P;
        const float* qb = qkv_b + (size_t)i * QKV3;
        const float* pb = proj_b + (size_t)i * HID;
        const float* n2 = norm2_w + (size_t)i * HID;
        const float* gb = gate_b + (size_t)i * INTER;
        const float* ub = up_b + (size_t)i * INTER;
        const float* db = down_b + (size_t)i * HID;
        const float* wnext = (i < DEPTH - 1) ? norm1_w + (size_t)(i + 1) * HID : ln_q_w;

        run_gemm(hhi, hlo, whi + oq, wlo + oq, qb, qkv, S_TOK, QKV3, HID, 0);
        rope_kernel<<<S_TOK, 256>>>();
        int windowed = (i == 3 || i == 7) ? 0 : 1;
        attn_kernel<<<dim3(NTILE64, HEADS), 256, attn_smem>>>(qkv, athi, atlo, windowed);
        if (i == 0) cudaStreamWaitEvent(0, evJoin, 0);
        // proj: split-K=3 -> partials; fused reduce + residual + rmsnorm(n2)
        run_gemm(athi, atlo, whi + op, wlo + op, nullptr, part, S_TOK, HID, HID, 0, 3);
        reduce_rms_kernel<<<S_TOK, 256>>>(x, part, pb, n2, hhi, hlo);

        // merged gate|up GEMM (biases applied in silu)
        run_gemm(hhi, hlo, whi + og, wlo + og, nullptr, gu, S_TOK, GU_N, HID, 0);
        silu_mul_kernel<<<1024, 256>>>(gu, gb, ub, achi, aclo);
        // down: split-K=3 -> partials; fused reduce + residual + rmsnorm(next/ln_q)
        run_gemm(achi, aclo, whi + od, wlo + od, nullptr, part, S_TOK, HID, INTER_P, 0, 3);
        reduce_rms_kernel<<<S_TOK, 256>>>(x, part, db, wnext, hhi, hlo);
    }

    // merger: h (as 576x5120) -> m1 splitK=2 -> gelu -> m2 -> scatter
    run_gemm(hhi, hlo, whi + OFF_M1, wlo + OFF_M1, nullptr, part, GROUPS, MERGED, MERGED, 0, 2);
    reduce2_gelu_kernel<<<512, 256>>>(part, m1_b, achi, aclo);
    run_gemm(achi, aclo, whi + OFF_M2, wlo + OFF_M2, m2_b, gu, GROUPS, OUTDIM, MERGED, 0);
    scatter_out_kernel<<<512, 256>>>(gu, out);
}